// round 6
// baseline (speedup 1.0000x reference)
#include <cuda_runtime.h>

#define N_ 32
#define T_ 48

// ---------------- packed f32x2 helpers (Blackwell) ----------------
__device__ __forceinline__ unsigned long long f2_pack(float lo, float hi) {
    unsigned long long d;
    asm("mov.b64 %0, {%1, %2};" : "=l"(d) : "f"(lo), "f"(hi));
    return d;
}
__device__ __forceinline__ float2 f2_unpack(unsigned long long v) {
    float2 r;
    asm("mov.b64 {%0, %1}, %2;" : "=f"(r.x), "=f"(r.y) : "l"(v));
    return r;
}
__device__ __forceinline__ unsigned long long f2_fma(unsigned long long a,
                                                     unsigned long long b,
                                                     unsigned long long c) {
    unsigned long long d;
    asm("fma.rn.f32x2 %0, %1, %2, %3;" : "=l"(d) : "l"(a), "l"(b), "l"(c));
    return d;
}

// ---------------- scratch (t-major: [T][N][C][H][W]) ----------------
__device__ float g_xt[(size_t)T_*N_*32*32];          // x transposed (C=1)
__device__ float g_z1c[(size_t)T_*N_*16*28*28];      // conv1 pre-acts
__device__ float g_h1[(size_t)T_*N_*16*28*28];       // conv1 spikes
__device__ float g_z2c[(size_t)T_*N_*32*24*24];      // conv2 pre-acts
__device__ float g_p1[(size_t)T_*N_*32*12*12];       // pool1 spikes
__device__ float g_z3c[(size_t)T_*N_*32*8*8];        // conv3 pre-acts
__device__ float g_p2[(size_t)T_*N_*32*4*4];         // pool2 spikes
__device__ float g_wt1[512*128];                     // Wf1 transposed [k][o]
__device__ float g_z1[(size_t)T_*N_*128];            // fc1 pre-activations

// ---------------- transpose x: [N,1,32,32,T] -> [T][N][32][32] ----------------
__global__ void k_transpose_x(const float* __restrict__ x) {
    int idx = blockIdx.x * blockDim.x + threadIdx.x;
    if (idx >= N_*32*32) return;
    int n = idx >> 10, hw = idx & 1023;
    const float* xp = x + (size_t)idx * T_;
    #pragma unroll
    for (int t = 0; t < T_; t++)
        g_xt[((size_t)t*N_ + n)*1024 + hw] = xp[t];
}

// ---------------- transpose Wf1: [128][512] -> [512][128] ----------------
__global__ void k_transpose_wf1(const float* __restrict__ Wf1) {
    int idx = blockIdx.x * blockDim.x + threadIdx.x;
    if (idx >= 128*512) return;
    int o = idx >> 9, k = idx & 511;
    g_wt1[k*128 + o] = Wf1[idx];
}

// ---------------- 5x5 VALID conv (pre-act only), f32x2-packed over 2 time steps ----------------
// Smem weights channel-last: ws[(c*25+k)*COUT + oc] -> LDS.128 per GO=4 group.
// Double-buffered input rows; inner product uses fma.rn.f32x2 (2 FMA/issue).
template<int CIN,int COUT,int HIN,int WIN,int GO,int WOT,int HOT,int MINB>
__global__ void
__launch_bounds__(((WIN-4)/WOT)*(COUT/GO)*HOT, MINB)
k_conv(const float* __restrict__ in,
       const float* __restrict__ Wc,
       const float* __restrict__ bc,
       float* __restrict__ z) {
    constexpr int HOUT = HIN-4, WOUT = WIN-4;
    constexpr int NWG  = WOUT/WOT;
    constexpr int NOG  = COUT/GO;
    constexpr int LANES = NWG*NOG;
    constexpr int HBLK = HOUT/HOT;
    constexpr int M    = CIN*5;            // flattened (c,kh)
    constexpr size_t TS_IN  = (size_t)N_*CIN*HIN*WIN;
    constexpr size_t TS_OUT = (size_t)N_*COUT*HOUT*WOUT;
    extern __shared__ float ws[];          // CIN*25*COUT, channel-last
    {
        int tid = threadIdx.y*LANES + threadIdx.x;
        for (int i = tid; i < COUT*CIN*25; i += LANES*HOT) {
            int oc = i % COUT;
            int ck = i / COUT;
            ws[i] = Wc[oc*CIN*25 + ck];
        }
    }
    __syncthreads();

    int hb = blockIdx.x % HBLK;
    int t0 = (blockIdx.x / HBLK) * 2;      // 2 time steps packed
    int n  = blockIdx.y;
    int wg = threadIdx.x % NWG;
    int og = threadIdx.x / NWG;
    int wo = wg * WOT;
    int ho = hb*HOT + threadIdx.y;

    unsigned long long acc2[GO][WOT];
    #pragma unroll
    for (int g = 0; g < GO; g++) {
        float b = bc[og*GO + g];
        unsigned long long b2 = f2_pack(b, b);
        #pragma unroll
        for (int ww = 0; ww < WOT; ww++) acc2[g][ww] = b2;
    }

    const float* inb = in + (size_t)t0*TS_IN + (size_t)n*CIN*HIN*WIN
                          + (size_t)ho*WIN + wo;

    unsigned long long va[WOT+4], vb[WOT+4];

    auto load_v = [&](int m, unsigned long long (&v2)[WOT+4]) {
        int c = m / 5, kh = m % 5;
        const float* ip = inb + ((size_t)c*HIN + kh)*WIN;
        const float2* p0 = reinterpret_cast<const float2*>(ip);
        const float2* p1 = reinterpret_cast<const float2*>(ip + TS_IN);
        #pragma unroll
        for (int j2 = 0; j2 < (WOT+4)/2; j2++) {
            float2 a = p0[j2];
            float2 b = p1[j2];
            v2[2*j2]   = f2_pack(a.x, b.x);
            v2[2*j2+1] = f2_pack(a.y, b.y);
        }
    };

    auto fma_step = [&](int m, unsigned long long (&v2)[WOT+4]) {
        #pragma unroll
        for (int kw = 0; kw < 5; kw++) {
            unsigned long long w2[GO];
            if constexpr (GO == 4) {
                float4 w4 = *reinterpret_cast<const float4*>(&ws[(m*5 + kw)*COUT + og*4]);
                w2[0] = f2_pack(w4.x, w4.x);
                w2[1] = f2_pack(w4.y, w4.y);
                w2[2] = f2_pack(w4.z, w4.z);
                w2[3] = f2_pack(w4.w, w4.w);
            } else if constexpr (GO == 2) {
                float2 wv = *reinterpret_cast<const float2*>(&ws[(m*5 + kw)*COUT + og*2]);
                w2[0] = f2_pack(wv.x, wv.x);
                w2[1] = f2_pack(wv.y, wv.y);
            } else {
                #pragma unroll
                for (int g = 0; g < GO; g++) {
                    float w = ws[(m*5 + kw)*COUT + og*GO + g];
                    w2[g] = f2_pack(w, w);
                }
            }
            #pragma unroll
            for (int g = 0; g < GO; g++)
                #pragma unroll
                for (int ww = 0; ww < WOT; ww++)
                    acc2[g][ww] = f2_fma(v2[ww+kw], w2[g], acc2[g][ww]);
        }
    };

    load_v(0, va);
    int m = 0;
    #pragma unroll 1
    for (; m + 2 <= M; m += 2) {
        load_v(m + 1, vb);
        fma_step(m, va);
        if (m + 2 < M) load_v(m + 2, va);
        fma_step(m + 1, vb);
    }
    if (m < M) fma_step(m, va);   // odd M tail (va preloaded)

    float* zb = z + (size_t)t0*TS_OUT + (size_t)n*COUT*HOUT*WOUT
                  + (size_t)og*GO*HOUT*WOUT + (size_t)ho*WOUT + wo;
    #pragma unroll
    for (int g = 0; g < GO; g++) {
        float* op0 = zb + (size_t)g*HOUT*WOUT;
        float* op1 = op0 + TS_OUT;
        #pragma unroll
        for (int j2 = 0; j2 < WOT/2; j2++) {
            float2 a = f2_unpack(acc2[g][2*j2]);
            float2 b = f2_unpack(acc2[g][2*j2+1]);
            float2 d0; d0.x = a.x; d0.y = b.x;   // time step t0
            float2 d1; d1.x = a.y; d1.y = b.y;   // time step t0+1
            reinterpret_cast<float2*>(op0)[j2] = d0;
            reinterpret_cast<float2*>(op1)[j2] = d1;
        }
    }
}

// ---------------- LIF scan over T: z -> spikes ----------------
template<int SZ>
__global__ void k_scan(const float* __restrict__ z, float* __restrict__ s_out) {
    int idx = blockIdx.x * blockDim.x + threadIdx.x;
    if (idx >= SZ) return;
    float u = 0.f;
    #pragma unroll 4
    for (int t = 0; t < T_; t++) {
        u += z[(size_t)t*SZ + idx];
        float s = (u >= 1.0f) ? 1.0f : 0.0f;
        u -= s;
        s_out[(size_t)t*SZ + idx] = s;
    }
}

// ---------------- fused LIF scan + 2x2 avg-pool + LIF scan ----------------
template<int C,int HIN>
__global__ void k_scanpool(const float* __restrict__ z, float* __restrict__ out) {
    constexpr int HO = HIN/2;
    constexpr size_t TS_IN  = (size_t)N_*C*HIN*HIN;
    constexpr size_t TS_OUT = (size_t)N_*C*HO*HO;
    int idx = blockIdx.x * blockDim.x + threadIdx.x;
    if (idx >= N_*C*HO*HO) return;
    int wo = idx % HO; int t1 = idx / HO;
    int ho = t1 % HO;  int t2 = t1 / HO;
    int c  = t2 % C;   int n  = t2 / C;
    const float* ip = z + ((size_t)n*C + c)*HIN*HIN + (size_t)(2*ho)*HIN + 2*wo;
    float* op = out + ((size_t)n*C + c)*HO*HO + (size_t)ho*HO + wo;
    float u0 = 0.f, u1 = 0.f, u2 = 0.f, u3 = 0.f, up = 0.f;
    #pragma unroll 4
    for (int t = 0; t < T_; t++) {
        const float* p = ip + (size_t)t*TS_IN;
        float2 r0 = *reinterpret_cast<const float2*>(p);
        float2 r1 = *reinterpret_cast<const float2*>(p + HIN);
        u0 += r0.x; float s0 = (u0 >= 1.0f) ? 1.0f : 0.0f; u0 -= s0;
        u1 += r0.y; float s1 = (u1 >= 1.0f) ? 1.0f : 0.0f; u1 -= s1;
        u2 += r1.x; float s2 = (u2 >= 1.0f) ? 1.0f : 0.0f; u2 -= s2;
        u3 += r1.y; float s3 = (u3 >= 1.0f) ? 1.0f : 0.0f; u3 -= s3;
        up += 0.25f*(s0 + s1 + s2 + s3);
        float sp = (up >= 1.0f) ? 1.0f : 0.0f; up -= sp;
        op[(size_t)t*TS_OUT] = sp;
    }
}

// ---------------- fc1 GEMM ----------------
__global__ void k_fc1(const float* __restrict__ bf1) {
    __shared__ float sin_[4][512];
    int t0 = blockIdx.x*4, n = blockIdx.y, o = threadIdx.x;
    for (int i = o; i < 4*512; i += 128) {
        int tv = i >> 9, k = i & 511;
        sin_[tv][k] = g_p2[((size_t)(t0+tv)*N_ + n)*512 + k];
    }
    __syncthreads();
    float b = bf1[o];
    float acc[4] = {b, b, b, b};
    #pragma unroll 4
    for (int k = 0; k < 512; k++) {
        float w = g_wt1[k*128 + o];
        #pragma unroll
        for (int tv = 0; tv < 4; tv++) acc[tv] += sin_[tv][k] * w;
    }
    #pragma unroll
    for (int tv = 0; tv < 4; tv++)
        g_z1[((size_t)(t0+tv)*N_ + n)*128 + o] = acc[tv];
}

// ---------------- head ----------------
__global__ void k_head(const float* __restrict__ Wf2, const float* __restrict__ bf2,
                       float* __restrict__ out) {
    int n = blockIdx.x, o = threadIdx.x;
    __shared__ float s1[128];
    __shared__ float w2[2][128];
    w2[0][o] = Wf2[o];
    w2[1][o] = Wf2[128 + o];
    float u1 = 0.f, u2 = 0.f, ssum = 0.f;
    float b2 = (o < 2) ? bf2[o] : 0.f;
    __syncthreads();
    for (int t = 0; t < T_; t++) {
        float z = g_z1[((size_t)t*N_ + n)*128 + o];
        u1 += z;
        float s = (u1 >= 1.0f) ? 1.0f : 0.0f;
        u1 -= s;
        s1[o] = s;
        __syncthreads();
        if (o < 2) {
            float d = b2;
            #pragma unroll 8
            for (int k = 0; k < 128; k++) d += s1[k] * w2[o][k];
            u2 += d;
            float s2 = (u2 >= 1.0f) ? 1.0f : 0.0f;
            u2 -= s2;
            ssum += s2;
        }
        __syncthreads();
    }
    if (o < 2) out[n*2 + o] = ssum * (1.0f / T_);
}

// ---------------- launch ----------------
extern "C" void kernel_launch(void* const* d_in, const int* in_sizes, int n_in,
                              void* d_out, int out_size) {
    (void)in_sizes; (void)n_in; (void)out_size;
    const float* x   = (const float*)d_in[0];
    const float* Wc1 = (const float*)d_in[1];
    const float* bc1 = (const float*)d_in[2];
    const float* Wc2 = (const float*)d_in[3];
    const float* bc2 = (const float*)d_in[4];
    const float* Wc3 = (const float*)d_in[5];
    const float* bc3 = (const float*)d_in[6];
    const float* Wf1 = (const float*)d_in[7];
    const float* bf1 = (const float*)d_in[8];
    const float* Wf2 = (const float*)d_in[9];
    const float* bf2 = (const float*)d_in[10];
    float* out = (float*)d_out;

    float *p_xt, *p_z1c, *p_h1, *p_z2c, *p_p1, *p_z3c, *p_p2;
    cudaGetSymbolAddress((void**)&p_xt,  g_xt);
    cudaGetSymbolAddress((void**)&p_z1c, g_z1c);
    cudaGetSymbolAddress((void**)&p_h1,  g_h1);
    cudaGetSymbolAddress((void**)&p_z2c, g_z2c);
    cudaGetSymbolAddress((void**)&p_p1,  g_p1);
    cudaGetSymbolAddress((void**)&p_z3c, g_z3c);
    cudaGetSymbolAddress((void**)&p_p2,  g_p2);

    // conv1: CIN=1,  GO=2, WOT=4, HOT=4 -> block (56,4)=224 thr
    auto c1 = k_conv<1,16,32,32,2,4,4,2>;
    // conv2: CIN=16, GO=4, WOT=6, HOT=4 -> block (32,4)=128 thr
    auto c2 = k_conv<16,32,28,28,4,6,4,4>;
    // conv3: CIN=32, GO=4, WOT=4, HOT=8 -> block (16,8)=128 thr
    auto c3 = k_conv<32,32,12,12,4,4,8,4>;
    cudaFuncSetAttribute(c2, cudaFuncAttributeMaxDynamicSharedMemorySize, 32*16*25*4);
    cudaFuncSetAttribute(c3, cudaFuncAttributeMaxDynamicSharedMemorySize, 32*32*25*4);

    k_transpose_x<<<(N_*1024 + 255)/256, 256>>>(x);
    k_transpose_wf1<<<(128*512 + 255)/256, 256>>>(Wf1);

    constexpr int SZ1 = N_*16*28*28;

    c1<<<dim3(7*(T_/2), N_), dim3(56, 4), 16*1*25*4>>>(p_xt, Wc1, bc1, p_z1c);
    k_scan<SZ1><<<(SZ1 + 255)/256, 256>>>(p_z1c, p_h1);

    c2<<<dim3(6*(T_/2), N_), dim3(32, 4), 32*16*25*4>>>(p_h1, Wc2, bc2, p_z2c);
    k_scanpool<32,24><<<(N_*32*12*12 + 255)/256, 256>>>(p_z2c, p_p1);

    c3<<<dim3(1*(T_/2), N_), dim3(16, 8), 32*32*25*4>>>(p_p1, Wc3, bc3, p_z3c);
    k_scanpool<32,8><<<(N_*32*4*4 + 255)/256, 256>>>(p_z3c, p_p2);

    k_fc1<<<dim3(T_/4, N_), 128>>>(bf1);
    k_head<<<N_, 128>>>(Wf2, bf2, out);
}

// round 7
// speedup vs baseline: 1.6077x; 1.6077x over previous
#include <cuda_runtime.h>
#include <cuda_bf16.h>

#define N_ 32
#define T_ 48

// ---------------- scratch (t-major: [T][N][C][H][W]) ----------------
__device__ float g_xt[(size_t)T_*N_*32*32];          // x transposed (C=1)
__device__ float g_z1c[(size_t)T_*N_*16*28*28];      // conv1 pre-acts
__device__ float g_h1[(size_t)T_*N_*16*28*28];       // conv1 spikes
__device__ float g_z2c[(size_t)T_*N_*32*24*24];      // conv2 pre-acts
__device__ float g_p1[(size_t)T_*N_*32*12*12];       // pool1 spikes
__device__ float g_z3c[(size_t)T_*N_*32*8*8];        // conv3 pre-acts
__device__ float g_p2[(size_t)T_*N_*32*4*4];         // pool2 spikes
__device__ float g_wt1[512*128];                     // Wf1 transposed [k][o]
__device__ float g_z1[(size_t)T_*N_*128];            // fc1 pre-activations
__device__ __nv_bfloat16 g_w2s[3*25*32*16];          // conv2 weights, 3-way bf16 split,
                                                     // layout [split][j=kh*5+kw][o][c]

// ---------------- transpose x: [N,1,32,32,T] -> [T][N][32][32] ----------------
__global__ void k_transpose_x(const float* __restrict__ x) {
    int idx = blockIdx.x * blockDim.x + threadIdx.x;
    if (idx >= N_*32*32) return;
    int n = idx >> 10, hw = idx & 1023;
    const float* xp = x + (size_t)idx * T_;
    #pragma unroll
    for (int t = 0; t < T_; t++)
        g_xt[((size_t)t*N_ + n)*1024 + hw] = xp[t];
}

// ---------------- transpose Wf1: [128][512] -> [512][128] ----------------
__global__ void k_transpose_wf1(const float* __restrict__ Wf1) {
    int idx = blockIdx.x * blockDim.x + threadIdx.x;
    if (idx >= 128*512) return;
    int o = idx >> 9, k = idx & 511;
    g_wt1[k*128 + o] = Wf1[idx];
}

// ---------------- conv2 weight split: fp32 -> 3x bf16 ----------------
__global__ void k_split_w2(const float* __restrict__ Wc2) {
    int i = blockIdx.x*256 + threadIdx.x;   // 25*32*16 = 12800
    if (i >= 12800) return;
    int c = i % 16, o = (i/16) % 32, j = i/512;     // j = kh*5+kw
    int kh = j/5, kw = j%5;
    float w = Wc2[((o*16 + c)*5 + kh)*5 + kw];
    __nv_bfloat16 h = __float2bfloat16(w);
    float r = w - __bfloat162float(h);
    __nv_bfloat16 m = __float2bfloat16(r);
    float r2 = r - __bfloat162float(m);
    __nv_bfloat16 l = __float2bfloat16(r2);
    g_w2s[0*12800 + i] = h;
    g_w2s[1*12800 + i] = m;
    g_w2s[2*12800 + i] = l;
}

// ---------------- mma.m16n8k16 bf16 helper ----------------
__device__ __forceinline__ void mma16816(float* c, const unsigned* a,
                                         unsigned b0, unsigned b1) {
    asm volatile(
        "mma.sync.aligned.m16n8k16.row.col.f32.bf16.bf16.f32 "
        "{%0,%1,%2,%3}, {%4,%5,%6,%7}, {%8,%9}, {%0,%1,%2,%3};"
        : "+f"(c[0]), "+f"(c[1]), "+f"(c[2]), "+f"(c[3])
        : "r"(a[0]), "r"(a[1]), "r"(a[2]), "r"(a[3]), "r"(b0), "r"(b1));
}

// ---------------- conv2 via tensor cores ----------------
// One block per (t,n). C[32 o][576 sp] = sum_j W_j[32x16] * patch_j[16x576], 3 bf16 splits.
// smem: input tile [28*28][16] bf16 (+ spikes are exact in bf16), weights [3][25][32][16] bf16.
__global__ void __launch_bounds__(384, 1)
k_conv2_mma(const float* __restrict__ h1s,
            const float* __restrict__ bc2,
            float* __restrict__ z2c) {
    extern __shared__ char sm[];
    __nv_bfloat16* sIn = reinterpret_cast<__nv_bfloat16*>(sm);            // 784*16
    __nv_bfloat16* sW  = reinterpret_cast<__nv_bfloat16*>(sm + 25088);    // 3*25*32*16

    int t = blockIdx.x, n = blockIdx.y;
    int tid = threadIdx.x;

    // stage weights (coalesced 32-bit copies)
    {
        const unsigned* src = reinterpret_cast<const unsigned*>(g_w2s);
        unsigned* dst = reinterpret_cast<unsigned*>(sW);
        for (int i = tid; i < 3*25*32*16/2; i += 384) dst[i] = src[i];
    }
    // stage input: h1 [t][n][c][784] fp32 -> sIn[hw][c] bf16
    {
        const float* ib = h1s + ((size_t)t*N_ + n)*16*784;
        for (int i = tid; i < 16*784; i += 384) {
            int c = i / 784, hw = i % 784;
            sIn[hw*16 + c] = __float2bfloat16(ib[i]);
        }
    }
    __syncthreads();

    int w    = tid >> 5;
    int lane = tid & 31;
    int qid  = lane >> 2;    // lane/4
    int rid  = lane & 3;     // lane%4

    float acc[2][6][4];
    #pragma unroll
    for (int mt = 0; mt < 2; mt++)
        #pragma unroll
        for (int nt = 0; nt < 6; nt++)
            #pragma unroll
            for (int r = 0; r < 4; r++) acc[mt][nt][r] = 0.f;

    // per-lane B base offsets (element index into sIn) for each n8 tile
    int bbase[6];
    #pragma unroll
    for (int nt = 0; nt < 6; nt++) {
        int sp = w*48 + nt*8 + qid;       // B frag: n = lane/4
        int ho = sp / 24, wo = sp % 24;
        bbase[nt] = (ho*28 + wo)*16 + rid*2;
    }

    #pragma unroll 1
    for (int j = 0; j < 25; j++) {
        int kh = j / 5, kw = j % 5;
        int shift = (kh*28 + kw)*16;

        // A fragments: weights [split][mtile], rows o = mt*16 + qid(+8), cols c = rid*2(+8)
        unsigned aF[3][2][4];
        #pragma unroll
        for (int s = 0; s < 3; s++)
            #pragma unroll
            for (int mt = 0; mt < 2; mt++) {
                const __nv_bfloat16* wp = sW + ((s*25 + j)*32 + mt*16)*16;
                aF[s][mt][0] = *reinterpret_cast<const unsigned*>(wp + qid*16     + rid*2);
                aF[s][mt][1] = *reinterpret_cast<const unsigned*>(wp + (qid+8)*16 + rid*2);
                aF[s][mt][2] = *reinterpret_cast<const unsigned*>(wp + qid*16     + rid*2 + 8);
                aF[s][mt][3] = *reinterpret_cast<const unsigned*>(wp + (qid+8)*16 + rid*2 + 8);
            }

        #pragma unroll
        for (int nt = 0; nt < 6; nt++) {
            const __nv_bfloat16* bp = sIn + bbase[nt] + shift;
            unsigned b0 = *reinterpret_cast<const unsigned*>(bp);
            unsigned b1 = *reinterpret_cast<const unsigned*>(bp + 8);
            #pragma unroll
            for (int s = 0; s < 3; s++)
                #pragma unroll
                for (int mt = 0; mt < 2; mt++)
                    mma16816(acc[mt][nt], aF[s][mt], b0, b1);
        }
    }

    // epilogue: bias + store. C frag: rows o = mt*16 + qid(+8), cols sp = ... + rid*2(+1)
    float* zb = z2c + ((size_t)t*N_ + n)*32*576;
    #pragma unroll
    for (int mt = 0; mt < 2; mt++) {
        int o0 = mt*16 + qid;
        float b0 = bc2[o0], b1 = bc2[o0 + 8];
        #pragma unroll
        for (int nt = 0; nt < 6; nt++) {
            int sp = w*48 + nt*8 + rid*2;
            float2 d0; d0.x = acc[mt][nt][0] + b0; d0.y = acc[mt][nt][1] + b0;
            float2 d1; d1.x = acc[mt][nt][2] + b1; d1.y = acc[mt][nt][3] + b1;
            *reinterpret_cast<float2*>(zb + (size_t)o0*576 + sp)       = d0;
            *reinterpret_cast<float2*>(zb + (size_t)(o0+8)*576 + sp)   = d1;
        }
    }
}

// ---------------- 5x5 VALID conv, scalar pipelined (conv1/conv3) ----------------
template<int CIN,int COUT,int HIN,int WIN,int GO,int WOT,int HOT,int TV,int MINB>
__global__ void
__launch_bounds__(((WIN-4)/WOT)*(COUT/GO)*HOT, MINB)
k_conv(const float* __restrict__ in,
       const float* __restrict__ Wc,
       const float* __restrict__ bc,
       float* __restrict__ z) {
    constexpr int HOUT = HIN-4, WOUT = WIN-4;
    constexpr int NWG  = WOUT/WOT;
    constexpr int NOG  = COUT/GO;
    constexpr int LANES = NWG*NOG;
    constexpr int HBLK = HOUT/HOT;
    constexpr int M    = CIN*5;
    constexpr size_t TS_IN  = (size_t)N_*CIN*HIN*WIN;
    constexpr size_t TS_OUT = (size_t)N_*COUT*HOUT*WOUT;
    extern __shared__ float ws[];
    {
        int tid = threadIdx.y*LANES + threadIdx.x;
        for (int i = tid; i < COUT*CIN*25; i += LANES*HOT) {
            int oc = i % COUT;
            int ck = i / COUT;
            ws[i] = Wc[oc*CIN*25 + ck];
        }
    }
    __syncthreads();

    int hb = blockIdx.x % HBLK;
    int t0 = (blockIdx.x / HBLK) * TV;
    int n  = blockIdx.y;
    int wg = threadIdx.x % NWG;
    int og = threadIdx.x / NWG;
    int wo = wg * WOT;
    int ho = hb*HOT + threadIdx.y;

    float acc[GO][WOT][TV];
    #pragma unroll
    for (int g = 0; g < GO; g++) {
        float b = bc[og*GO + g];
        #pragma unroll
        for (int ww = 0; ww < WOT; ww++)
            #pragma unroll
            for (int tv = 0; tv < TV; tv++) acc[g][ww][tv] = b;
    }

    const float* inb = in + (size_t)t0*TS_IN + (size_t)n*CIN*HIN*WIN
                          + (size_t)ho*WIN + wo;

    float va[WOT+4][TV], vb[WOT+4][TV];

    auto load_v = [&](int m, float (&v)[WOT+4][TV]) {
        int c = m / 5, kh = m % 5;
        const float* ip = inb + ((size_t)c*HIN + kh)*WIN;
        #pragma unroll
        for (int tv = 0; tv < TV; tv++) {
            const float2* p2 = reinterpret_cast<const float2*>(ip + (size_t)tv*TS_IN);
            #pragma unroll
            for (int j2 = 0; j2 < (WOT+4)/2; j2++) {
                float2 d = p2[j2];
                v[2*j2][tv]   = d.x;
                v[2*j2+1][tv] = d.y;
            }
        }
    };

    auto fma_step = [&](int m, float (&v)[WOT+4][TV]) {
        #pragma unroll
        for (int kw = 0; kw < 5; kw++) {
            float wreg[GO];
            if constexpr (GO == 4) {
                float4 w4 = *reinterpret_cast<const float4*>(&ws[(m*5 + kw)*COUT + og*4]);
                wreg[0] = w4.x; wreg[1] = w4.y; wreg[2] = w4.z; wreg[3] = w4.w;
            } else if constexpr (GO == 2) {
                float2 w2 = *reinterpret_cast<const float2*>(&ws[(m*5 + kw)*COUT + og*2]);
                wreg[0] = w2.x; wreg[1] = w2.y;
            } else {
                #pragma unroll
                for (int g = 0; g < GO; g++) wreg[g] = ws[(m*5 + kw)*COUT + og*GO + g];
            }
            #pragma unroll
            for (int g = 0; g < GO; g++)
                #pragma unroll
                for (int ww = 0; ww < WOT; ww++)
                    #pragma unroll
                    for (int tv = 0; tv < TV; tv++)
                        acc[g][ww][tv] += v[ww+kw][tv] * wreg[g];
        }
    };

    load_v(0, va);
    int m = 0;
    #pragma unroll 1
    for (; m + 2 <= M; m += 2) {
        load_v(m + 1, vb);
        fma_step(m, va);
        if (m + 2 < M) load_v(m + 2, va);
        fma_step(m + 1, vb);
    }
    if (m < M) fma_step(m, va);

    float* zb = z + (size_t)t0*TS_OUT + (size_t)n*COUT*HOUT*WOUT
                  + (size_t)og*GO*HOUT*WOUT + (size_t)ho*WOUT + wo;
    #pragma unroll
    for (int tv = 0; tv < TV; tv++)
        #pragma unroll
        for (int g = 0; g < GO; g++) {
            float* op = zb + (size_t)tv*TS_OUT + (size_t)g*HOUT*WOUT;
            #pragma unroll
            for (int j2 = 0; j2 < WOT/2; j2++) {
                float2 d; d.x = acc[g][2*j2][tv]; d.y = acc[g][2*j2+1][tv];
                reinterpret_cast<float2*>(op)[j2] = d;
            }
        }
}

// ---------------- LIF scan over T: z -> spikes ----------------
template<int SZ>
__global__ void k_scan(const float* __restrict__ z, float* __restrict__ s_out) {
    int idx = blockIdx.x * blockDim.x + threadIdx.x;
    if (idx >= SZ) return;
    float u = 0.f;
    #pragma unroll 4
    for (int t = 0; t < T_; t++) {
        u += z[(size_t)t*SZ + idx];
        float s = (u >= 1.0f) ? 1.0f : 0.0f;
        u -= s;
        s_out[(size_t)t*SZ + idx] = s;
    }
}

// ---------------- fused LIF scan + 2x2 avg-pool + LIF scan ----------------
template<int C,int HIN>
__global__ void k_scanpool(const float* __restrict__ z, float* __restrict__ out) {
    constexpr int HO = HIN/2;
    constexpr size_t TS_IN  = (size_t)N_*C*HIN*HIN;
    constexpr size_t TS_OUT = (size_t)N_*C*HO*HO;
    int idx = blockIdx.x * blockDim.x + threadIdx.x;
    if (idx >= N_*C*HO*HO) return;
    int wo = idx % HO; int t1 = idx / HO;
    int ho = t1 % HO;  int t2 = t1 / HO;
    int c  = t2 % C;   int n  = t2 / C;
    const float* ip = z + ((size_t)n*C + c)*HIN*HIN + (size_t)(2*ho)*HIN + 2*wo;
    float* op = out + ((size_t)n*C + c)*HO*HO + (size_t)ho*HO + wo;
    float u0 = 0.f, u1 = 0.f, u2 = 0.f, u3 = 0.f, up = 0.f;
    #pragma unroll 4
    for (int t = 0; t < T_; t++) {
        const float* p = ip + (size_t)t*TS_IN;
        float2 r0 = *reinterpret_cast<const float2*>(p);
        float2 r1 = *reinterpret_cast<const float2*>(p + HIN);
        u0 += r0.x; float s0 = (u0 >= 1.0f) ? 1.0f : 0.0f; u0 -= s0;
        u1 += r0.y; float s1 = (u1 >= 1.0f) ? 1.0f : 0.0f; u1 -= s1;
        u2 += r1.x; float s2 = (u2 >= 1.0f) ? 1.0f : 0.0f; u2 -= s2;
        u3 += r1.y; float s3 = (u3 >= 1.0f) ? 1.0f : 0.0f; u3 -= s3;
        up += 0.25f*(s0 + s1 + s2 + s3);
        float sp = (up >= 1.0f) ? 1.0f : 0.0f; up -= sp;
        op[(size_t)t*TS_OUT] = sp;
    }
}

// ---------------- fc1 GEMM ----------------
__global__ void k_fc1(const float* __restrict__ bf1) {
    __shared__ float sin_[4][512];
    int t0 = blockIdx.x*4, n = blockIdx.y, o = threadIdx.x;
    for (int i = o; i < 4*512; i += 128) {
        int tv = i >> 9, k = i & 511;
        sin_[tv][k] = g_p2[((size_t)(t0+tv)*N_ + n)*512 + k];
    }
    __syncthreads();
    float b = bf1[o];
    float acc[4] = {b, b, b, b};
    #pragma unroll 4
    for (int k = 0; k < 512; k++) {
        float w = g_wt1[k*128 + o];
        #pragma unroll
        for (int tv = 0; tv < 4; tv++) acc[tv] += sin_[tv][k] * w;
    }
    #pragma unroll
    for (int tv = 0; tv < 4; tv++)
        g_z1[((size_t)(t0+tv)*N_ + n)*128 + o] = acc[tv];
}

// ---------------- head ----------------
__global__ void k_head(const float* __restrict__ Wf2, const float* __restrict__ bf2,
                       float* __restrict__ out) {
    int n = blockIdx.x, o = threadIdx.x;
    __shared__ float s1[128];
    __shared__ float w2[2][128];
    w2[0][o] = Wf2[o];
    w2[1][o] = Wf2[128 + o];
    float u1 = 0.f, u2 = 0.f, ssum = 0.f;
    float b2 = (o < 2) ? bf2[o] : 0.f;
    __syncthreads();
    for (int t = 0; t < T_; t++) {
        float z = g_z1[((size_t)t*N_ + n)*128 + o];
        u1 += z;
        float s = (u1 >= 1.0f) ? 1.0f : 0.0f;
        u1 -= s;
        s1[o] = s;
        __syncthreads();
        if (o < 2) {
            float d = b2;
            #pragma unroll 8
            for (int k = 0; k < 128; k++) d += s1[k] * w2[o][k];
            u2 += d;
            float s2 = (u2 >= 1.0f) ? 1.0f : 0.0f;
            u2 -= s2;
            ssum += s2;
        }
        __syncthreads();
    }
    if (o < 2) out[n*2 + o] = ssum * (1.0f / T_);
}

// ---------------- launch ----------------
extern "C" void kernel_launch(void* const* d_in, const int* in_sizes, int n_in,
                              void* d_out, int out_size) {
    (void)in_sizes; (void)n_in; (void)out_size;
    const float* x   = (const float*)d_in[0];
    const float* Wc1 = (const float*)d_in[1];
    const float* bc1 = (const float*)d_in[2];
    const float* Wc2 = (const float*)d_in[3];
    const float* bc2 = (const float*)d_in[4];
    const float* Wc3 = (const float*)d_in[5];
    const float* bc3 = (const float*)d_in[6];
    const float* Wf1 = (const float*)d_in[7];
    const float* bf1 = (const float*)d_in[8];
    const float* Wf2 = (const float*)d_in[9];
    const float* bf2 = (const float*)d_in[10];
    float* out = (float*)d_out;

    float *p_xt, *p_z1c, *p_h1, *p_z2c, *p_p1, *p_z3c, *p_p2;
    cudaGetSymbolAddress((void**)&p_xt,  g_xt);
    cudaGetSymbolAddress((void**)&p_z1c, g_z1c);
    cudaGetSymbolAddress((void**)&p_h1,  g_h1);
    cudaGetSymbolAddress((void**)&p_z2c, g_z2c);
    cudaGetSymbolAddress((void**)&p_p1,  g_p1);
    cudaGetSymbolAddress((void**)&p_z3c, g_z3c);
    cudaGetSymbolAddress((void**)&p_p2,  g_p2);

    // conv1: scalar, CIN=1, GO=2, WOT=4, HOT=4, TV=2 -> block (56,4)=224 thr
    auto c1 = k_conv<1,16,32,32,2,4,4,2,2>;
    // conv3: scalar, CIN=32, GO=4, WOT=4, HOT=8, TV=2 -> block (16,8)=128 thr
    auto c3 = k_conv<32,32,12,12,4,4,8,2,4>;
    cudaFuncSetAttribute(c3, cudaFuncAttributeMaxDynamicSharedMemorySize, 32*32*25*4);
    constexpr int SMEM_C2 = 25088 + 3*25*32*16*2;   // 101,888 B
    cudaFuncSetAttribute(k_conv2_mma, cudaFuncAttributeMaxDynamicSharedMemorySize, SMEM_C2);

    k_transpose_x<<<(N_*1024 + 255)/256, 256>>>(x);
    k_transpose_wf1<<<(128*512 + 255)/256, 256>>>(Wf1);
    k_split_w2<<<(12800 + 255)/256, 256>>>(Wc2);

    constexpr int SZ1 = N_*16*28*28;

    c1<<<dim3(7*(T_/2), N_), dim3(56, 4), 16*1*25*4>>>(p_xt, Wc1, bc1, p_z1c);
    k_scan<SZ1><<<(SZ1 + 255)/256, 256>>>(p_z1c, p_h1);

    k_conv2_mma<<<dim3(T_, N_), 384, SMEM_C2>>>(p_h1, bc2, p_z2c);
    k_scanpool<32,24><<<(N_*32*12*12 + 255)/256, 256>>>(p_z2c, p_p1);

    c3<<<dim3(1*(T_/2), N_), dim3(16, 8), 32*32*25*4>>>(p_p1, Wc3, bc3, p_z3c);
    k_scanpool<32,8><<<(N_*32*4*4 + 255)/256, 256>>>(p_z3c, p_p2);

    k_fc1<<<dim3(T_/4, N_), 128>>>(bf1);
    k_head<<<N_, 128>>>(Wf2, bf2, out);
}

// round 8
// speedup vs baseline: 1.8216x; 1.1330x over previous
#include <cuda_runtime.h>
#include <cuda_bf16.h>

#define N_ 32
#define T_ 48

// ---------------- scratch (t-major: [T][N][C][H][W]) ----------------
__device__ float g_xt[(size_t)T_*N_*32*32];          // x transposed (C=1)
__device__ float g_z1c[(size_t)T_*N_*16*28*28];      // conv1 pre-acts
__device__ float g_h1[(size_t)T_*N_*16*28*28];       // conv1 spikes
__device__ float g_z2c[(size_t)T_*N_*32*24*24];      // conv2 pre-acts
__device__ float g_p1[(size_t)T_*N_*32*12*12];       // pool1 spikes
__device__ float g_z3c[(size_t)T_*N_*32*8*8];        // conv3 pre-acts
__device__ float g_p2[(size_t)T_*N_*32*4*4];         // pool2 spikes
__device__ float g_wt1[512*128];                     // Wf1 transposed [k][o]
__device__ float g_z1[(size_t)T_*N_*128];            // fc1 pre-activations
__device__ __nv_bfloat16 g_w2s[3*25*32*16];          // conv2 w split [s][j][o][c16]
__device__ __nv_bfloat16 g_w3s[3*25*32*32];          // conv3 w split [s][j][o][c32]

// ---------------- transpose x: [N,1,32,32,T] -> [T][N][32][32] ----------------
__global__ void k_transpose_x(const float* __restrict__ x) {
    int idx = blockIdx.x * blockDim.x + threadIdx.x;
    if (idx >= N_*32*32) return;
    int n = idx >> 10, hw = idx & 1023;
    const float* xp = x + (size_t)idx * T_;
    #pragma unroll
    for (int t = 0; t < T_; t++)
        g_xt[((size_t)t*N_ + n)*1024 + hw] = xp[t];
}

// ---------------- transpose Wf1: [128][512] -> [512][128] ----------------
__global__ void k_transpose_wf1(const float* __restrict__ Wf1) {
    int idx = blockIdx.x * blockDim.x + threadIdx.x;
    if (idx >= 128*512) return;
    int o = idx >> 9, k = idx & 511;
    g_wt1[k*128 + o] = Wf1[idx];
}

// ---------------- weight splits: fp32 -> 3x bf16 ----------------
__global__ void k_split_w2(const float* __restrict__ Wc2) {
    int i = blockIdx.x*256 + threadIdx.x;   // 25*32*16 = 12800
    if (i >= 12800) return;
    int c = i % 16, o = (i/16) % 32, j = i/512;
    int kh = j/5, kw = j%5;
    float w = Wc2[((o*16 + c)*5 + kh)*5 + kw];
    __nv_bfloat16 h = __float2bfloat16(w);
    float r = w - __bfloat162float(h);
    __nv_bfloat16 m = __float2bfloat16(r);
    float r2 = r - __bfloat162float(m);
    g_w2s[0*12800 + i] = h;
    g_w2s[1*12800 + i] = m;
    g_w2s[2*12800 + i] = __float2bfloat16(r2);
}

__global__ void k_split_w3(const float* __restrict__ Wc3) {
    int i = blockIdx.x*256 + threadIdx.x;   // 25*32*32 = 25600
    if (i >= 25600) return;
    int c = i % 32, o = (i/32) % 32, j = i/1024;
    int kh = j/5, kw = j%5;
    float w = Wc3[((o*32 + c)*5 + kh)*5 + kw];
    __nv_bfloat16 h = __float2bfloat16(w);
    float r = w - __bfloat162float(h);
    __nv_bfloat16 m = __float2bfloat16(r);
    float r2 = r - __bfloat162float(m);
    g_w3s[0*25600 + i] = h;
    g_w3s[1*25600 + i] = m;
    g_w3s[2*25600 + i] = __float2bfloat16(r2);
}

// ---------------- mma.m16n8k16 bf16 helper ----------------
__device__ __forceinline__ void mma16816(float* c, const unsigned* a,
                                         unsigned b0, unsigned b1) {
    asm volatile(
        "mma.sync.aligned.m16n8k16.row.col.f32.bf16.bf16.f32 "
        "{%0,%1,%2,%3}, {%4,%5,%6,%7}, {%8,%9}, {%0,%1,%2,%3};"
        : "+f"(c[0]), "+f"(c[1]), "+f"(c[2]), "+f"(c[3])
        : "r"(a[0]), "r"(a[1]), "r"(a[2]), "r"(a[3]), "r"(b0), "r"(b1));
}

// ---------------- conv2 via tensor cores ----------------
// One block per (t,n). Row pad 18 elems -> conflict-free A/B fragment LDS.
#define C2_PAD 18
__global__ void __launch_bounds__(384, 1)
k_conv2_mma(const float* __restrict__ h1s,
            const float* __restrict__ bc2,
            float* __restrict__ z2c) {
    extern __shared__ char sm[];
    __nv_bfloat16* sIn = reinterpret_cast<__nv_bfloat16*>(sm);            // 784*18
    __nv_bfloat16* sW  = reinterpret_cast<__nv_bfloat16*>(sm + 784*C2_PAD*2);

    int t = blockIdx.x, n = blockIdx.y;
    int tid = threadIdx.x;

    // stage weights with pad: rows of 16 -> stride 18
    {
        const unsigned* src = reinterpret_cast<const unsigned*>(g_w2s);
        unsigned* dst = reinterpret_cast<unsigned*>(sW);
        for (int i = tid; i < 3*25*32*16/2; i += 384) {
            int e = i*2; int row = e >> 4; int c = e & 15;
            dst[(row*C2_PAD + c) >> 1] = src[i];
        }
    }
    // stage input: h1 [t][n][c][784] fp32 -> sIn[hw][c] bf16
    {
        const float* ib = h1s + ((size_t)t*N_ + n)*16*784;
        for (int i = tid; i < 16*784; i += 384) {
            int c = i / 784, hw = i % 784;
            sIn[hw*C2_PAD + c] = __float2bfloat16(ib[i]);
        }
    }
    __syncthreads();

    int w    = tid >> 5;
    int lane = tid & 31;
    int qid  = lane >> 2;
    int rid  = lane & 3;

    float acc[2][6][4];
    #pragma unroll
    for (int mt = 0; mt < 2; mt++)
        #pragma unroll
        for (int nt = 0; nt < 6; nt++)
            #pragma unroll
            for (int r = 0; r < 4; r++) acc[mt][nt][r] = 0.f;

    int bbase[6];
    #pragma unroll
    for (int nt = 0; nt < 6; nt++) {
        int sp = w*48 + nt*8 + qid;
        int ho = sp / 24, wo = sp % 24;
        bbase[nt] = (ho*28 + wo)*C2_PAD + rid*2;
    }

    #pragma unroll 1
    for (int j = 0; j < 25; j++) {
        int kh = j / 5, kw = j % 5;
        int shift = (kh*28 + kw)*C2_PAD;

        unsigned aF[3][2][4];
        #pragma unroll
        for (int s = 0; s < 3; s++)
            #pragma unroll
            for (int mt = 0; mt < 2; mt++) {
                const __nv_bfloat16* wp = sW + ((s*25 + j)*32 + mt*16)*C2_PAD;
                aF[s][mt][0] = *reinterpret_cast<const unsigned*>(wp + qid*C2_PAD     + rid*2);
                aF[s][mt][1] = *reinterpret_cast<const unsigned*>(wp + (qid+8)*C2_PAD + rid*2);
                aF[s][mt][2] = *reinterpret_cast<const unsigned*>(wp + qid*C2_PAD     + rid*2 + 8);
                aF[s][mt][3] = *reinterpret_cast<const unsigned*>(wp + (qid+8)*C2_PAD + rid*2 + 8);
            }

        #pragma unroll
        for (int nt = 0; nt < 6; nt++) {
            const __nv_bfloat16* bp = sIn + bbase[nt] + shift;
            unsigned b0 = *reinterpret_cast<const unsigned*>(bp);
            unsigned b1 = *reinterpret_cast<const unsigned*>(bp + 8);
            #pragma unroll
            for (int s = 0; s < 3; s++)
                #pragma unroll
                for (int mt = 0; mt < 2; mt++)
                    mma16816(acc[mt][nt], aF[s][mt], b0, b1);
        }
    }

    float* zb = z2c + ((size_t)t*N_ + n)*32*576;
    #pragma unroll
    for (int mt = 0; mt < 2; mt++) {
        int o0 = mt*16 + qid;
        float b0 = bc2[o0], b1 = bc2[o0 + 8];
        #pragma unroll
        for (int nt = 0; nt < 6; nt++) {
            int sp = w*48 + nt*8 + rid*2;
            float2 d0; d0.x = acc[mt][nt][0] + b0; d0.y = acc[mt][nt][1] + b0;
            float2 d1; d1.x = acc[mt][nt][2] + b1; d1.y = acc[mt][nt][3] + b1;
            *reinterpret_cast<float2*>(zb + (size_t)o0*576 + sp)       = d0;
            *reinterpret_cast<float2*>(zb + (size_t)(o0+8)*576 + sp)   = d1;
        }
    }
}

// ---------------- conv3 via tensor cores ----------------
// Block = (3 timesteps, n). C[32 o][64 sp] = sum_j W_j[32x32] * B_j[32x64], 3 splits.
// 8 warps: warp -> (mt = w>>2, nt pair = w&3). Row pad 34 -> conflict-free LDS.
#define C3_PAD 34
#define C3_TB  3
__global__ void __launch_bounds__(256, 1)
k_conv3_mma(const float* __restrict__ p1s,
            const float* __restrict__ bc3,
            float* __restrict__ z3c) {
    extern __shared__ char sm[];
    __nv_bfloat16* sW  = reinterpret_cast<__nv_bfloat16*>(sm);                 // 3*25*32 rows of 34
    __nv_bfloat16* sIn = reinterpret_cast<__nv_bfloat16*>(sm + 3*25*32*C3_PAD*2);

    int t0 = blockIdx.x * C3_TB, n = blockIdx.y;
    int tid = threadIdx.x;

    // stage weights: rows of 32 -> stride 34
    {
        const unsigned* src = reinterpret_cast<const unsigned*>(g_w3s);
        unsigned* dst = reinterpret_cast<unsigned*>(sW);
        for (int i = tid; i < 3*25*32*32/2; i += 256) {
            int e = i*2; int row = e >> 5; int c = e & 31;
            dst[(row*C3_PAD + c) >> 1] = src[i];
        }
    }
    // stage input: p1 [t][n][c][144] fp32 -> sIn[(tt*144+hw)][c] bf16
    for (int tt = 0; tt < C3_TB; tt++) {
        const float* ib = p1s + ((size_t)(t0+tt)*N_ + n)*32*144;
        for (int i = tid; i < 32*144; i += 256) {
            int c = i / 144, hw = i % 144;
            sIn[(tt*144 + hw)*C3_PAD + c] = __float2bfloat16(ib[i]);
        }
    }
    __syncthreads();

    int w    = tid >> 5;
    int lane = tid & 31;
    int qid  = lane >> 2;
    int rid  = lane & 3;
    int mt   = w >> 2;               // 0..1
    int ntp  = w & 3;                // 0..3  -> nt rows {2*ntp, 2*ntp+1}

    int o0 = mt*16 + qid;
    float bb0 = bc3[o0], bb1 = bc3[o0 + 8];

    #pragma unroll 1
    for (int tt = 0; tt < C3_TB; tt++) {
        float acc[2][4];
        #pragma unroll
        for (int q = 0; q < 2; q++)
            #pragma unroll
            for (int r = 0; r < 4; r++) acc[q][r] = 0.f;

        #pragma unroll 1
        for (int j = 0; j < 25; j++) {
            int kh = j / 5, kw = j % 5;
            #pragma unroll
            for (int kc = 0; kc < 2; kc++) {
                unsigned aF[3][4];
                #pragma unroll
                for (int s = 0; s < 3; s++) {
                    const __nv_bfloat16* wp = sW + ((s*25 + j)*32 + mt*16)*C3_PAD + kc*16;
                    aF[s][0] = *reinterpret_cast<const unsigned*>(wp + qid*C3_PAD     + rid*2);
                    aF[s][1] = *reinterpret_cast<const unsigned*>(wp + (qid+8)*C3_PAD + rid*2);
                    aF[s][2] = *reinterpret_cast<const unsigned*>(wp + qid*C3_PAD     + rid*2 + 8);
                    aF[s][3] = *reinterpret_cast<const unsigned*>(wp + (qid+8)*C3_PAD + rid*2 + 8);
                }
                #pragma unroll
                for (int q = 0; q < 2; q++) {
                    int ntr = ntp*2 + q;         // output row 0..7
                    const __nv_bfloat16* bp = sIn
                        + (size_t)(tt*144 + (ntr + kh)*12 + qid + kw)*C3_PAD
                        + kc*16 + rid*2;
                    unsigned b0 = *reinterpret_cast<const unsigned*>(bp);
                    unsigned b1 = *reinterpret_cast<const unsigned*>(bp + 8);
                    #pragma unroll
                    for (int s = 0; s < 3; s++)
                        mma16816(acc[q], aF[s], b0, b1);
                }
            }
        }

        float* zb = z3c + ((size_t)(t0+tt)*N_ + n)*32*64;
        #pragma unroll
        for (int q = 0; q < 2; q++) {
            int sp = (ntp*2 + q)*8 + rid*2;
            float2 d0; d0.x = acc[q][0] + bb0; d0.y = acc[q][1] + bb0;
            float2 d1; d1.x = acc[q][2] + bb1; d1.y = acc[q][3] + bb1;
            *reinterpret_cast<float2*>(zb + (size_t)o0*64 + sp)     = d0;
            *reinterpret_cast<float2*>(zb + (size_t)(o0+8)*64 + sp) = d1;
        }
    }
}

// ---------------- 5x5 VALID conv, scalar pipelined (conv1 only) ----------------
template<int CIN,int COUT,int HIN,int WIN,int GO,int WOT,int HOT,int TV,int MINB>
__global__ void
__launch_bounds__(((WIN-4)/WOT)*(COUT/GO)*HOT, MINB)
k_conv(const float* __restrict__ in,
       const float* __restrict__ Wc,
       const float* __restrict__ bc,
       float* __restrict__ z) {
    constexpr int HOUT = HIN-4, WOUT = WIN-4;
    constexpr int NWG  = WOUT/WOT;
    constexpr int NOG  = COUT/GO;
    constexpr int LANES = NWG*NOG;
    constexpr int HBLK = HOUT/HOT;
    constexpr int M    = CIN*5;
    constexpr size_t TS_IN  = (size_t)N_*CIN*HIN*WIN;
    constexpr size_t TS_OUT = (size_t)N_*COUT*HOUT*WOUT;
    extern __shared__ float ws[];
    {
        int tid = threadIdx.y*LANES + threadIdx.x;
        for (int i = tid; i < COUT*CIN*25; i += LANES*HOT) {
            int oc = i % COUT;
            int ck = i / COUT;
            ws[i] = Wc[oc*CIN*25 + ck];
        }
    }
    __syncthreads();

    int hb = blockIdx.x % HBLK;
    int t0 = (blockIdx.x / HBLK) * TV;
    int n  = blockIdx.y;
    int wg = threadIdx.x % NWG;
    int og = threadIdx.x / NWG;
    int wo = wg * WOT;
    int ho = hb*HOT + threadIdx.y;

    float acc[GO][WOT][TV];
    #pragma unroll
    for (int g = 0; g < GO; g++) {
        float b = bc[og*GO + g];
        #pragma unroll
        for (int ww = 0; ww < WOT; ww++)
            #pragma unroll
            for (int tv = 0; tv < TV; tv++) acc[g][ww][tv] = b;
    }

    const float* inb = in + (size_t)t0*TS_IN + (size_t)n*CIN*HIN*WIN
                          + (size_t)ho*WIN + wo;

    float va[WOT+4][TV], vb[WOT+4][TV];

    auto load_v = [&](int m, float (&v)[WOT+4][TV]) {
        int c = m / 5, kh = m % 5;
        const float* ip = inb + ((size_t)c*HIN + kh)*WIN;
        #pragma unroll
        for (int tv = 0; tv < TV; tv++) {
            const float2* p2 = reinterpret_cast<const float2*>(ip + (size_t)tv*TS_IN);
            #pragma unroll
            for (int j2 = 0; j2 < (WOT+4)/2; j2++) {
                float2 d = p2[j2];
                v[2*j2][tv]   = d.x;
                v[2*j2+1][tv] = d.y;
            }
        }
    };

    auto fma_step = [&](int m, float (&v)[WOT+4][TV]) {
        #pragma unroll
        for (int kw = 0; kw < 5; kw++) {
            float wreg[GO];
            if constexpr (GO == 4) {
                float4 w4 = *reinterpret_cast<const float4*>(&ws[(m*5 + kw)*COUT + og*4]);
                wreg[0] = w4.x; wreg[1] = w4.y; wreg[2] = w4.z; wreg[3] = w4.w;
            } else if constexpr (GO == 2) {
                float2 w2 = *reinterpret_cast<const float2*>(&ws[(m*5 + kw)*COUT + og*2]);
                wreg[0] = w2.x; wreg[1] = w2.y;
            } else {
                #pragma unroll
                for (int g = 0; g < GO; g++) wreg[g] = ws[(m*5 + kw)*COUT + og*GO + g];
            }
            #pragma unroll
            for (int g = 0; g < GO; g++)
                #pragma unroll
                for (int ww = 0; ww < WOT; ww++)
                    #pragma unroll
                    for (int tv = 0; tv < TV; tv++)
                        acc[g][ww][tv] += v[ww+kw][tv] * wreg[g];
        }
    };

    load_v(0, va);
    int m = 0;
    #pragma unroll 1
    for (; m + 2 <= M; m += 2) {
        load_v(m + 1, vb);
        fma_step(m, va);
        if (m + 2 < M) load_v(m + 2, va);
        fma_step(m + 1, vb);
    }
    if (m < M) fma_step(m, va);

    float* zb = z + (size_t)t0*TS_OUT + (size_t)n*COUT*HOUT*WOUT
                  + (size_t)og*GO*HOUT*WOUT + (size_t)ho*WOUT + wo;
    #pragma unroll
    for (int tv = 0; tv < TV; tv++)
        #pragma unroll
        for (int g = 0; g < GO; g++) {
            float* op = zb + (size_t)tv*TS_OUT + (size_t)g*HOUT*WOUT;
            #pragma unroll
            for (int j2 = 0; j2 < WOT/2; j2++) {
                float2 d; d.x = acc[g][2*j2][tv]; d.y = acc[g][2*j2+1][tv];
                reinterpret_cast<float2*>(op)[j2] = d;
            }
        }
}

// ---------------- LIF scan over T: z -> spikes ----------------
template<int SZ>
__global__ void k_scan(const float* __restrict__ z, float* __restrict__ s_out) {
    int idx = blockIdx.x * blockDim.x + threadIdx.x;
    if (idx >= SZ) return;
    float u = 0.f;
    #pragma unroll 4
    for (int t = 0; t < T_; t++) {
        u += z[(size_t)t*SZ + idx];
        float s = (u >= 1.0f) ? 1.0f : 0.0f;
        u -= s;
        s_out[(size_t)t*SZ + idx] = s;
    }
}

// ---------------- fused LIF scan + 2x2 avg-pool + LIF scan ----------------
template<int C,int HIN>
__global__ void k_scanpool(const float* __restrict__ z, float* __restrict__ out) {
    constexpr int HO = HIN/2;
    constexpr size_t TS_IN  = (size_t)N_*C*HIN*HIN;
    constexpr size_t TS_OUT = (size_t)N_*C*HO*HO;
    int idx = blockIdx.x * blockDim.x + threadIdx.x;
    if (idx >= N_*C*HO*HO) return;
    int wo = idx % HO; int t1 = idx / HO;
    int ho = t1 % HO;  int t2 = t1 / HO;
    int c  = t2 % C;   int n  = t2 / C;
    const float* ip = z + ((size_t)n*C + c)*HIN*HIN + (size_t)(2*ho)*HIN + 2*wo;
    float* op = out + ((size_t)n*C + c)*HO*HO + (size_t)ho*HO + wo;
    float u0 = 0.f, u1 = 0.f, u2 = 0.f, u3 = 0.f, up = 0.f;
    #pragma unroll 4
    for (int t = 0; t < T_; t++) {
        const float* p = ip + (size_t)t*TS_IN;
        float2 r0 = *reinterpret_cast<const float2*>(p);
        float2 r1 = *reinterpret_cast<const float2*>(p + HIN);
        u0 += r0.x; float s0 = (u0 >= 1.0f) ? 1.0f : 0.0f; u0 -= s0;
        u1 += r0.y; float s1 = (u1 >= 1.0f) ? 1.0f : 0.0f; u1 -= s1;
        u2 += r1.x; float s2 = (u2 >= 1.0f) ? 1.0f : 0.0f; u2 -= s2;
        u3 += r1.y; float s3 = (u3 >= 1.0f) ? 1.0f : 0.0f; u3 -= s3;
        up += 0.25f*(s0 + s1 + s2 + s3);
        float sp = (up >= 1.0f) ? 1.0f : 0.0f; up -= sp;
        op[(size_t)t*TS_OUT] = sp;
    }
}

// ---------------- fc1 GEMM ----------------
__global__ void k_fc1(const float* __restrict__ bf1) {
    __shared__ float sin_[4][512];
    int t0 = blockIdx.x*4, n = blockIdx.y, o = threadIdx.x;
    for (int i = o; i < 4*512; i += 128) {
        int tv = i >> 9, k = i & 511;
        sin_[tv][k] = g_p2[((size_t)(t0+tv)*N_ + n)*512 + k];
    }
    __syncthreads();
    float b = bf1[o];
    float acc[4] = {b, b, b, b};
    #pragma unroll 4
    for (int k = 0; k < 512; k++) {
        float w = g_wt1[k*128 + o];
        #pragma unroll
        for (int tv = 0; tv < 4; tv++) acc[tv] += sin_[tv][k] * w;
    }
    #pragma unroll
    for (int tv = 0; tv < 4; tv++)
        g_z1[((size_t)(t0+tv)*N_ + n)*128 + o] = acc[tv];
}

// ---------------- head ----------------
__global__ void k_head(const float* __restrict__ Wf2, const float* __restrict__ bf2,
                       float* __restrict__ out) {
    int n = blockIdx.x, o = threadIdx.x;
    __shared__ float s1[128];
    __shared__ float w2[2][128];
    w2[0][o] = Wf2[o];
    w2[1][o] = Wf2[128 + o];
    float u1 = 0.f, u2 = 0.f, ssum = 0.f;
    float b2 = (o < 2) ? bf2[o] : 0.f;
    __syncthreads();
    for (int t = 0; t < T_; t++) {
        float z = g_z1[((size_t)t*N_ + n)*128 + o];
        u1 += z;
        float s = (u1 >= 1.0f) ? 1.0f : 0.0f;
        u1 -= s;
        s1[o] = s;
        __syncthreads();
        if (o < 2) {
            float d = b2;
            #pragma unroll 8
            for (int k = 0; k < 128; k++) d += s1[k] * w2[o][k];
            u2 += d;
            float s2 = (u2 >= 1.0f) ? 1.0f : 0.0f;
            u2 -= s2;
            ssum += s2;
        }
        __syncthreads();
    }
    if (o < 2) out[n*2 + o] = ssum * (1.0f / T_);
}

// ---------------- launch ----------------
extern "C" void kernel_launch(void* const* d_in, const int* in_sizes, int n_in,
                              void* d_out, int out_size) {
    (void)in_sizes; (void)n_in; (void)out_size;
    const float* x   = (const float*)d_in[0];
    const float* Wc1 = (const float*)d_in[1];
    const float* bc1 = (const float*)d_in[2];
    const float* Wc2 = (const float*)d_in[3];
    const float* bc2 = (const float*)d_in[4];
    const float* Wc3 = (const float*)d_in[5];
    const float* bc3 = (const float*)d_in[6];
    const float* Wf1 = (const float*)d_in[7];
    const float* bf1 = (const float*)d_in[8];
    const float* Wf2 = (const float*)d_in[9];
    const float* bf2 = (const float*)d_in[10];
    float* out = (float*)d_out;

    float *p_xt, *p_z1c, *p_h1, *p_z2c, *p_p1, *p_z3c, *p_p2;
    cudaGetSymbolAddress((void**)&p_xt,  g_xt);
    cudaGetSymbolAddress((void**)&p_z1c, g_z1c);
    cudaGetSymbolAddress((void**)&p_h1,  g_h1);
    cudaGetSymbolAddress((void**)&p_z2c, g_z2c);
    cudaGetSymbolAddress((void**)&p_p1,  g_p1);
    cudaGetSymbolAddress((void**)&p_z3c, g_z3c);
    cudaGetSymbolAddress((void**)&p_p2,  g_p2);

    // conv1: scalar, CIN=1, GO=2, WOT=4, HOT=4, TV=2 -> block (56,4)=224 thr
    auto c1 = k_conv<1,16,32,32,2,4,4,2,2>;

    constexpr int SMEM_C2 = 784*C2_PAD*2 + 3*25*32*C2_PAD*2;          // 28224 + 86400
    constexpr int SMEM_C3 = 3*25*32*C3_PAD*2 + C3_TB*144*C3_PAD*2;    // 163200 + 29376
    cudaFuncSetAttribute(k_conv2_mma, cudaFuncAttributeMaxDynamicSharedMemorySize, SMEM_C2);
    cudaFuncSetAttribute(k_conv3_mma, cudaFuncAttributeMaxDynamicSharedMemorySize, SMEM_C3);

    k_transpose_x<<<(N_*1024 + 255)/256, 256>>>(x);
    k_transpose_wf1<<<(128*512 + 255)/256, 256>>>(Wf1);
    k_split_w2<<<(12800 + 255)/256, 256>>>(Wc2);
    k_split_w3<<<(25600 + 255)/256, 256>>>(Wc3);

    constexpr int SZ1 = N_*16*28*28;

    c1<<<dim3(7*(T_/2), N_), dim3(56, 4), 16*1*25*4>>>(p_xt, Wc1, bc1, p_z1c);
    k_scan<SZ1><<<(SZ1 + 255)/256, 256>>>(p_z1c, p_h1);

    k_conv2_mma<<<dim3(T_, N_), 384, SMEM_C2>>>(p_h1, bc2, p_z2c);
    k_scanpool<32,24><<<(N_*32*12*12 + 255)/256, 256>>>(p_z2c, p_p1);

    k_conv3_mma<<<dim3(T_/C3_TB, N_), 256, SMEM_C3>>>(p_p1, bc3, p_z3c);
    k_scanpool<32,8><<<(N_*32*4*4 + 255)/256, 256>>>(p_z3c, p_p2);

    k_fc1<<<dim3(T_/4, N_), 128>>>(bf1);
    k_head<<<N_, 128>>>(Wf2, bf2, out);
}

// round 10
// speedup vs baseline: 1.9372x; 1.0635x over previous
#include <cuda_runtime.h>
#include <cuda_bf16.h>

#define N_ 32
#define T_ 48

// ---------------- scratch (t-major: [T][N][C][H][W]) ----------------
__device__ float g_xt[(size_t)T_*N_*32*32];
__device__ float g_z1c[(size_t)T_*N_*16*28*28];
__device__ float g_h1[(size_t)T_*N_*16*28*28];
__device__ float g_z2c[(size_t)T_*N_*32*24*24];
__device__ float g_p1[(size_t)T_*N_*32*12*12];
__device__ float g_z3c[(size_t)T_*N_*32*8*8];
__device__ float g_p2[(size_t)T_*N_*32*4*4];
__device__ float g_wt1[512*128];
__device__ float g_z1[(size_t)T_*N_*128];
__device__ __nv_bfloat16 g_w2s[3*25*32*16];   // conv2 w split [s][j][o][c16]
__device__ __nv_bfloat16 g_w3s[3*25*32*32];   // conv3 w split [s][j][o][c32]

// ---------------- transpose x ----------------
__global__ void k_transpose_x(const float* __restrict__ x) {
    int idx = blockIdx.x * blockDim.x + threadIdx.x;
    if (idx >= N_*32*32) return;
    int n = idx >> 10, hw = idx & 1023;
    const float* xp = x + (size_t)idx * T_;
    #pragma unroll
    for (int t = 0; t < T_; t++)
        g_xt[((size_t)t*N_ + n)*1024 + hw] = xp[t];
}

// ---------------- transpose Wf1 ----------------
__global__ void k_transpose_wf1(const float* __restrict__ Wf1) {
    int idx = blockIdx.x * blockDim.x + threadIdx.x;
    if (idx >= 128*512) return;
    int o = idx >> 9, k = idx & 511;
    g_wt1[k*128 + o] = Wf1[idx];
}

// ---------------- weight splits: fp32 -> 3x bf16 ----------------
__global__ void k_split_w2(const float* __restrict__ Wc2) {
    int i = blockIdx.x*256 + threadIdx.x;   // 12800
    if (i >= 12800) return;
    int c = i % 16, o = (i/16) % 32, j = i/512;
    int kh = j/5, kw = j%5;
    float w = Wc2[((o*16 + c)*5 + kh)*5 + kw];
    __nv_bfloat16 h = __float2bfloat16(w);
    float r = w - __bfloat162float(h);
    __nv_bfloat16 m = __float2bfloat16(r);
    float r2 = r - __bfloat162float(m);
    g_w2s[0*12800 + i] = h;
    g_w2s[1*12800 + i] = m;
    g_w2s[2*12800 + i] = __float2bfloat16(r2);
}

__global__ void k_split_w3(const float* __restrict__ Wc3) {
    int i = blockIdx.x*256 + threadIdx.x;   // 25600
    if (i >= 25600) return;
    int c = i % 32, o = (i/32) % 32, j = i/1024;
    int kh = j/5, kw = j%5;
    float w = Wc3[((o*32 + c)*5 + kh)*5 + kw];
    __nv_bfloat16 h = __float2bfloat16(w);
    float r = w - __bfloat162float(h);
    __nv_bfloat16 m = __float2bfloat16(r);
    float r2 = r - __bfloat162float(m);
    g_w3s[0*25600 + i] = h;
    g_w3s[1*25600 + i] = m;
    g_w3s[2*25600 + i] = __float2bfloat16(r2);
}

// ---------------- mma / ldmatrix helpers ----------------
__device__ __forceinline__ void mma16816(float* c, const unsigned* a,
                                         unsigned b0, unsigned b1) {
    asm volatile(
        "mma.sync.aligned.m16n8k16.row.col.f32.bf16.bf16.f32 "
        "{%0,%1,%2,%3}, {%4,%5,%6,%7}, {%8,%9}, {%0,%1,%2,%3};"
        : "+f"(c[0]), "+f"(c[1]), "+f"(c[2]), "+f"(c[3])
        : "r"(a[0]), "r"(a[1]), "r"(a[2]), "r"(a[3]), "r"(b0), "r"(b1));
}
__device__ __forceinline__ void ldsm_x4(unsigned* d, unsigned a) {
    asm volatile("ldmatrix.sync.aligned.m8n8.x4.shared.b16 {%0,%1,%2,%3}, [%4];"
                 : "=r"(d[0]), "=r"(d[1]), "=r"(d[2]), "=r"(d[3]) : "r"(a));
}
__device__ __forceinline__ void ldsm_x2(unsigned& d0, unsigned& d1, unsigned a) {
    asm volatile("ldmatrix.sync.aligned.m8n8.x2.shared.b16 {%0,%1}, [%2];"
                 : "=r"(d0), "=r"(d1) : "r"(a));
}

// ---------------- conv2 via tensor cores + ldmatrix ----------------
// Row stride 24 bf16 = 48 B: 16B-aligned (ldmatrix requirement) AND 48%128!=0
// -> 8 consecutive rows hit distinct 16B banks (offsets mod 128 all distinct).
#define C2_PAD 24
__global__ void __launch_bounds__(384, 1)
k_conv2_mma(const float* __restrict__ h1s,
            const float* __restrict__ bc2,
            float* __restrict__ z2c) {
    extern __shared__ char sm[];
    __nv_bfloat16* sIn = reinterpret_cast<__nv_bfloat16*>(sm);            // 784*C2_PAD
    __nv_bfloat16* sW  = reinterpret_cast<__nv_bfloat16*>(sm + 784*C2_PAD*2);

    int t = blockIdx.x, n = blockIdx.y;
    int tid = threadIdx.x;

    {   // stage weights: row stride C2_PAD
        const unsigned* src = reinterpret_cast<const unsigned*>(g_w2s);
        unsigned* dst = reinterpret_cast<unsigned*>(sW);
        for (int i = tid; i < 3*25*32*16/2; i += 384) {
            int e = i*2; int row = e >> 4; int c = e & 15;
            dst[(row*C2_PAD + c) >> 1] = src[i];
        }
    }
    {   // stage input: [c][784] fp32 -> sIn[hw][c] bf16
        const float* ib = h1s + ((size_t)t*N_ + n)*16*784;
        for (int i = tid; i < 16*784; i += 384) {
            int c = i / 784, hw = i % 784;
            sIn[hw*C2_PAD + c] = __float2bfloat16(ib[i]);
        }
    }
    __syncthreads();

    int w    = tid >> 5;
    int lane = tid & 31;
    int qid  = lane >> 2;
    int rid  = lane & 3;
    int mi   = lane >> 3;       // ldmatrix matrix index 0..3
    int rr   = lane & 7;        // row within matrix
    int matB = mi & 1;          // for x2

    unsigned sInA = (unsigned)__cvta_generic_to_shared(sIn);
    unsigned sWA  = (unsigned)__cvta_generic_to_shared(sW);

    // A row addresses per (s,mt): row = mt*16 + (mi&1)*8 + rr, col half (mi>>1)*8
    unsigned aaddr[3][2];
    #pragma unroll
    for (int s = 0; s < 3; s++)
        #pragma unroll
        for (int mt = 0; mt < 2; mt++) {
            int row = mt*16 + (mi & 1)*8 + rr;
            aaddr[s][mt] = sWA + (((s*25)*32 + row)*C2_PAD + (mi >> 1)*8)*2;
        }

    // B row addresses per nt: row sp = w*48 + nt*8 + rr, col half matB*8
    unsigned baddr[6];
    #pragma unroll
    for (int nt = 0; nt < 6; nt++) {
        int sp = w*48 + nt*8 + rr;
        int ho = sp / 24, wo = sp % 24;
        baddr[nt] = sInA + ((ho*28 + wo)*C2_PAD + matB*8)*2;
    }

    float acc[2][6][4];
    #pragma unroll
    for (int mt = 0; mt < 2; mt++)
        #pragma unroll
        for (int nt = 0; nt < 6; nt++)
            #pragma unroll
            for (int r = 0; r < 4; r++) acc[mt][nt][r] = 0.f;

    #pragma unroll 1
    for (int j = 0; j < 25; j++) {
        int kh = j / 5, kw = j % 5;
        unsigned aoff = (unsigned)(j*32*C2_PAD*2);
        unsigned boff = (unsigned)((kh*28 + kw)*C2_PAD*2);

        unsigned aF[3][2][4];
        #pragma unroll
        for (int s = 0; s < 3; s++)
            #pragma unroll
            for (int mt = 0; mt < 2; mt++)
                ldsm_x4(aF[s][mt], aaddr[s][mt] + aoff);

        #pragma unroll
        for (int nt = 0; nt < 6; nt++) {
            unsigned b0, b1;
            ldsm_x2(b0, b1, baddr[nt] + boff);
            #pragma unroll
            for (int s = 0; s < 3; s++)
                #pragma unroll
                for (int mt = 0; mt < 2; mt++)
                    mma16816(acc[mt][nt], aF[s][mt], b0, b1);
        }
    }

    float* zb = z2c + ((size_t)t*N_ + n)*32*576;
    #pragma unroll
    for (int mt = 0; mt < 2; mt++) {
        int o0 = mt*16 + qid;
        float b0 = bc2[o0], b1 = bc2[o0 + 8];
        #pragma unroll
        for (int nt = 0; nt < 6; nt++) {
            int sp = w*48 + nt*8 + rid*2;
            float2 d0; d0.x = acc[mt][nt][0] + b0; d0.y = acc[mt][nt][1] + b0;
            float2 d1; d1.x = acc[mt][nt][2] + b1; d1.y = acc[mt][nt][3] + b1;
            *reinterpret_cast<float2*>(zb + (size_t)o0*576 + sp)     = d0;
            *reinterpret_cast<float2*>(zb + (size_t)(o0+8)*576 + sp) = d1;
        }
    }
}

// ---------------- conv3 via tensor cores + ldmatrix ----------------
// Row stride 40 bf16 = 80 B: 16B-aligned, 80%128!=0 -> conflict-free LDSM.
#define C3_PAD 40
#define C3_TB  3
__global__ void __launch_bounds__(256, 1)
k_conv3_mma(const float* __restrict__ p1s,
            const float* __restrict__ bc3,
            float* __restrict__ z3c) {
    extern __shared__ char sm[];
    __nv_bfloat16* sW  = reinterpret_cast<__nv_bfloat16*>(sm);
    __nv_bfloat16* sIn = reinterpret_cast<__nv_bfloat16*>(sm + 3*25*32*C3_PAD*2);

    int t0 = blockIdx.x * C3_TB, n = blockIdx.y;
    int tid = threadIdx.x;

    {   // stage weights: row stride C3_PAD
        const unsigned* src = reinterpret_cast<const unsigned*>(g_w3s);
        unsigned* dst = reinterpret_cast<unsigned*>(sW);
        for (int i = tid; i < 3*25*32*32/2; i += 256) {
            int e = i*2; int row = e >> 5; int c = e & 31;
            dst[(row*C3_PAD + c) >> 1] = src[i];
        }
    }
    for (int tt = 0; tt < C3_TB; tt++) {
        const float* ib = p1s + ((size_t)(t0+tt)*N_ + n)*32*144;
        for (int i = tid; i < 32*144; i += 256) {
            int c = i / 144, hw = i % 144;
            sIn[(tt*144 + hw)*C3_PAD + c] = __float2bfloat16(ib[i]);
        }
    }
    __syncthreads();

    int w    = tid >> 5;
    int lane = tid & 31;
    int qid  = lane >> 2;
    int rid  = lane & 3;
    int mi   = lane >> 3;
    int rr   = lane & 7;
    int matB = mi & 1;
    int mt   = w >> 2;          // 0..1
    int ntp  = w & 3;           // 0..3

    unsigned sInA = (unsigned)__cvta_generic_to_shared(sIn);
    unsigned sWA  = (unsigned)__cvta_generic_to_shared(sW);

    unsigned aaddr[3];
    #pragma unroll
    for (int s = 0; s < 3; s++) {
        int row = mt*16 + (mi & 1)*8 + rr;
        aaddr[s] = sWA + (((s*25)*32 + row)*C3_PAD + (mi >> 1)*8)*2;
    }
    unsigned baddr[2];
    #pragma unroll
    for (int q = 0; q < 2; q++) {
        int ntr = ntp*2 + q;
        baddr[q] = sInA + ((ntr*12 + rr)*C3_PAD + matB*8)*2;
    }

    int o0 = mt*16 + qid;
    float bb0 = bc3[o0], bb1 = bc3[o0 + 8];

    #pragma unroll 1
    for (int tt = 0; tt < C3_TB; tt++) {
        float acc[2][4];
        #pragma unroll
        for (int q = 0; q < 2; q++)
            #pragma unroll
            for (int r = 0; r < 4; r++) acc[q][r] = 0.f;

        unsigned ttoff = (unsigned)(tt*144*C3_PAD*2);

        #pragma unroll 1
        for (int j = 0; j < 25; j++) {
            int kh = j / 5, kw = j % 5;
            #pragma unroll
            for (int kc = 0; kc < 2; kc++) {
                unsigned aoff = (unsigned)((j*32*C3_PAD + kc*16)*2);
                unsigned boff = ttoff + (unsigned)(((kh*12 + kw)*C3_PAD + kc*16)*2);
                unsigned aF[3][4];
                #pragma unroll
                for (int s = 0; s < 3; s++) ldsm_x4(aF[s], aaddr[s] + aoff);
                #pragma unroll
                for (int q = 0; q < 2; q++) {
                    unsigned b0, b1;
                    ldsm_x2(b0, b1, baddr[q] + boff);
                    #pragma unroll
                    for (int s = 0; s < 3; s++)
                        mma16816(acc[q], aF[s], b0, b1);
                }
            }
        }

        float* zb = z3c + ((size_t)(t0+tt)*N_ + n)*32*64;
        #pragma unroll
        for (int q = 0; q < 2; q++) {
            int sp = (ntp*2 + q)*8 + rid*2;
            float2 d0; d0.x = acc[q][0] + bb0; d0.y = acc[q][1] + bb0;
            float2 d1; d1.x = acc[q][2] + bb1; d1.y = acc[q][3] + bb1;
            *reinterpret_cast<float2*>(zb + (size_t)o0*64 + sp)     = d0;
            *reinterpret_cast<float2*>(zb + (size_t)(o0+8)*64 + sp) = d1;
        }
    }
}

// ---------------- 5x5 VALID conv, scalar pipelined (conv1 only) ----------------
template<int CIN,int COUT,int HIN,int WIN,int GO,int WOT,int HOT,int TV,int MINB>
__global__ void
__launch_bounds__(((WIN-4)/WOT)*(COUT/GO)*HOT, MINB)
k_conv(const float* __restrict__ in,
       const float* __restrict__ Wc,
       const float* __restrict__ bc,
       float* __restrict__ z) {
    constexpr int HOUT = HIN-4, WOUT = WIN-4;
    constexpr int NWG  = WOUT/WOT;
    constexpr int NOG  = COUT/GO;
    constexpr int LANES = NWG*NOG;
    constexpr int HBLK = HOUT/HOT;
    constexpr int M    = CIN*5;
    constexpr size_t TS_IN  = (size_t)N_*CIN*HIN*WIN;
    constexpr size_t TS_OUT = (size_t)N_*COUT*HOUT*WOUT;
    extern __shared__ float ws[];
    {
        int tid = threadIdx.y*LANES + threadIdx.x;
        for (int i = tid; i < COUT*CIN*25; i += LANES*HOT) {
            int oc = i % COUT;
            int ck = i / COUT;
            ws[i] = Wc[oc*CIN*25 + ck];
        }
    }
    __syncthreads();

    int hb = blockIdx.x % HBLK;
    int t0 = (blockIdx.x / HBLK) * TV;
    int n  = blockIdx.y;
    int wg = threadIdx.x % NWG;
    int og = threadIdx.x / NWG;
    int wo = wg * WOT;
    int ho = hb*HOT + threadIdx.y;

    float acc[GO][WOT][TV];
    #pragma unroll
    for (int g = 0; g < GO; g++) {
        float b = bc[og*GO + g];
        #pragma unroll
        for (int ww = 0; ww < WOT; ww++)
            #pragma unroll
            for (int tv = 0; tv < TV; tv++) acc[g][ww][tv] = b;
    }

    const float* inb = in + (size_t)t0*TS_IN + (size_t)n*CIN*HIN*WIN
                          + (size_t)ho*WIN + wo;

    float va[WOT+4][TV], vb[WOT+4][TV];

    auto load_v = [&](int m, float (&v)[WOT+4][TV]) {
        int c = m / 5, kh = m % 5;
        const float* ip = inb + ((size_t)c*HIN + kh)*WIN;
        #pragma unroll
        for (int tv = 0; tv < TV; tv++) {
            const float2* p2 = reinterpret_cast<const float2*>(ip + (size_t)tv*TS_IN);
            #pragma unroll
            for (int j2 = 0; j2 < (WOT+4)/2; j2++) {
                float2 d = p2[j2];
                v[2*j2][tv]   = d.x;
                v[2*j2+1][tv] = d.y;
            }
        }
    };

    auto fma_step = [&](int m, float (&v)[WOT+4][TV]) {
        #pragma unroll
        for (int kw = 0; kw < 5; kw++) {
            float wreg[GO];
            if constexpr (GO == 4) {
                float4 w4 = *reinterpret_cast<const float4*>(&ws[(m*5 + kw)*COUT + og*4]);
                wreg[0] = w4.x; wreg[1] = w4.y; wreg[2] = w4.z; wreg[3] = w4.w;
            } else if constexpr (GO == 2) {
                float2 w2 = *reinterpret_cast<const float2*>(&ws[(m*5 + kw)*COUT + og*2]);
                wreg[0] = w2.x; wreg[1] = w2.y;
            } else {
                #pragma unroll
                for (int g = 0; g < GO; g++) wreg[g] = ws[(m*5 + kw)*COUT + og*GO + g];
            }
            #pragma unroll
            for (int g = 0; g < GO; g++)
                #pragma unroll
                for (int ww = 0; ww < WOT; ww++)
                    #pragma unroll
                    for (int tv = 0; tv < TV; tv++)
                        acc[g][ww][tv] += v[ww+kw][tv] * wreg[g];
        }
    };

    load_v(0, va);
    int m = 0;
    #pragma unroll 1
    for (; m + 2 <= M; m += 2) {
        load_v(m + 1, vb);
        fma_step(m, va);
        if (m + 2 < M) load_v(m + 2, va);
        fma_step(m + 1, vb);
    }
    if (m < M) fma_step(m, va);

    float* zb = z + (size_t)t0*TS_OUT + (size_t)n*COUT*HOUT*WOUT
                  + (size_t)og*GO*HOUT*WOUT + (size_t)ho*WOUT + wo;
    #pragma unroll
    for (int tv = 0; tv < TV; tv++)
        #pragma unroll
        for (int g = 0; g < GO; g++) {
            float* op = zb + (size_t)tv*TS_OUT + (size_t)g*HOUT*WOUT;
            #pragma unroll
            for (int j2 = 0; j2 < WOT/2; j2++) {
                float2 d; d.x = acc[g][2*j2][tv]; d.y = acc[g][2*j2+1][tv];
                reinterpret_cast<float2*>(op)[j2] = d;
            }
        }
}

// ---------------- LIF scan ----------------
template<int SZ>
__global__ void k_scan(const float* __restrict__ z, float* __restrict__ s_out) {
    int idx = blockIdx.x * blockDim.x + threadIdx.x;
    if (idx >= SZ) return;
    float u = 0.f;
    #pragma unroll 4
    for (int t = 0; t < T_; t++) {
        u += z[(size_t)t*SZ + idx];
        float s = (u >= 1.0f) ? 1.0f : 0.0f;
        u -= s;
        s_out[(size_t)t*SZ + idx] = s;
    }
}

// ---------------- fused LIF scan + 2x2 avg-pool + LIF scan ----------------
template<int C,int HIN>
__global__ void k_scanpool(const float* __restrict__ z, float* __restrict__ out) {
    constexpr int HO = HIN/2;
    constexpr size_t TS_IN  = (size_t)N_*C*HIN*HIN;
    constexpr size_t TS_OUT = (size_t)N_*C*HO*HO;
    int idx = blockIdx.x * blockDim.x + threadIdx.x;
    if (idx >= N_*C*HO*HO) return;
    int wo = idx % HO; int t1 = idx / HO;
    int ho = t1 % HO;  int t2 = t1 / HO;
    int c  = t2 % C;   int n  = t2 / C;
    const float* ip = z + ((size_t)n*C + c)*HIN*HIN + (size_t)(2*ho)*HIN + 2*wo;
    float* op = out + ((size_t)n*C + c)*HO*HO + (size_t)ho*HO + wo;
    float u0 = 0.f, u1 = 0.f, u2 = 0.f, u3 = 0.f, up = 0.f;
    #pragma unroll 4
    for (int t = 0; t < T_; t++) {
        const float* p = ip + (size_t)t*TS_IN;
        float2 r0 = *reinterpret_cast<const float2*>(p);
        float2 r1 = *reinterpret_cast<const float2*>(p + HIN);
        u0 += r0.x; float s0 = (u0 >= 1.0f) ? 1.0f : 0.0f; u0 -= s0;
        u1 += r0.y; float s1 = (u1 >= 1.0f) ? 1.0f : 0.0f; u1 -= s1;
        u2 += r1.x; float s2 = (u2 >= 1.0f) ? 1.0f : 0.0f; u2 -= s2;
        u3 += r1.y; float s3 = (u3 >= 1.0f) ? 1.0f : 0.0f; u3 -= s3;
        up += 0.25f*(s0 + s1 + s2 + s3);
        float sp = (up >= 1.0f) ? 1.0f : 0.0f; up -= sp;
        op[(size_t)t*TS_OUT] = sp;
    }
}

// ---------------- fc1 GEMM ----------------
__global__ void k_fc1(const float* __restrict__ bf1) {
    __shared__ float sin_[4][512];
    int t0 = blockIdx.x*4, n = blockIdx.y, o = threadIdx.x;
    for (int i = o; i < 4*512; i += 128) {
        int tv = i >> 9, k = i & 511;
        sin_[tv][k] = g_p2[((size_t)(t0+tv)*N_ + n)*512 + k];
    }
    __syncthreads();
    float b = bf1[o];
    float acc[4] = {b, b, b, b};
    #pragma unroll 4
    for (int k = 0; k < 512; k++) {
        float w = g_wt1[k*128 + o];
        #pragma unroll
        for (int tv = 0; tv < 4; tv++) acc[tv] += sin_[tv][k] * w;
    }
    #pragma unroll
    for (int tv = 0; tv < 4; tv++)
        g_z1[((size_t)(t0+tv)*N_ + n)*128 + o] = acc[tv];
}

// ---------------- head ----------------
__global__ void k_head(const float* __restrict__ Wf2, const float* __restrict__ bf2,
                       float* __restrict__ out) {
    int n = blockIdx.x, o = threadIdx.x;
    __shared__ float s1[128];
    __shared__ float w2[2][128];
    w2[0][o] = Wf2[o];
    w2[1][o] = Wf2[128 + o];
    float u1 = 0.f, u2 = 0.f, ssum = 0.f;
    float b2 = (o < 2) ? bf2[o] : 0.f;
    __syncthreads();
    for (int t = 0; t < T_; t++) {
        float z = g_z1[((size_t)t*N_ + n)*128 + o];
        u1 += z;
        float s = (u1 >= 1.0f) ? 1.0f : 0.0f;
        u1 -= s;
        s1[o] = s;
        __syncthreads();
        if (o < 2) {
            float d = b2;
            #pragma unroll 8
            for (int k = 0; k < 128; k++) d += s1[k] * w2[o][k];
            u2 += d;
            float s2 = (u2 >= 1.0f) ? 1.0f : 0.0f;
            u2 -= s2;
            ssum += s2;
        }
        __syncthreads();
    }
    if (o < 2) out[n*2 + o] = ssum * (1.0f / T_);
}

// ---------------- launch ----------------
extern "C" void kernel_launch(void* const* d_in, const int* in_sizes, int n_in,
                              void* d_out, int out_size) {
    (void)in_sizes; (void)n_in; (void)out_size;
    const float* x   = (const float*)d_in[0];
    const float* Wc1 = (const float*)d_in[1];
    const float* bc1 = (const float*)d_in[2];
    const float* Wc2 = (const float*)d_in[3];
    const float* bc2 = (const float*)d_in[4];
    const float* Wc3 = (const float*)d_in[5];
    const float* bc3 = (const float*)d_in[6];
    const float* Wf1 = (const float*)d_in[7];
    const float* bf1 = (const float*)d_in[8];
    const float* Wf2 = (const float*)d_in[9];
    const float* bf2 = (const float*)d_in[10];
    float* out = (float*)d_out;

    float *p_xt, *p_z1c, *p_h1, *p_z2c, *p_p1, *p_z3c, *p_p2;
    cudaGetSymbolAddress((void**)&p_xt,  g_xt);
    cudaGetSymbolAddress((void**)&p_z1c, g_z1c);
    cudaGetSymbolAddress((void**)&p_h1,  g_h1);
    cudaGetSymbolAddress((void**)&p_z2c, g_z2c);
    cudaGetSymbolAddress((void**)&p_p1,  g_p1);
    cudaGetSymbolAddress((void**)&p_z3c, g_z3c);
    cudaGetSymbolAddress((void**)&p_p2,  g_p2);

    // conv1: scalar, GO=4, WOT=4, HOT=7, TV=2 -> block (28,7)=196 thr
    auto c1 = k_conv<1,16,32,32,4,4,7,2,2>;

    constexpr int SMEM_C2 = 784*C2_PAD*2 + 3*25*32*C2_PAD*2;          // 37632 + 115200
    constexpr int SMEM_C3 = 3*25*32*C3_PAD*2 + C3_TB*144*C3_PAD*2;    // 192000 + 34560
    cudaFuncSetAttribute(k_conv2_mma, cudaFuncAttributeMaxDynamicSharedMemorySize, SMEM_C2);
    cudaFuncSetAttribute(k_conv3_mma, cudaFuncAttributeMaxDynamicSharedMemorySize, SMEM_C3);

    k_transpose_x<<<(N_*1024 + 255)/256, 256>>>(x);
    k_transpose_wf1<<<(128*512 + 255)/256, 256>>>(Wf1);
    k_split_w2<<<(12800 + 255)/256, 256>>>(Wc2);
    k_split_w3<<<(25600 + 255)/256, 256>>>(Wc3);

    constexpr int SZ1 = N_*16*28*28;

    c1<<<dim3(4*(T_/2), N_), dim3(28, 7), 16*1*25*4>>>(p_xt, Wc1, bc1, p_z1c);
    k_scan<SZ1><<<(SZ1 + 255)/256, 256>>>(p_z1c, p_h1);

    k_conv2_mma<<<dim3(T_, N_), 384, SMEM_C2>>>(p_h1, bc2, p_z2c);
    k_scanpool<32,24><<<(N_*32*12*12 + 255)/256, 256>>>(p_z2c, p_p1);

    k_conv3_mma<<<dim3(T_/C3_TB, N_), 256, SMEM_C3>>>(p_p1, bc3, p_z3c);
    k_scanpool<32,8><<<(N_*32*4*4 + 255)/256, 256>>>(p_z3c, p_p2);

    k_fc1<<<dim3(T_/4, N_), 128>>>(bf1);
    k_head<<<N_, 128>>>(Wf2, bf2, out);
}

// round 11
// speedup vs baseline: 2.2976x; 1.1860x over previous
#include <cuda_runtime.h>
#include <cuda_bf16.h>
#include <cuda_fp16.h>

#define N_ 32
#define T_ 48

// ---------------- scratch (t-major: [T][N][C][H][W]) ----------------
__device__ float g_xt[(size_t)T_*N_*32*32];
__device__ float g_z1c[(size_t)T_*N_*16*28*28];
__device__ float g_h1[(size_t)T_*N_*16*28*28];
__device__ float g_z2c[(size_t)T_*N_*32*24*24];
__device__ float g_p1[(size_t)T_*N_*32*12*12];
__device__ float g_z3c[(size_t)T_*N_*32*8*8];
__device__ float g_p2[(size_t)T_*N_*32*4*4];
__device__ float g_wt1[512*128];
__device__ float g_z1[(size_t)T_*N_*128];
__device__ __half g_w2s[2*25*32*16];   // conv2 w split [s][j][o][c16], fp16 2-way
__device__ __half g_w3s[2*25*32*32];   // conv3 w split [s][j][o][c32], fp16 2-way

// ---------------- transpose x ----------------
__global__ void k_transpose_x(const float* __restrict__ x) {
    int idx = blockIdx.x * blockDim.x + threadIdx.x;
    if (idx >= N_*32*32) return;
    int n = idx >> 10, hw = idx & 1023;
    const float* xp = x + (size_t)idx * T_;
    #pragma unroll
    for (int t = 0; t < T_; t++)
        g_xt[((size_t)t*N_ + n)*1024 + hw] = xp[t];
}

// ---------------- transpose Wf1 ----------------
__global__ void k_transpose_wf1(const float* __restrict__ Wf1) {
    int idx = blockIdx.x * blockDim.x + threadIdx.x;
    if (idx >= 128*512) return;
    int o = idx >> 9, k = idx & 511;
    g_wt1[k*128 + o] = Wf1[idx];
}

// ---------------- weight splits: fp32 -> 2x fp16 ----------------
__global__ void k_split_w2(const float* __restrict__ Wc2) {
    int i = blockIdx.x*256 + threadIdx.x;   // 12800
    if (i >= 12800) return;
    int c = i % 16, o = (i/16) % 32, j = i/512;
    int kh = j/5, kw = j%5;
    float w = Wc2[((o*16 + c)*5 + kh)*5 + kw];
    __half h = __float2half_rn(w);
    float r = w - __half2float(h);
    g_w2s[0*12800 + i] = h;
    g_w2s[1*12800 + i] = __float2half_rn(r);
}

__global__ void k_split_w3(const float* __restrict__ Wc3) {
    int i = blockIdx.x*256 + threadIdx.x;   // 25600
    if (i >= 25600) return;
    int c = i % 32, o = (i/32) % 32, j = i/1024;
    int kh = j/5, kw = j%5;
    float w = Wc3[((o*32 + c)*5 + kh)*5 + kw];
    __half h = __float2half_rn(w);
    float r = w - __half2float(h);
    g_w3s[0*25600 + i] = h;
    g_w3s[1*25600 + i] = __float2half_rn(r);
}

// ---------------- mma / ldmatrix helpers ----------------
__device__ __forceinline__ void mma16816(float* c, const unsigned* a,
                                         unsigned b0, unsigned b1) {
    asm volatile(
        "mma.sync.aligned.m16n8k16.row.col.f32.f16.f16.f32 "
        "{%0,%1,%2,%3}, {%4,%5,%6,%7}, {%8,%9}, {%0,%1,%2,%3};"
        : "+f"(c[0]), "+f"(c[1]), "+f"(c[2]), "+f"(c[3])
        : "r"(a[0]), "r"(a[1]), "r"(a[2]), "r"(a[3]), "r"(b0), "r"(b1));
}
__device__ __forceinline__ void ldsm_x4(unsigned* d, unsigned a) {
    asm volatile("ldmatrix.sync.aligned.m8n8.x4.shared.b16 {%0,%1,%2,%3}, [%4];"
                 : "=r"(d[0]), "=r"(d[1]), "=r"(d[2]), "=r"(d[3]) : "r"(a));
}
__device__ __forceinline__ void ldsm_x2(unsigned& d0, unsigned& d1, unsigned a) {
    asm volatile("ldmatrix.sync.aligned.m8n8.x2.shared.b16 {%0,%1}, [%2];"
                 : "=r"(d0), "=r"(d1) : "r"(a));
}

// ---------------- conv2 via tensor cores + ldmatrix, 2 timesteps/block ----------------
// Row stride 24 halfs = 48 B: 16B-aligned, 48%128!=0 -> conflict-free LDSM.
#define C2_PAD 24
#define C2_TB  2
__global__ void __launch_bounds__(384, 1)
k_conv2_mma(const float* __restrict__ h1s,
            const float* __restrict__ bc2,
            float* __restrict__ z2c) {
    extern __shared__ char sm[];
    __half* sIn = reinterpret_cast<__half*>(sm);                         // [C2_TB][784][C2_PAD]
    __half* sW  = reinterpret_cast<__half*>(sm + C2_TB*784*C2_PAD*2);    // [2][25][32][C2_PAD]

    int t0 = blockIdx.x * C2_TB, n = blockIdx.y;
    int tid = threadIdx.x;

    {   // stage weights: row stride C2_PAD
        const unsigned* src = reinterpret_cast<const unsigned*>(g_w2s);
        unsigned* dst = reinterpret_cast<unsigned*>(sW);
        for (int i = tid; i < 2*25*32*16/2; i += 384) {
            int e = i*2; int row = e >> 4; int c = e & 15;
            dst[(row*C2_PAD + c) >> 1] = src[i];
        }
    }
    // stage inputs: [tt][c][784] fp32 -> sIn[tt][hw][c] fp16
    for (int tt = 0; tt < C2_TB; tt++) {
        const float* ib = h1s + ((size_t)(t0+tt)*N_ + n)*16*784;
        __half* sI = sIn + tt*784*C2_PAD;
        for (int i = tid; i < 16*784; i += 384) {
            int c = i / 784, hw = i % 784;
            sI[hw*C2_PAD + c] = __float2half_rn(ib[i]);
        }
    }
    __syncthreads();

    int w    = tid >> 5;
    int lane = tid & 31;
    int qid  = lane >> 2;
    int rid  = lane & 3;
    int mi   = lane >> 3;
    int rr   = lane & 7;
    int matB = mi & 1;

    unsigned sInA = (unsigned)__cvta_generic_to_shared(sIn);
    unsigned sWA  = (unsigned)__cvta_generic_to_shared(sW);

    unsigned aaddr[2][2];
    #pragma unroll
    for (int s = 0; s < 2; s++)
        #pragma unroll
        for (int mt = 0; mt < 2; mt++) {
            int row = mt*16 + (mi & 1)*8 + rr;
            aaddr[s][mt] = sWA + (((s*25)*32 + row)*C2_PAD + (mi >> 1)*8)*2;
        }

    unsigned baddr[6];
    #pragma unroll
    for (int nt = 0; nt < 6; nt++) {
        int sp = w*48 + nt*8 + rr;
        int ho = sp / 24, wo = sp % 24;
        baddr[nt] = sInA + ((ho*28 + wo)*C2_PAD + matB*8)*2;
    }

    #pragma unroll 1
    for (int tt = 0; tt < C2_TB; tt++) {
        unsigned ttoff = (unsigned)(tt*784*C2_PAD*2);

        float acc[2][6][4];
        #pragma unroll
        for (int mt = 0; mt < 2; mt++)
            #pragma unroll
            for (int nt = 0; nt < 6; nt++)
                #pragma unroll
                for (int r = 0; r < 4; r++) acc[mt][nt][r] = 0.f;

        #pragma unroll 1
        for (int j = 0; j < 25; j++) {
            int kh = j / 5, kw = j % 5;
            unsigned aoff = (unsigned)(j*32*C2_PAD*2);
            unsigned boff = ttoff + (unsigned)((kh*28 + kw)*C2_PAD*2);

            unsigned aF[2][2][4];
            #pragma unroll
            for (int s = 0; s < 2; s++)
                #pragma unroll
                for (int mt = 0; mt < 2; mt++)
                    ldsm_x4(aF[s][mt], aaddr[s][mt] + aoff);

            #pragma unroll
            for (int nt = 0; nt < 6; nt++) {
                unsigned b0, b1;
                ldsm_x2(b0, b1, baddr[nt] + boff);
                #pragma unroll
                for (int s = 0; s < 2; s++)
                    #pragma unroll
                    for (int mt = 0; mt < 2; mt++)
                        mma16816(acc[mt][nt], aF[s][mt], b0, b1);
            }
        }

        float* zb = z2c + ((size_t)(t0+tt)*N_ + n)*32*576;
        #pragma unroll
        for (int mt = 0; mt < 2; mt++) {
            int o0 = mt*16 + qid;
            float b0 = bc2[o0], b1 = bc2[o0 + 8];
            #pragma unroll
            for (int nt = 0; nt < 6; nt++) {
                int sp = w*48 + nt*8 + rid*2;
                float2 d0; d0.x = acc[mt][nt][0] + b0; d0.y = acc[mt][nt][1] + b0;
                float2 d1; d1.x = acc[mt][nt][2] + b1; d1.y = acc[mt][nt][3] + b1;
                *reinterpret_cast<float2*>(zb + (size_t)o0*576 + sp)     = d0;
                *reinterpret_cast<float2*>(zb + (size_t)(o0+8)*576 + sp) = d1;
            }
        }
    }
}

// ---------------- conv3 via tensor cores + ldmatrix, 4 timesteps/block ----------------
// Row stride 40 halfs = 80 B: 16B-aligned, 80%128!=0 -> conflict-free LDSM.
#define C3_PAD 40
#define C3_TB  4
__global__ void __launch_bounds__(256, 1)
k_conv3_mma(const float* __restrict__ p1s,
            const float* __restrict__ bc3,
            float* __restrict__ z3c) {
    extern __shared__ char sm[];
    __half* sW  = reinterpret_cast<__half*>(sm);                          // [2][25][32][C3_PAD]
    __half* sIn = reinterpret_cast<__half*>(sm + 2*25*32*C3_PAD*2);       // [C3_TB][144][C3_PAD]

    int t0 = blockIdx.x * C3_TB, n = blockIdx.y;
    int tid = threadIdx.x;

    {
        const unsigned* src = reinterpret_cast<const unsigned*>(g_w3s);
        unsigned* dst = reinterpret_cast<unsigned*>(sW);
        for (int i = tid; i < 2*25*32*32/2; i += 256) {
            int e = i*2; int row = e >> 5; int c = e & 31;
            dst[(row*C3_PAD + c) >> 1] = src[i];
        }
    }
    for (int tt = 0; tt < C3_TB; tt++) {
        const float* ib = p1s + ((size_t)(t0+tt)*N_ + n)*32*144;
        __half* sI = sIn + tt*144*C3_PAD;
        for (int i = tid; i < 32*144; i += 256) {
            int c = i / 144, hw = i % 144;
            sI[hw*C3_PAD + c] = __float2half_rn(ib[i]);
        }
    }
    __syncthreads();

    int w    = tid >> 5;
    int lane = tid & 31;
    int qid  = lane >> 2;
    int rid  = lane & 3;
    int mi   = lane >> 3;
    int rr   = lane & 7;
    int matB = mi & 1;
    int mt   = w >> 2;
    int ntp  = w & 3;

    unsigned sInA = (unsigned)__cvta_generic_to_shared(sIn);
    unsigned sWA  = (unsigned)__cvta_generic_to_shared(sW);

    unsigned aaddr[2];
    #pragma unroll
    for (int s = 0; s < 2; s++) {
        int row = mt*16 + (mi & 1)*8 + rr;
        aaddr[s] = sWA + (((s*25)*32 + row)*C3_PAD + (mi >> 1)*8)*2;
    }
    unsigned baddr[2];
    #pragma unroll
    for (int q = 0; q < 2; q++) {
        int ntr = ntp*2 + q;
        baddr[q] = sInA + ((ntr*12 + rr)*C3_PAD + matB*8)*2;
    }

    int o0 = mt*16 + qid;
    float bb0 = bc3[o0], bb1 = bc3[o0 + 8];

    #pragma unroll 1
    for (int tt = 0; tt < C3_TB; tt++) {
        float acc[2][4];
        #pragma unroll
        for (int q = 0; q < 2; q++)
            #pragma unroll
            for (int r = 0; r < 4; r++) acc[q][r] = 0.f;

        unsigned ttoff = (unsigned)(tt*144*C3_PAD*2);

        #pragma unroll 1
        for (int j = 0; j < 25; j++) {
            int kh = j / 5, kw = j % 5;
            #pragma unroll
            for (int kc = 0; kc < 2; kc++) {
                unsigned aoff = (unsigned)((j*32*C3_PAD + kc*16)*2);
                unsigned boff = ttoff + (unsigned)(((kh*12 + kw)*C3_PAD + kc*16)*2);
                unsigned aF[2][4];
                #pragma unroll
                for (int s = 0; s < 2; s++) ldsm_x4(aF[s], aaddr[s] + aoff);
                #pragma unroll
                for (int q = 0; q < 2; q++) {
                    unsigned b0, b1;
                    ldsm_x2(b0, b1, baddr[q] + boff);
                    #pragma unroll
                    for (int s = 0; s < 2; s++)
                        mma16816(acc[q], aF[s], b0, b1);
                }
            }
        }

        float* zb = z3c + ((size_t)(t0+tt)*N_ + n)*32*64;
        #pragma unroll
        for (int q = 0; q < 2; q++) {
            int sp = (ntp*2 + q)*8 + rid*2;
            float2 d0; d0.x = acc[q][0] + bb0; d0.y = acc[q][1] + bb0;
            float2 d1; d1.x = acc[q][2] + bb1; d1.y = acc[q][3] + bb1;
            *reinterpret_cast<float2*>(zb + (size_t)o0*64 + sp)     = d0;
            *reinterpret_cast<float2*>(zb + (size_t)(o0+8)*64 + sp) = d1;
        }
    }
}

// ---------------- 5x5 VALID conv, scalar pipelined (conv1 only) ----------------
template<int CIN,int COUT,int HIN,int WIN,int GO,int WOT,int HOT,int TV,int MINB>
__global__ void
__launch_bounds__(((WIN-4)/WOT)*(COUT/GO)*HOT, MINB)
k_conv(const float* __restrict__ in,
       const float* __restrict__ Wc,
       const float* __restrict__ bc,
       float* __restrict__ z) {
    constexpr int HOUT = HIN-4, WOUT = WIN-4;
    constexpr int NWG  = WOUT/WOT;
    constexpr int NOG  = COUT/GO;
    constexpr int LANES = NWG*NOG;
    constexpr int HBLK = HOUT/HOT;
    constexpr int M    = CIN*5;
    constexpr size_t TS_IN  = (size_t)N_*CIN*HIN*WIN;
    constexpr size_t TS_OUT = (size_t)N_*COUT*HOUT*WOUT;
    extern __shared__ float ws[];
    {
        int tid = threadIdx.y*LANES + threadIdx.x;
        for (int i = tid; i < COUT*CIN*25; i += LANES*HOT) {
            int oc = i % COUT;
            int ck = i / COUT;
            ws[i] = Wc[oc*CIN*25 + ck];
        }
    }
    __syncthreads();

    int hb = blockIdx.x % HBLK;
    int t0 = (blockIdx.x / HBLK) * TV;
    int n  = blockIdx.y;
    int wg = threadIdx.x % NWG;
    int og = threadIdx.x / NWG;
    int wo = wg * WOT;
    int ho = hb*HOT + threadIdx.y;

    float acc[GO][WOT][TV];
    #pragma unroll
    for (int g = 0; g < GO; g++) {
        float b = bc[og*GO + g];
        #pragma unroll
        for (int ww = 0; ww < WOT; ww++)
            #pragma unroll
            for (int tv = 0; tv < TV; tv++) acc[g][ww][tv] = b;
    }

    const float* inb = in + (size_t)t0*TS_IN + (size_t)n*CIN*HIN*WIN
                          + (size_t)ho*WIN + wo;

    float va[WOT+4][TV], vb[WOT+4][TV];

    auto load_v = [&](int m, float (&v)[WOT+4][TV]) {
        int c = m / 5, kh = m % 5;
        const float* ip = inb + ((size_t)c*HIN + kh)*WIN;
        #pragma unroll
        for (int tv = 0; tv < TV; tv++) {
            const float2* p2 = reinterpret_cast<const float2*>(ip + (size_t)tv*TS_IN);
            #pragma unroll
            for (int j2 = 0; j2 < (WOT+4)/2; j2++) {
                float2 d = p2[j2];
                v[2*j2][tv]   = d.x;
                v[2*j2+1][tv] = d.y;
            }
        }
    };

    auto fma_step = [&](int m, float (&v)[WOT+4][TV]) {
        #pragma unroll
        for (int kw = 0; kw < 5; kw++) {
            float wreg[GO];
            if constexpr (GO == 4) {
                float4 w4 = *reinterpret_cast<const float4*>(&ws[(m*5 + kw)*COUT + og*4]);
                wreg[0] = w4.x; wreg[1] = w4.y; wreg[2] = w4.z; wreg[3] = w4.w;
            } else if constexpr (GO == 2) {
                float2 w2 = *reinterpret_cast<const float2*>(&ws[(m*5 + kw)*COUT + og*2]);
                wreg[0] = w2.x; wreg[1] = w2.y;
            } else {
                #pragma unroll
                for (int g = 0; g < GO; g++) wreg[g] = ws[(m*5 + kw)*COUT + og*GO + g];
            }
            #pragma unroll
            for (int g = 0; g < GO; g++)
                #pragma unroll
                for (int ww = 0; ww < WOT; ww++)
                    #pragma unroll
                    for (int tv = 0; tv < TV; tv++)
                        acc[g][ww][tv] += v[ww+kw][tv] * wreg[g];
        }
    };

    load_v(0, va);
    int m = 0;
    #pragma unroll 1
    for (; m + 2 <= M; m += 2) {
        load_v(m + 1, vb);
        fma_step(m, va);
        if (m + 2 < M) load_v(m + 2, va);
        fma_step(m + 1, vb);
    }
    if (m < M) fma_step(m, va);

    float* zb = z + (size_t)t0*TS_OUT + (size_t)n*COUT*HOUT*WOUT
                  + (size_t)og*GO*HOUT*WOUT + (size_t)ho*WOUT + wo;
    #pragma unroll
    for (int tv = 0; tv < TV; tv++)
        #pragma unroll
        for (int g = 0; g < GO; g++) {
            float* op = zb + (size_t)tv*TS_OUT + (size_t)g*HOUT*WOUT;
            #pragma unroll
            for (int j2 = 0; j2 < WOT/2; j2++) {
                float2 d; d.x = acc[g][2*j2][tv]; d.y = acc[g][2*j2+1][tv];
                reinterpret_cast<float2*>(op)[j2] = d;
            }
        }
}

// ---------------- LIF scan ----------------
template<int SZ>
__global__ void k_scan(const float* __restrict__ z, float* __restrict__ s_out) {
    int idx = blockIdx.x * blockDim.x + threadIdx.x;
    if (idx >= SZ) return;
    float u = 0.f;
    #pragma unroll 4
    for (int t = 0; t < T_; t++) {
        u += z[(size_t)t*SZ + idx];
        float s = (u >= 1.0f) ? 1.0f : 0.0f;
        u -= s;
        s_out[(size_t)t*SZ + idx] = s;
    }
}

// ---------------- fused LIF scan + 2x2 avg-pool + LIF scan ----------------
template<int C,int HIN>
__global__ void k_scanpool(const float* __restrict__ z, float* __restrict__ out) {
    constexpr int HO = HIN/2;
    constexpr size_t TS_IN  = (size_t)N_*C*HIN*HIN;
    constexpr size_t TS_OUT = (size_t)N_*C*HO*HO;
    int idx = blockIdx.x * blockDim.x + threadIdx.x;
    if (idx >= N_*C*HO*HO) return;
    int wo = idx % HO; int t1 = idx / HO;
    int ho = t1 % HO;  int t2 = t1 / HO;
    int c  = t2 % C;   int n  = t2 / C;
    const float* ip = z + ((size_t)n*C + c)*HIN*HIN + (size_t)(2*ho)*HIN + 2*wo;
    float* op = out + ((size_t)n*C + c)*HO*HO + (size_t)ho*HO + wo;
    float u0 = 0.f, u1 = 0.f, u2 = 0.f, u3 = 0.f, up = 0.f;
    #pragma unroll 4
    for (int t = 0; t < T_; t++) {
        const float* p = ip + (size_t)t*TS_IN;
        float2 r0 = *reinterpret_cast<const float2*>(p);
        float2 r1 = *reinterpret_cast<const float2*>(p + HIN);
        u0 += r0.x; float s0 = (u0 >= 1.0f) ? 1.0f : 0.0f; u0 -= s0;
        u1 += r0.y; float s1 = (u1 >= 1.0f) ? 1.0f : 0.0f; u1 -= s1;
        u2 += r1.x; float s2 = (u2 >= 1.0f) ? 1.0f : 0.0f; u2 -= s2;
        u3 += r1.y; float s3 = (u3 >= 1.0f) ? 1.0f : 0.0f; u3 -= s3;
        up += 0.25f*(s0 + s1 + s2 + s3);
        float sp = (up >= 1.0f) ? 1.0f : 0.0f; up -= sp;
        op[(size_t)t*TS_OUT] = sp;
    }
}

// ---------------- fc1 GEMM ----------------
__global__ void k_fc1(const float* __restrict__ bf1) {
    __shared__ float sin_[4][512];
    int t0 = blockIdx.x*4, n = blockIdx.y, o = threadIdx.x;
    for (int i = o; i < 4*512; i += 128) {
        int tv = i >> 9, k = i & 511;
        sin_[tv][k] = g_p2[((size_t)(t0+tv)*N_ + n)*512 + k];
    }
    __syncthreads();
    float b = bf1[o];
    float acc[4] = {b, b, b, b};
    #pragma unroll 4
    for (int k = 0; k < 512; k++) {
        float w = g_wt1[k*128 + o];
        #pragma unroll
        for (int tv = 0; tv < 4; tv++) acc[tv] += sin_[tv][k] * w;
    }
    #pragma unroll
    for (int tv = 0; tv < 4; tv++)
        g_z1[((size_t)(t0+tv)*N_ + n)*128 + o] = acc[tv];
}

// ---------------- head ----------------
__global__ void k_head(const float* __restrict__ Wf2, const float* __restrict__ bf2,
                       float* __restrict__ out) {
    int n = blockIdx.x, o = threadIdx.x;
    __shared__ float s1[128];
    __shared__ float w2[2][128];
    w2[0][o] = Wf2[o];
    w2[1][o] = Wf2[128 + o];
    float u1 = 0.f, u2 = 0.f, ssum = 0.f;
    float b2 = (o < 2) ? bf2[o] : 0.f;
    __syncthreads();
    for (int t = 0; t < T_; t++) {
        float z = g_z1[((size_t)t*N_ + n)*128 + o];
        u1 += z;
        float s = (u1 >= 1.0f) ? 1.0f : 0.0f;
        u1 -= s;
        s1[o] = s;
        __syncthreads();
        if (o < 2) {
            float d = b2;
            #pragma unroll 8
            for (int k = 0; k < 128; k++) d += s1[k] * w2[o][k];
            u2 += d;
            float s2 = (u2 >= 1.0f) ? 1.0f : 0.0f;
            u2 -= s2;
            ssum += s2;
        }
        __syncthreads();
    }
    if (o < 2) out[n*2 + o] = ssum * (1.0f / T_);
}

// ---------------- launch ----------------
extern "C" void kernel_launch(void* const* d_in, const int* in_sizes, int n_in,
                              void* d_out, int out_size) {
    (void)in_sizes; (void)n_in; (void)out_size;
    const float* x   = (const float*)d_in[0];
    const float* Wc1 = (const float*)d_in[1];
    const float* bc1 = (const float*)d_in[2];
    const float* Wc2 = (const float*)d_in[3];
    const float* bc2 = (const float*)d_in[4];
    const float* Wc3 = (const float*)d_in[5];
    const float* bc3 = (const float*)d_in[6];
    const float* Wf1 = (const float*)d_in[7];
    const float* bf1 = (const float*)d_in[8];
    const float* Wf2 = (const float*)d_in[9];
    const float* bf2 = (const float*)d_in[10];
    float* out = (float*)d_out;

    float *p_xt, *p_z1c, *p_h1, *p_z2c, *p_p1, *p_z3c, *p_p2;
    cudaGetSymbolAddress((void**)&p_xt,  g_xt);
    cudaGetSymbolAddress((void**)&p_z1c, g_z1c);
    cudaGetSymbolAddress((void**)&p_h1,  g_h1);
    cudaGetSymbolAddress((void**)&p_z2c, g_z2c);
    cudaGetSymbolAddress((void**)&p_p1,  g_p1);
    cudaGetSymbolAddress((void**)&p_z3c, g_z3c);
    cudaGetSymbolAddress((void**)&p_p2,  g_p2);

    // conv1: scalar, GO=4, WOT=4, HOT=7, TV=2 -> block (28,7)=196 thr
    auto c1 = k_conv<1,16,32,32,4,4,7,2,2>;

    constexpr int SMEM_C2 = C2_TB*784*C2_PAD*2 + 2*25*32*C2_PAD*2;    // 75264 + 76800
    constexpr int SMEM_C3 = 2*25*32*C3_PAD*2 + C3_TB*144*C3_PAD*2;    // 128000 + 46080
    cudaFuncSetAttribute(k_conv2_mma, cudaFuncAttributeMaxDynamicSharedMemorySize, SMEM_C2);
    cudaFuncSetAttribute(k_conv3_mma, cudaFuncAttributeMaxDynamicSharedMemorySize, SMEM_C3);

    k_transpose_x<<<(N_*1024 + 255)/256, 256>>>(x);
    k_transpose_wf1<<<(128*512 + 255)/256, 256>>>(Wf1);
    k_split_w2<<<(12800 + 255)/256, 256>>>(Wc2);
    k_split_w3<<<(25600 + 255)/256, 256>>>(Wc3);

    constexpr int SZ1 = N_*16*28*28;

    c1<<<dim3(4*(T_/2), N_), dim3(28, 7), 16*1*25*4>>>(p_xt, Wc1, bc1, p_z1c);
    k_scan<SZ1><<<(SZ1 + 255)/256, 256>>>(p_z1c, p_h1);

    k_conv2_mma<<<dim3(T_/C2_TB, N_), 384, SMEM_C2>>>(p_h1, bc2, p_z2c);
    k_scanpool<32,24><<<(N_*32*12*12 + 255)/256, 256>>>(p_z2c, p_p1);

    k_conv3_mma<<<dim3(T_/C3_TB, N_), 256, SMEM_C3>>>(p_p1, bc3, p_z3c);
    k_scanpool<32,8><<<(N_*32*4*4 + 255)/256, 256>>>(p_z3c, p_p2);

    k_fc1<<<dim3(T_/4, N_), 128>>>(bf1);
    k_head<<<N_, 128>>>(Wf2, bf2, out);
}

// round 12
// speedup vs baseline: 2.4498x; 1.0663x over previous
#include <cuda_runtime.h>
#include <cuda_bf16.h>
#include <cuda_fp16.h>

#define N_ 32
#define T_ 48

// ---------------- scratch (t-major: [T][N][C][H][W]) ----------------
__device__ float g_xt[(size_t)T_*N_*32*32];
__device__ float g_z1c[(size_t)T_*N_*16*28*28];
__device__ float g_h1[(size_t)T_*N_*16*28*28];
__device__ float g_z2c[(size_t)T_*N_*32*24*24];
__device__ float g_p1[(size_t)T_*N_*32*12*12];
__device__ float g_z3c[(size_t)T_*N_*32*8*8];
__device__ float g_p2[(size_t)T_*N_*32*4*4];
__device__ float g_wt1[512*128];
__device__ float g_z1[(size_t)T_*N_*128];
__device__ __half g_w2s[2*25*32*16];   // conv2 w split [s][j][o][c16], fp16 2-way
__device__ __half g_w3s[2*25*32*32];   // conv3 w split [s][j][o][c32], fp16 2-way

// ---------------- transpose x ----------------
__global__ void k_transpose_x(const float* __restrict__ x) {
    int idx = blockIdx.x * blockDim.x + threadIdx.x;
    if (idx >= N_*32*32) return;
    int n = idx >> 10, hw = idx & 1023;
    const float* xp = x + (size_t)idx * T_;
    #pragma unroll
    for (int t = 0; t < T_; t++)
        g_xt[((size_t)t*N_ + n)*1024 + hw] = xp[t];
}

// ---------------- transpose Wf1 ----------------
__global__ void k_transpose_wf1(const float* __restrict__ Wf1) {
    int idx = blockIdx.x * blockDim.x + threadIdx.x;
    if (idx >= 128*512) return;
    int o = idx >> 9, k = idx & 511;
    g_wt1[k*128 + o] = Wf1[idx];
}

// ---------------- weight splits: fp32 -> 2x fp16 ----------------
__global__ void k_split_w2(const float* __restrict__ Wc2) {
    int i = blockIdx.x*256 + threadIdx.x;   // 12800
    if (i >= 12800) return;
    int c = i % 16, o = (i/16) % 32, j = i/512;
    int kh = j/5, kw = j%5;
    float w = Wc2[((o*16 + c)*5 + kh)*5 + kw];
    __half h = __float2half_rn(w);
    float r = w - __half2float(h);
    g_w2s[0*12800 + i] = h;
    g_w2s[1*12800 + i] = __float2half_rn(r);
}

__global__ void k_split_w3(const float* __restrict__ Wc3) {
    int i = blockIdx.x*256 + threadIdx.x;   // 25600
    if (i >= 25600) return;
    int c = i % 32, o = (i/32) % 32, j = i/1024;
    int kh = j/5, kw = j%5;
    float w = Wc3[((o*32 + c)*5 + kh)*5 + kw];
    __half h = __float2half_rn(w);
    float r = w - __half2float(h);
    g_w3s[0*25600 + i] = h;
    g_w3s[1*25600 + i] = __float2half_rn(r);
}

// ---------------- mma / ldmatrix helpers ----------------
__device__ __forceinline__ void mma16816(float* c, const unsigned* a,
                                         unsigned b0, unsigned b1) {
    asm volatile(
        "mma.sync.aligned.m16n8k16.row.col.f32.f16.f16.f32 "
        "{%0,%1,%2,%3}, {%4,%5,%6,%7}, {%8,%9}, {%0,%1,%2,%3};"
        : "+f"(c[0]), "+f"(c[1]), "+f"(c[2]), "+f"(c[3])
        : "r"(a[0]), "r"(a[1]), "r"(a[2]), "r"(a[3]), "r"(b0), "r"(b1));
}
__device__ __forceinline__ void ldsm_x4(unsigned* d, unsigned a) {
    asm volatile("ldmatrix.sync.aligned.m8n8.x4.shared.b16 {%0,%1,%2,%3}, [%4];"
                 : "=r"(d[0]), "=r"(d[1]), "=r"(d[2]), "=r"(d[3]) : "r"(a));
}
__device__ __forceinline__ void ldsm_x2(unsigned& d0, unsigned& d1, unsigned a) {
    asm volatile("ldmatrix.sync.aligned.m8n8.x2.shared.b16 {%0,%1}, [%2];"
                 : "=r"(d0), "=r"(d1) : "r"(a));
}

// ---------------- conv2 via tensor cores + ldmatrix, 2 timesteps/block ----------------
// Row stride 24 halfs = 48 B: 16B-aligned, 48%128!=0 -> conflict-free LDSM.
// j-loop covers BOTH timesteps: A frags loaded once; per-acc MMA reuse distance 12.
#define C2_PAD 24
#define C2_TB  2
__global__ void __launch_bounds__(384, 1)
k_conv2_mma(const float* __restrict__ h1s,
            const float* __restrict__ bc2,
            float* __restrict__ z2c) {
    extern __shared__ char sm[];
    __half* sIn = reinterpret_cast<__half*>(sm);                         // [C2_TB][784][C2_PAD]
    __half* sW  = reinterpret_cast<__half*>(sm + C2_TB*784*C2_PAD*2);    // [2][25][32][C2_PAD]

    int t0 = blockIdx.x * C2_TB, n = blockIdx.y;
    int tid = threadIdx.x;

    {   // stage weights
        const unsigned* src = reinterpret_cast<const unsigned*>(g_w2s);
        unsigned* dst = reinterpret_cast<unsigned*>(sW);
        for (int i = tid; i < 2*25*32*16/2; i += 384) {
            int e = i*2; int row = e >> 4; int c = e & 15;
            dst[(row*C2_PAD + c) >> 1] = src[i];
        }
    }
    for (int tt = 0; tt < C2_TB; tt++) {
        const float* ib = h1s + ((size_t)(t0+tt)*N_ + n)*16*784;
        __half* sI = sIn + tt*784*C2_PAD;
        for (int i = tid; i < 16*784; i += 384) {
            int c = i / 784, hw = i % 784;
            sI[hw*C2_PAD + c] = __float2half_rn(ib[i]);
        }
    }
    __syncthreads();

    int w    = tid >> 5;
    int lane = tid & 31;
    int qid  = lane >> 2;
    int rid  = lane & 3;
    int mi   = lane >> 3;
    int rr   = lane & 7;
    int matB = mi & 1;

    unsigned sInA = (unsigned)__cvta_generic_to_shared(sIn);
    unsigned sWA  = (unsigned)__cvta_generic_to_shared(sW);

    unsigned aaddr[2][2];
    #pragma unroll
    for (int s = 0; s < 2; s++)
        #pragma unroll
        for (int mt = 0; mt < 2; mt++) {
            int row = mt*16 + (mi & 1)*8 + rr;
            aaddr[s][mt] = sWA + (((s*25)*32 + row)*C2_PAD + (mi >> 1)*8)*2;
        }

    unsigned baddr[6];
    #pragma unroll
    for (int nt = 0; nt < 6; nt++) {
        int sp = w*48 + nt*8 + rr;
        int ho = sp / 24, wo = sp % 24;
        baddr[nt] = sInA + ((ho*28 + wo)*C2_PAD + matB*8)*2;
    }
    constexpr unsigned TTOFF = 784*C2_PAD*2;

    float acc[C2_TB][2][6][4];
    #pragma unroll
    for (int tt = 0; tt < C2_TB; tt++)
        #pragma unroll
        for (int mt = 0; mt < 2; mt++)
            #pragma unroll
            for (int nt = 0; nt < 6; nt++)
                #pragma unroll
                for (int r = 0; r < 4; r++) acc[tt][mt][nt][r] = 0.f;

    #pragma unroll 1
    for (int j = 0; j < 25; j++) {
        int kh = j / 5, kw = j % 5;
        unsigned aoff = (unsigned)(j*32*C2_PAD*2);
        unsigned boff = (unsigned)((kh*28 + kw)*C2_PAD*2);

        unsigned aF[2][2][4];
        #pragma unroll
        for (int s = 0; s < 2; s++)
            #pragma unroll
            for (int mt = 0; mt < 2; mt++)
                ldsm_x4(aF[s][mt], aaddr[s][mt] + aoff);

        #pragma unroll
        for (int tt = 0; tt < C2_TB; tt++) {
            unsigned bF[6][2];
            #pragma unroll
            for (int nt = 0; nt < 6; nt++)
                ldsm_x2(bF[nt][0], bF[nt][1], baddr[nt] + boff + tt*TTOFF);
            // same-acc reuse distance = 12 MMAs (one s sweep)
            #pragma unroll
            for (int s = 0; s < 2; s++)
                #pragma unroll
                for (int nt = 0; nt < 6; nt++)
                    #pragma unroll
                    for (int mt = 0; mt < 2; mt++)
                        mma16816(acc[tt][mt][nt], aF[s][mt], bF[nt][0], bF[nt][1]);
        }
    }

    #pragma unroll
    for (int tt = 0; tt < C2_TB; tt++) {
        float* zb = z2c + ((size_t)(t0+tt)*N_ + n)*32*576;
        #pragma unroll
        for (int mt = 0; mt < 2; mt++) {
            int o0 = mt*16 + qid;
            float b0 = bc2[o0], b1 = bc2[o0 + 8];
            #pragma unroll
            for (int nt = 0; nt < 6; nt++) {
                int sp = w*48 + nt*8 + rid*2;
                float2 d0; d0.x = acc[tt][mt][nt][0] + b0; d0.y = acc[tt][mt][nt][1] + b0;
                float2 d1; d1.x = acc[tt][mt][nt][2] + b1; d1.y = acc[tt][mt][nt][3] + b1;
                *reinterpret_cast<float2*>(zb + (size_t)o0*576 + sp)     = d0;
                *reinterpret_cast<float2*>(zb + (size_t)(o0+8)*576 + sp) = d1;
            }
        }
    }
}

// ---------------- conv3 via tensor cores + ldmatrix, 4 timesteps/block ----------------
// Row stride 40 halfs = 80 B: 16B-aligned, 80%128!=0 -> conflict-free LDSM.
// Two timesteps in flight per inner loop: per-acc MMA reuse distance 4.
#define C3_PAD 40
#define C3_TB  4
__global__ void __launch_bounds__(256, 1)
k_conv3_mma(const float* __restrict__ p1s,
            const float* __restrict__ bc3,
            float* __restrict__ z3c) {
    extern __shared__ char sm[];
    __half* sW  = reinterpret_cast<__half*>(sm);                          // [2][25][32][C3_PAD]
    __half* sIn = reinterpret_cast<__half*>(sm + 2*25*32*C3_PAD*2);       // [C3_TB][144][C3_PAD]

    int t0 = blockIdx.x * C3_TB, n = blockIdx.y;
    int tid = threadIdx.x;

    {
        const unsigned* src = reinterpret_cast<const unsigned*>(g_w3s);
        unsigned* dst = reinterpret_cast<unsigned*>(sW);
        for (int i = tid; i < 2*25*32*32/2; i += 256) {
            int e = i*2; int row = e >> 5; int c = e & 31;
            dst[(row*C3_PAD + c) >> 1] = src[i];
        }
    }
    for (int tt = 0; tt < C3_TB; tt++) {
        const float* ib = p1s + ((size_t)(t0+tt)*N_ + n)*32*144;
        __half* sI = sIn + tt*144*C3_PAD;
        for (int i = tid; i < 32*144; i += 256) {
            int c = i / 144, hw = i % 144;
            sI[hw*C3_PAD + c] = __float2half_rn(ib[i]);
        }
    }
    __syncthreads();

    int w    = tid >> 5;
    int lane = tid & 31;
    int qid  = lane >> 2;
    int rid  = lane & 3;
    int mi   = lane >> 3;
    int rr   = lane & 7;
    int matB = mi & 1;
    int mt   = w >> 2;
    int ntp  = w & 3;

    unsigned sInA = (unsigned)__cvta_generic_to_shared(sIn);
    unsigned sWA  = (unsigned)__cvta_generic_to_shared(sW);

    unsigned aaddr[2];
    #pragma unroll
    for (int s = 0; s < 2; s++) {
        int row = mt*16 + (mi & 1)*8 + rr;
        aaddr[s] = sWA + (((s*25)*32 + row)*C3_PAD + (mi >> 1)*8)*2;
    }
    unsigned baddr[2];
    #pragma unroll
    for (int q = 0; q < 2; q++) {
        int ntr = ntp*2 + q;
        baddr[q] = sInA + ((ntr*12 + rr)*C3_PAD + matB*8)*2;
    }
    constexpr unsigned TTOFF3 = 144*C3_PAD*2;

    int o0 = mt*16 + qid;
    float bb0 = bc3[o0], bb1 = bc3[o0 + 8];

    #pragma unroll 1
    for (int tp = 0; tp < C3_TB/2; tp++) {
        int ttA = tp*2, ttB = tp*2 + 1;
        float acc[2][2][4];     // [ttpair][q][4]
        #pragma unroll
        for (int u = 0; u < 2; u++)
            #pragma unroll
            for (int q = 0; q < 2; q++)
                #pragma unroll
                for (int r = 0; r < 4; r++) acc[u][q][r] = 0.f;

        unsigned toffA = ttA*TTOFF3, toffB = ttB*TTOFF3;

        #pragma unroll 1
        for (int j = 0; j < 25; j++) {
            int kh = j / 5, kw = j % 5;
            unsigned aF[2][2][4];   // [s][kc][4]
            #pragma unroll
            for (int s = 0; s < 2; s++)
                #pragma unroll
                for (int kc = 0; kc < 2; kc++)
                    ldsm_x4(aF[s][kc], aaddr[s] + (unsigned)((j*32*C3_PAD + kc*16)*2));

            unsigned bF[2][2][2][2];  // [ttpair][kc][q][2]
            #pragma unroll
            for (int kc = 0; kc < 2; kc++) {
                unsigned bo = (unsigned)(((kh*12 + kw)*C3_PAD + kc*16)*2);
                #pragma unroll
                for (int q = 0; q < 2; q++) {
                    ldsm_x2(bF[0][kc][q][0], bF[0][kc][q][1], baddr[q] + bo + toffA);
                    ldsm_x2(bF[1][kc][q][0], bF[1][kc][q][1], baddr[q] + bo + toffB);
                }
            }
            // 16 MMAs; same-acc reuse distance 4
            #pragma unroll
            for (int s = 0; s < 2; s++)
                #pragma unroll
                for (int kc = 0; kc < 2; kc++)
                    #pragma unroll
                    for (int u = 0; u < 2; u++)
                        #pragma unroll
                        for (int q = 0; q < 2; q++)
                            mma16816(acc[u][q], aF[s][kc], bF[u][kc][q][0], bF[u][kc][q][1]);
        }

        #pragma unroll
        for (int u = 0; u < 2; u++) {
            float* zb = z3c + ((size_t)(t0 + tp*2 + u)*N_ + n)*32*64;
            #pragma unroll
            for (int q = 0; q < 2; q++) {
                int sp = (ntp*2 + q)*8 + rid*2;
                float2 d0; d0.x = acc[u][q][0] + bb0; d0.y = acc[u][q][1] + bb0;
                float2 d1; d1.x = acc[u][q][2] + bb1; d1.y = acc[u][q][3] + bb1;
                *reinterpret_cast<float2*>(zb + (size_t)o0*64 + sp)     = d0;
                *reinterpret_cast<float2*>(zb + (size_t)(o0+8)*64 + sp) = d1;
            }
        }
    }
}

// ---------------- 5x5 VALID conv, scalar pipelined (conv1 only) ----------------
template<int CIN,int COUT,int HIN,int WIN,int GO,int WOT,int HOT,int TV,int MINB>
__global__ void
__launch_bounds__(((WIN-4)/WOT)*(COUT/GO)*HOT, MINB)
k_conv(const float* __restrict__ in,
       const float* __restrict__ Wc,
       const float* __restrict__ bc,
       float* __restrict__ z) {
    constexpr int HOUT = HIN-4, WOUT = WIN-4;
    constexpr int NWG  = WOUT/WOT;
    constexpr int NOG  = COUT/GO;
    constexpr int LANES = NWG*NOG;
    constexpr int HBLK = HOUT/HOT;
    constexpr int M    = CIN*5;
    constexpr size_t TS_IN  = (size_t)N_*CIN*HIN*WIN;
    constexpr size_t TS_OUT = (size_t)N_*COUT*HOUT*WOUT;
    extern __shared__ float ws[];
    {
        int tid = threadIdx.y*LANES + threadIdx.x;
        for (int i = tid; i < COUT*CIN*25; i += LANES*HOT) {
            int oc = i % COUT;
            int ck = i / COUT;
            ws[i] = Wc[oc*CIN*25 + ck];
        }
    }
    __syncthreads();

    int hb = blockIdx.x % HBLK;
    int t0 = (blockIdx.x / HBLK) * TV;
    int n  = blockIdx.y;
    int wg = threadIdx.x % NWG;
    int og = threadIdx.x / NWG;
    int wo = wg * WOT;
    int ho = hb*HOT + threadIdx.y;

    float acc[GO][WOT][TV];
    #pragma unroll
    for (int g = 0; g < GO; g++) {
        float b = bc[og*GO + g];
        #pragma unroll
        for (int ww = 0; ww < WOT; ww++)
            #pragma unroll
            for (int tv = 0; tv < TV; tv++) acc[g][ww][tv] = b;
    }

    const float* inb = in + (size_t)t0*TS_IN + (size_t)n*CIN*HIN*WIN
                          + (size_t)ho*WIN + wo;

    float va[WOT+4][TV], vb[WOT+4][TV];

    auto load_v = [&](int m, float (&v)[WOT+4][TV]) {
        int c = m / 5, kh = m % 5;
        const float* ip = inb + ((size_t)c*HIN + kh)*WIN;
        #pragma unroll
        for (int tv = 0; tv < TV; tv++) {
            const float2* p2 = reinterpret_cast<const float2*>(ip + (size_t)tv*TS_IN);
            #pragma unroll
            for (int j2 = 0; j2 < (WOT+4)/2; j2++) {
                float2 d = p2[j2];
                v[2*j2][tv]   = d.x;
                v[2*j2+1][tv] = d.y;
            }
        }
    };

    auto fma_step = [&](int m, float (&v)[WOT+4][TV]) {
        #pragma unroll
        for (int kw = 0; kw < 5; kw++) {
            float wreg[GO];
            if constexpr (GO == 4) {
                float4 w4 = *reinterpret_cast<const float4*>(&ws[(m*5 + kw)*COUT + og*4]);
                wreg[0] = w4.x; wreg[1] = w4.y; wreg[2] = w4.z; wreg[3] = w4.w;
            } else if constexpr (GO == 2) {
                float2 w2 = *reinterpret_cast<const float2*>(&ws[(m*5 + kw)*COUT + og*2]);
                wreg[0] = w2.x; wreg[1] = w2.y;
            } else {
                #pragma unroll
                for (int g = 0; g < GO; g++) wreg[g] = ws[(m*5 + kw)*COUT + og*GO + g];
            }
            #pragma unroll
            for (int g = 0; g < GO; g++)
                #pragma unroll
                for (int ww = 0; ww < WOT; ww++)
                    #pragma unroll
                    for (int tv = 0; tv < TV; tv++)
                        acc[g][ww][tv] += v[ww+kw][tv] * wreg[g];
        }
    };

    load_v(0, va);
    int m = 0;
    #pragma unroll 1
    for (; m + 2 <= M; m += 2) {
        load_v(m + 1, vb);
        fma_step(m, va);
        if (m + 2 < M) load_v(m + 2, va);
        fma_step(m + 1, vb);
    }
    if (m < M) fma_step(m, va);

    float* zb = z + (size_t)t0*TS_OUT + (size_t)n*COUT*HOUT*WOUT
                  + (size_t)og*GO*HOUT*WOUT + (size_t)ho*WOUT + wo;
    #pragma unroll
    for (int tv = 0; tv < TV; tv++)
        #pragma unroll
        for (int g = 0; g < GO; g++) {
            float* op = zb + (size_t)tv*TS_OUT + (size_t)g*HOUT*WOUT;
            #pragma unroll
            for (int j2 = 0; j2 < WOT/2; j2++) {
                float2 d; d.x = acc[g][2*j2][tv]; d.y = acc[g][2*j2+1][tv];
                reinterpret_cast<float2*>(op)[j2] = d;
            }
        }
}

// ---------------- LIF scan ----------------
template<int SZ>
__global__ void k_scan(const float* __restrict__ z, float* __restrict__ s_out) {
    int idx = blockIdx.x * blockDim.x + threadIdx.x;
    if (idx >= SZ) return;
    float u = 0.f;
    #pragma unroll 4
    for (int t = 0; t < T_; t++) {
        u += z[(size_t)t*SZ + idx];
        float s = (u >= 1.0f) ? 1.0f : 0.0f;
        u -= s;
        s_out[(size_t)t*SZ + idx] = s;
    }
}

// ---------------- fused LIF scan + 2x2 avg-pool + LIF scan ----------------
template<int C,int HIN>
__global__ void k_scanpool(const float* __restrict__ z, float* __restrict__ out) {
    constexpr int HO = HIN/2;
    constexpr size_t TS_IN  = (size_t)N_*C*HIN*HIN;
    constexpr size_t TS_OUT = (size_t)N_*C*HO*HO;
    int idx = blockIdx.x * blockDim.x + threadIdx.x;
    if (idx >= N_*C*HO*HO) return;
    int wo = idx % HO; int t1 = idx / HO;
    int ho = t1 % HO;  int t2 = t1 / HO;
    int c  = t2 % C;   int n  = t2 / C;
    const float* ip = z + ((size_t)n*C + c)*HIN*HIN + (size_t)(2*ho)*HIN + 2*wo;
    float* op = out + ((size_t)n*C + c)*HO*HO + (size_t)ho*HO + wo;
    float u0 = 0.f, u1 = 0.f, u2 = 0.f, u3 = 0.f, up = 0.f;
    #pragma unroll 4
    for (int t = 0; t < T_; t++) {
        const float* p = ip + (size_t)t*TS_IN;
        float2 r0 = *reinterpret_cast<const float2*>(p);
        float2 r1 = *reinterpret_cast<const float2*>(p + HIN);
        u0 += r0.x; float s0 = (u0 >= 1.0f) ? 1.0f : 0.0f; u0 -= s0;
        u1 += r0.y; float s1 = (u1 >= 1.0f) ? 1.0f : 0.0f; u1 -= s1;
        u2 += r1.x; float s2 = (u2 >= 1.0f) ? 1.0f : 0.0f; u2 -= s2;
        u3 += r1.y; float s3 = (u3 >= 1.0f) ? 1.0f : 0.0f; u3 -= s3;
        up += 0.25f*(s0 + s1 + s2 + s3);
        float sp = (up >= 1.0f) ? 1.0f : 0.0f; up -= sp;
        op[(size_t)t*TS_OUT] = sp;
    }
}

// ---------------- fc1 GEMM ----------------
__global__ void k_fc1(const float* __restrict__ bf1) {
    __shared__ float sin_[4][512];
    int t0 = blockIdx.x*4, n = blockIdx.y, o = threadIdx.x;
    for (int i = o; i < 4*512; i += 128) {
        int tv = i >> 9, k = i & 511;
        sin_[tv][k] = g_p2[((size_t)(t0+tv)*N_ + n)*512 + k];
    }
    __syncthreads();
    float b = bf1[o];
    float acc[4] = {b, b, b, b};
    #pragma unroll 4
    for (int k = 0; k < 512; k++) {
        float w = g_wt1[k*128 + o];
        #pragma unroll
        for (int tv = 0; tv < 4; tv++) acc[tv] += sin_[tv][k] * w;
    }
    #pragma unroll
    for (int tv = 0; tv < 4; tv++)
        g_z1[((size_t)(t0+tv)*N_ + n)*128 + o] = acc[tv];
}

// ---------------- head: warp-parallel fc2 ----------------
__global__ void k_head(const float* __restrict__ Wf2, const float* __restrict__ bf2,
                       float* __restrict__ out) {
    int n = blockIdx.x, o = threadIdx.x;
    int wid = o >> 5, lane = o & 31;
    __shared__ float s1[128];
    float wr[4] = {0.f, 0.f, 0.f, 0.f};
    float b2 = 0.f;
    if (wid < 2) {
        #pragma unroll
        for (int k = 0; k < 4; k++) wr[k] = Wf2[wid*128 + lane + 32*k];
        b2 = bf2[wid];
    }
    float u1 = 0.f, u2 = 0.f, ssum = 0.f;
    for (int t = 0; t < T_; t++) {
        float z = g_z1[((size_t)t*N_ + n)*128 + o];
        u1 += z;
        float s = (u1 >= 1.0f) ? 1.0f : 0.0f;
        u1 -= s;
        s1[o] = s;
        __syncthreads();
        if (wid < 2) {
            float d = s1[lane]*wr[0] + s1[lane+32]*wr[1]
                    + s1[lane+64]*wr[2] + s1[lane+96]*wr[3];
            #pragma unroll
            for (int off = 16; off > 0; off >>= 1)
                d += __shfl_xor_sync(0xFFFFFFFFu, d, off);
            u2 += d + b2;
            float s2 = (u2 >= 1.0f) ? 1.0f : 0.0f;
            u2 -= s2;
            ssum += s2;
        }
        __syncthreads();
    }
    if (wid < 2 && lane == 0) out[n*2 + wid] = ssum * (1.0f / T_);
}

// ---------------- launch ----------------
extern "C" void kernel_launch(void* const* d_in, const int* in_sizes, int n_in,
                              void* d_out, int out_size) {
    (void)in_sizes; (void)n_in; (void)out_size;
    const float* x   = (const float*)d_in[0];
    const float* Wc1 = (const float*)d_in[1];
    const float* bc1 = (const float*)d_in[2];
    const float* Wc2 = (const float*)d_in[3];
    const float* bc2 = (const float*)d_in[4];
    const float* Wc3 = (const float*)d_in[5];
    const float* bc3 = (const float*)d_in[6];
    const float* Wf1 = (const float*)d_in[7];
    const float* bf1 = (const float*)d_in[8];
    const float* Wf2 = (const float*)d_in[9];
    const float* bf2 = (const float*)d_in[10];
    float* out = (float*)d_out;

    float *p_xt, *p_z1c, *p_h1, *p_z2c, *p_p1, *p_z3c, *p_p2;
    cudaGetSymbolAddress((void**)&p_xt,  g_xt);
    cudaGetSymbolAddress((void**)&p_z1c, g_z1c);
    cudaGetSymbolAddress((void**)&p_h1,  g_h1);
    cudaGetSymbolAddress((void**)&p_z2c, g_z2c);
    cudaGetSymbolAddress((void**)&p_p1,  g_p1);
    cudaGetSymbolAddress((void**)&p_z3c, g_z3c);
    cudaGetSymbolAddress((void**)&p_p2,  g_p2);

    auto c1 = k_conv<1,16,32,32,4,4,7,2,2>;

    constexpr int SMEM_C2 = C2_TB*784*C2_PAD*2 + 2*25*32*C2_PAD*2;
    constexpr int SMEM_C3 = 2*25*32*C3_PAD*2 + C3_TB*144*C3_PAD*2;
    cudaFuncSetAttribute(k_conv2_mma, cudaFuncAttributeMaxDynamicSharedMemorySize, SMEM_C2);
    cudaFuncSetAttribute(k_conv3_mma, cudaFuncAttributeMaxDynamicSharedMemorySize, SMEM_C3);

    k_transpose_x<<<(N_*1024 + 255)/256, 256>>>(x);
    k_transpose_wf1<<<(128*512 + 255)/256, 256>>>(Wf1);
    k_split_w2<<<(12800 + 255)/256, 256>>>(Wc2);
    k_split_w3<<<(25600 + 255)/256, 256>>>(Wc3);

    constexpr int SZ1 = N_*16*28*28;

    c1<<<dim3(4*(T_/2), N_), dim3(28, 7), 16*1*25*4>>>(p_xt, Wc1, bc1, p_z1c);
    k_scan<SZ1><<<(SZ1 + 255)/256, 256>>>(p_z1c, p_h1);

    k_conv2_mma<<<dim3(T_/C2_TB, N_), 384, SMEM_C2>>>(p_h1, bc2, p_z2c);
    k_scanpool<32,24><<<(N_*32*12*12 + 255)/256, 256>>>(p_z2c, p_p1);

    k_conv3_mma<<<dim3(T_/C3_TB, N_), 256, SMEM_C3>>>(p_p1, bc3, p_z3c);
    k_scanpool<32,8><<<(N_*32*4*4 + 255)/256, 256>>>(p_z3c, p_p2);

    k_fc1<<<dim3(T_/4, N_), 128>>>(bf1);
    k_head<<<N_, 128>>>(Wf2, bf2, out);
}

// round 13
// speedup vs baseline: 2.5182x; 1.0279x over previous
#include <cuda_runtime.h>
#include <cuda_bf16.h>
#include <cuda_fp16.h>

#define N_ 32
#define T_ 48
#define NSM 148

// ---------------- scratch (t-major: [T][N][C][H][W]) ----------------
__device__ float g_xt[(size_t)T_*N_*32*32];
__device__ float g_z1c[(size_t)T_*N_*16*28*28];
__device__ float g_h1[(size_t)T_*N_*16*28*28];
__device__ float g_z2c[(size_t)T_*N_*32*24*24];
__device__ float g_p1[(size_t)T_*N_*32*12*12];
__device__ float g_z3c[(size_t)T_*N_*32*8*8];
__device__ float g_p2[(size_t)T_*N_*32*4*4];
__device__ float g_wt1[512*128];
__device__ float g_z1[(size_t)T_*N_*128];
__device__ __half g_w2s[2*25*32*16];   // conv2 w split [s][j][o][c16], fp16 2-way
__device__ __half g_w3s[2*25*32*32];   // conv3 w split [s][j][o][c32], fp16 2-way

// ---------------- fused prep: transpose x, transpose Wf1, split w2/w3 ----------------
#define PW0 (N_*32*32)          // 32768  transpose_x elements
#define PW1 (128*512)           // 65536  wf1 transpose
#define PW2 (25*32*16)          // 12800  split w2
#define PW3 (25*32*32)          // 25600  split w3
#define PWT (PW0+PW1+PW2+PW3)   // 136704
__global__ void k_prep(const float* __restrict__ x,  const float* __restrict__ Wf1,
                       const float* __restrict__ Wc2, const float* __restrict__ Wc3) {
    int gid = blockIdx.x*256 + threadIdx.x;
    if (gid < PW0) {
        int n = gid >> 10, hw = gid & 1023;
        const float* xp = x + (size_t)gid * T_;
        #pragma unroll
        for (int t = 0; t < T_; t++)
            g_xt[((size_t)t*N_ + n)*1024 + hw] = xp[t];
    } else if (gid < PW0+PW1) {
        int i = gid - PW0;
        int o = i >> 9, k = i & 511;
        g_wt1[k*128 + o] = Wf1[i];
    } else if (gid < PW0+PW1+PW2) {
        int i = gid - (PW0+PW1);
        int c = i % 16, o = (i/16) % 32, j = i/512;
        int kh = j/5, kw = j%5;
        float w = Wc2[((o*16 + c)*5 + kh)*5 + kw];
        __half h = __float2half_rn(w);
        float r = w - __half2float(h);
        g_w2s[0*12800 + i] = h;
        g_w2s[1*12800 + i] = __float2half_rn(r);
    } else if (gid < PWT) {
        int i = gid - (PW0+PW1+PW2);
        int c = i % 32, o = (i/32) % 32, j = i/1024;
        int kh = j/5, kw = j%5;
        float w = Wc3[((o*32 + c)*5 + kh)*5 + kw];
        __half h = __float2half_rn(w);
        float r = w - __half2float(h);
        g_w3s[0*25600 + i] = h;
        g_w3s[1*25600 + i] = __float2half_rn(r);
    }
}

// ---------------- mma / ldmatrix helpers ----------------
__device__ __forceinline__ void mma16816(float* c, const unsigned* a,
                                         unsigned b0, unsigned b1) {
    asm volatile(
        "mma.sync.aligned.m16n8k16.row.col.f32.f16.f16.f32 "
        "{%0,%1,%2,%3}, {%4,%5,%6,%7}, {%8,%9}, {%0,%1,%2,%3};"
        : "+f"(c[0]), "+f"(c[1]), "+f"(c[2]), "+f"(c[3])
        : "r"(a[0]), "r"(a[1]), "r"(a[2]), "r"(a[3]), "r"(b0), "r"(b1));
}
__device__ __forceinline__ void ldsm_x4(unsigned* d, unsigned a) {
    asm volatile("ldmatrix.sync.aligned.m8n8.x4.shared.b16 {%0,%1,%2,%3}, [%4];"
                 : "=r"(d[0]), "=r"(d[1]), "=r"(d[2]), "=r"(d[3]) : "r"(a));
}
__device__ __forceinline__ void ldsm_x2(unsigned& d0, unsigned& d1, unsigned a) {
    asm volatile("ldmatrix.sync.aligned.m8n8.x2.shared.b16 {%0,%1}, [%2];"
                 : "=r"(d0), "=r"(d1) : "r"(a));
}

// ---------------- conv2, tensor cores, PERSISTENT blocks ----------------
// Weights staged ONCE per block; grid-stride loop over (t-pair, n) tiles.
// Row stride 24 halfs = 48 B: 16B-aligned, conflict-free LDSM.
#define C2_PAD 24
#define C2_TB  2
#define C2_TILES ((T_/C2_TB)*N_)   // 768
__global__ void __launch_bounds__(384, 1)
k_conv2_mma(const float* __restrict__ h1s,
            const float* __restrict__ bc2,
            float* __restrict__ z2c) {
    extern __shared__ char sm[];
    __half* sIn = reinterpret_cast<__half*>(sm);                         // [C2_TB][784][C2_PAD]
    __half* sW  = reinterpret_cast<__half*>(sm + C2_TB*784*C2_PAD*2);    // [2][25][32][C2_PAD]

    int tid = threadIdx.x;

    {   // stage weights ONCE
        const unsigned* src = reinterpret_cast<const unsigned*>(g_w2s);
        unsigned* dst = reinterpret_cast<unsigned*>(sW);
        for (int i = tid; i < 2*25*32*16/2; i += 384) {
            int e = i*2; int row = e >> 4; int c = e & 15;
            dst[(row*C2_PAD + c) >> 1] = src[i];
        }
    }

    int w    = tid >> 5;
    int lane = tid & 31;
    int qid  = lane >> 2;
    int rid  = lane & 3;
    int mi   = lane >> 3;
    int rr   = lane & 7;
    int matB = mi & 1;

    unsigned sInA = (unsigned)__cvta_generic_to_shared(sIn);
    unsigned sWA  = (unsigned)__cvta_generic_to_shared(sW);

    unsigned aaddr[2][2];
    #pragma unroll
    for (int s = 0; s < 2; s++)
        #pragma unroll
        for (int mt = 0; mt < 2; mt++) {
            int row = mt*16 + (mi & 1)*8 + rr;
            aaddr[s][mt] = sWA + (((s*25)*32 + row)*C2_PAD + (mi >> 1)*8)*2;
        }
    unsigned baddr[6];
    #pragma unroll
    for (int nt = 0; nt < 6; nt++) {
        int sp = w*48 + nt*8 + rr;
        int ho = sp / 24, wo = sp % 24;
        baddr[nt] = sInA + ((ho*28 + wo)*C2_PAD + matB*8)*2;
    }
    constexpr unsigned TTOFF = 784*C2_PAD*2;

    #pragma unroll 1
    for (int tile = blockIdx.x; tile < C2_TILES; tile += gridDim.x) {
        int n  = tile & (N_-1);
        int t0 = (tile >> 5) * C2_TB;

        __syncthreads();   // prior tile's MMAs done before overwriting sIn (also covers weight staging, iter 0)
        for (int tt = 0; tt < C2_TB; tt++) {
            const float* ib = h1s + ((size_t)(t0+tt)*N_ + n)*16*784;
            __half* sI = sIn + tt*784*C2_PAD;
            for (int i = tid; i < 16*784; i += 384) {
                int c = i / 784, hw = i % 784;
                sI[hw*C2_PAD + c] = __float2half_rn(ib[i]);
            }
        }
        __syncthreads();

        float acc[C2_TB][2][6][4];
        #pragma unroll
        for (int tt = 0; tt < C2_TB; tt++)
            #pragma unroll
            for (int mt = 0; mt < 2; mt++)
                #pragma unroll
                for (int nt = 0; nt < 6; nt++)
                    #pragma unroll
                    for (int r = 0; r < 4; r++) acc[tt][mt][nt][r] = 0.f;

        #pragma unroll 1
        for (int j = 0; j < 25; j++) {
            int kh = j / 5, kw = j % 5;
            unsigned aoff = (unsigned)(j*32*C2_PAD*2);
            unsigned boff = (unsigned)((kh*28 + kw)*C2_PAD*2);

            unsigned aF[2][2][4];
            #pragma unroll
            for (int s = 0; s < 2; s++)
                #pragma unroll
                for (int mt = 0; mt < 2; mt++)
                    ldsm_x4(aF[s][mt], aaddr[s][mt] + aoff);

            #pragma unroll
            for (int tt = 0; tt < C2_TB; tt++) {
                unsigned bF[6][2];
                #pragma unroll
                for (int nt = 0; nt < 6; nt++)
                    ldsm_x2(bF[nt][0], bF[nt][1], baddr[nt] + boff + tt*TTOFF);
                #pragma unroll
                for (int s = 0; s < 2; s++)
                    #pragma unroll
                    for (int nt = 0; nt < 6; nt++)
                        #pragma unroll
                        for (int mt = 0; mt < 2; mt++)
                            mma16816(acc[tt][mt][nt], aF[s][mt], bF[nt][0], bF[nt][1]);
            }
        }

        #pragma unroll
        for (int tt = 0; tt < C2_TB; tt++) {
            float* zb = z2c + ((size_t)(t0+tt)*N_ + n)*32*576;
            #pragma unroll
            for (int mt = 0; mt < 2; mt++) {
                int o0 = mt*16 + qid;
                float b0 = bc2[o0], b1 = bc2[o0 + 8];
                #pragma unroll
                for (int nt = 0; nt < 6; nt++) {
                    int sp = w*48 + nt*8 + rid*2;
                    float2 d0; d0.x = acc[tt][mt][nt][0] + b0; d0.y = acc[tt][mt][nt][1] + b0;
                    float2 d1; d1.x = acc[tt][mt][nt][2] + b1; d1.y = acc[tt][mt][nt][3] + b1;
                    *reinterpret_cast<float2*>(zb + (size_t)o0*576 + sp)     = d0;
                    *reinterpret_cast<float2*>(zb + (size_t)(o0+8)*576 + sp) = d1;
                }
            }
        }
    }
}

// ---------------- conv3, tensor cores, PERSISTENT blocks ----------------
// Row stride 40 halfs = 80 B: 16B-aligned, conflict-free LDSM.
#define C3_PAD 40
#define C3_TB  4
#define C3_TILES ((T_/C3_TB)*N_)   // 384
__global__ void __launch_bounds__(256, 1)
k_conv3_mma(const float* __restrict__ p1s,
            const float* __restrict__ bc3,
            float* __restrict__ z3c) {
    extern __shared__ char sm[];
    __half* sW  = reinterpret_cast<__half*>(sm);                          // [2][25][32][C3_PAD]
    __half* sIn = reinterpret_cast<__half*>(sm + 2*25*32*C3_PAD*2);       // [C3_TB][144][C3_PAD]

    int tid = threadIdx.x;

    {   // stage weights ONCE
        const unsigned* src = reinterpret_cast<const unsigned*>(g_w3s);
        unsigned* dst = reinterpret_cast<unsigned*>(sW);
        for (int i = tid; i < 2*25*32*32/2; i += 256) {
            int e = i*2; int row = e >> 5; int c = e & 31;
            dst[(row*C3_PAD + c) >> 1] = src[i];
        }
    }

    int w    = tid >> 5;
    int lane = tid & 31;
    int qid  = lane >> 2;
    int rid  = lane & 3;
    int mi   = lane >> 3;
    int rr   = lane & 7;
    int matB = mi & 1;
    int mt   = w >> 2;
    int ntp  = w & 3;

    unsigned sInA = (unsigned)__cvta_generic_to_shared(sIn);
    unsigned sWA  = (unsigned)__cvta_generic_to_shared(sW);

    unsigned aaddr[2];
    #pragma unroll
    for (int s = 0; s < 2; s++) {
        int row = mt*16 + (mi & 1)*8 + rr;
        aaddr[s] = sWA + (((s*25)*32 + row)*C3_PAD + (mi >> 1)*8)*2;
    }
    unsigned baddr[2];
    #pragma unroll
    for (int q = 0; q < 2; q++) {
        int ntr = ntp*2 + q;
        baddr[q] = sInA + ((ntr*12 + rr)*C3_PAD + matB*8)*2;
    }
    constexpr unsigned TTOFF3 = 144*C3_PAD*2;

    int o0 = mt*16 + qid;
    float bb0 = bc3[o0], bb1 = bc3[o0 + 8];

    #pragma unroll 1
    for (int tile = blockIdx.x; tile < C3_TILES; tile += gridDim.x) {
        int n  = tile & (N_-1);
        int t0 = (tile >> 5) * C3_TB;

        __syncthreads();
        for (int tt = 0; tt < C3_TB; tt++) {
            const float* ib = p1s + ((size_t)(t0+tt)*N_ + n)*32*144;
            __half* sI = sIn + tt*144*C3_PAD;
            for (int i = tid; i < 32*144; i += 256) {
                int c = i / 144, hw = i % 144;
                sI[hw*C3_PAD + c] = __float2half_rn(ib[i]);
            }
        }
        __syncthreads();

        #pragma unroll 1
        for (int tp = 0; tp < C3_TB/2; tp++) {
            float acc[2][2][4];
            #pragma unroll
            for (int u = 0; u < 2; u++)
                #pragma unroll
                for (int q = 0; q < 2; q++)
                    #pragma unroll
                    for (int r = 0; r < 4; r++) acc[u][q][r] = 0.f;

            unsigned toffA = (tp*2)*TTOFF3, toffB = (tp*2+1)*TTOFF3;

            #pragma unroll 1
            for (int j = 0; j < 25; j++) {
                int kh = j / 5, kw = j % 5;
                unsigned aF[2][2][4];
                #pragma unroll
                for (int s = 0; s < 2; s++)
                    #pragma unroll
                    for (int kc = 0; kc < 2; kc++)
                        ldsm_x4(aF[s][kc], aaddr[s] + (unsigned)((j*32*C3_PAD + kc*16)*2));

                unsigned bF[2][2][2][2];
                #pragma unroll
                for (int kc = 0; kc < 2; kc++) {
                    unsigned bo = (unsigned)(((kh*12 + kw)*C3_PAD + kc*16)*2);
                    #pragma unroll
                    for (int q = 0; q < 2; q++) {
                        ldsm_x2(bF[0][kc][q][0], bF[0][kc][q][1], baddr[q] + bo + toffA);
                        ldsm_x2(bF[1][kc][q][0], bF[1][kc][q][1], baddr[q] + bo + toffB);
                    }
                }
                #pragma unroll
                for (int s = 0; s < 2; s++)
                    #pragma unroll
                    for (int kc = 0; kc < 2; kc++)
                        #pragma unroll
                        for (int u = 0; u < 2; u++)
                            #pragma unroll
                            for (int q = 0; q < 2; q++)
                                mma16816(acc[u][q], aF[s][kc], bF[u][kc][q][0], bF[u][kc][q][1]);
            }

            #pragma unroll
            for (int u = 0; u < 2; u++) {
                float* zb = z3c + ((size_t)(t0 + tp*2 + u)*N_ + n)*32*64;
                #pragma unroll
                for (int q = 0; q < 2; q++) {
                    int sp = (ntp*2 + q)*8 + rid*2;
                    float2 d0; d0.x = acc[u][q][0] + bb0; d0.y = acc[u][q][1] + bb0;
                    float2 d1; d1.x = acc[u][q][2] + bb1; d1.y = acc[u][q][3] + bb1;
                    *reinterpret_cast<float2*>(zb + (size_t)o0*64 + sp)     = d0;
                    *reinterpret_cast<float2*>(zb + (size_t)(o0+8)*64 + sp) = d1;
                }
            }
        }
    }
}

// ---------------- 5x5 VALID conv, scalar pipelined (conv1 only) ----------------
template<int CIN,int COUT,int HIN,int WIN,int GO,int WOT,int HOT,int TV,int MINB>
__global__ void
__launch_bounds__(((WIN-4)/WOT)*(COUT/GO)*HOT, MINB)
k_conv(const float* __restrict__ in,
       const float* __restrict__ Wc,
       const float* __restrict__ bc,
       float* __restrict__ z) {
    constexpr int HOUT = HIN-4, WOUT = WIN-4;
    constexpr int NWG  = WOUT/WOT;
    constexpr int NOG  = COUT/GO;
    constexpr int LANES = NWG*NOG;
    constexpr int HBLK = HOUT/HOT;
    constexpr int M    = CIN*5;
    constexpr size_t TS_IN  = (size_t)N_*CIN*HIN*WIN;
    constexpr size_t TS_OUT = (size_t)N_*COUT*HOUT*WOUT;
    extern __shared__ float ws[];
    {
        int tid = threadIdx.y*LANES + threadIdx.x;
        for (int i = tid; i < COUT*CIN*25; i += LANES*HOT) {
            int oc = i % COUT;
            int ck = i / COUT;
            ws[i] = Wc[oc*CIN*25 + ck];
        }
    }
    __syncthreads();

    int hb = blockIdx.x % HBLK;
    int t0 = (blockIdx.x / HBLK) * TV;
    int n  = blockIdx.y;
    int wg = threadIdx.x % NWG;
    int og = threadIdx.x / NWG;
    int wo = wg * WOT;
    int ho = hb*HOT + threadIdx.y;

    float acc[GO][WOT][TV];
    #pragma unroll
    for (int g = 0; g < GO; g++) {
        float b = bc[og*GO + g];
        #pragma unroll
        for (int ww = 0; ww < WOT; ww++)
            #pragma unroll
            for (int tv = 0; tv < TV; tv++) acc[g][ww][tv] = b;
    }

    const float* inb = in + (size_t)t0*TS_IN + (size_t)n*CIN*HIN*WIN
                          + (size_t)ho*WIN + wo;

    float va[WOT+4][TV], vb[WOT+4][TV];

    auto load_v = [&](int m, float (&v)[WOT+4][TV]) {
        int c = m / 5, kh = m % 5;
        const float* ip = inb + ((size_t)c*HIN + kh)*WIN;
        #pragma unroll
        for (int tv = 0; tv < TV; tv++) {
            const float2* p2 = reinterpret_cast<const float2*>(ip + (size_t)tv*TS_IN);
            #pragma unroll
            for (int j2 = 0; j2 < (WOT+4)/2; j2++) {
                float2 d = p2[j2];
                v[2*j2][tv]   = d.x;
                v[2*j2+1][tv] = d.y;
            }
        }
    };

    auto fma_step = [&](int m, float (&v)[WOT+4][TV]) {
        #pragma unroll
        for (int kw = 0; kw < 5; kw++) {
            float wreg[GO];
            if constexpr (GO == 4) {
                float4 w4 = *reinterpret_cast<const float4*>(&ws[(m*5 + kw)*COUT + og*4]);
                wreg[0] = w4.x; wreg[1] = w4.y; wreg[2] = w4.z; wreg[3] = w4.w;
            } else if constexpr (GO == 2) {
                float2 w2 = *reinterpret_cast<const float2*>(&ws[(m*5 + kw)*COUT + og*2]);
                wreg[0] = w2.x; wreg[1] = w2.y;
            } else {
                #pragma unroll
                for (int g = 0; g < GO; g++) wreg[g] = ws[(m*5 + kw)*COUT + og*GO + g];
            }
            #pragma unroll
            for (int g = 0; g < GO; g++)
                #pragma unroll
                for (int ww = 0; ww < WOT; ww++)
                    #pragma unroll
                    for (int tv = 0; tv < TV; tv++)
                        acc[g][ww][tv] += v[ww+kw][tv] * wreg[g];
        }
    };

    load_v(0, va);
    int m = 0;
    #pragma unroll 1
    for (; m + 2 <= M; m += 2) {
        load_v(m + 1, vb);
        fma_step(m, va);
        if (m + 2 < M) load_v(m + 2, va);
        fma_step(m + 1, vb);
    }
    if (m < M) fma_step(m, va);

    float* zb = z + (size_t)t0*TS_OUT + (size_t)n*COUT*HOUT*WOUT
                  + (size_t)og*GO*HOUT*WOUT + (size_t)ho*WOUT + wo;
    #pragma unroll
    for (int tv = 0; tv < TV; tv++)
        #pragma unroll
        for (int g = 0; g < GO; g++) {
            float* op = zb + (size_t)tv*TS_OUT + (size_t)g*HOUT*WOUT;
            #pragma unroll
            for (int j2 = 0; j2 < WOT/2; j2++) {
                float2 d; d.x = acc[g][2*j2][tv]; d.y = acc[g][2*j2+1][tv];
                reinterpret_cast<float2*>(op)[j2] = d;
            }
        }
}

// ---------------- LIF scan ----------------
template<int SZ>
__global__ void k_scan(const float* __restrict__ z, float* __restrict__ s_out) {
    int idx = blockIdx.x * blockDim.x + threadIdx.x;
    if (idx >= SZ) return;
    float u = 0.f;
    #pragma unroll 4
    for (int t = 0; t < T_; t++) {
        u += z[(size_t)t*SZ + idx];
        float s = (u >= 1.0f) ? 1.0f : 0.0f;
        u -= s;
        s_out[(size_t)t*SZ + idx] = s;
    }
}

// ---------------- fused LIF scan + 2x2 avg-pool + LIF scan ----------------
template<int C,int HIN>
__global__ void k_scanpool(const float* __restrict__ z, float* __restrict__ out) {
    constexpr int HO = HIN/2;
    constexpr size_t TS_IN  = (size_t)N_*C*HIN*HIN;
    constexpr size_t TS_OUT = (size_t)N_*C*HO*HO;
    int idx = blockIdx.x * blockDim.x + threadIdx.x;
    if (idx >= N_*C*HO*HO) return;
    int wo = idx % HO; int t1 = idx / HO;
    int ho = t1 % HO;  int t2 = t1 / HO;
    int c  = t2 % C;   int n  = t2 / C;
    const float* ip = z + ((size_t)n*C + c)*HIN*HIN + (size_t)(2*ho)*HIN + 2*wo;
    float* op = out + ((size_t)n*C + c)*HO*HO + (size_t)ho*HO + wo;
    float u0 = 0.f, u1 = 0.f, u2 = 0.f, u3 = 0.f, up = 0.f;
    #pragma unroll 4
    for (int t = 0; t < T_; t++) {
        const float* p = ip + (size_t)t*TS_IN;
        float2 r0 = *reinterpret_cast<const float2*>(p);
        float2 r1 = *reinterpret_cast<const float2*>(p + HIN);
        u0 += r0.x; float s0 = (u0 >= 1.0f) ? 1.0f : 0.0f; u0 -= s0;
        u1 += r0.y; float s1 = (u1 >= 1.0f) ? 1.0f : 0.0f; u1 -= s1;
        u2 += r1.x; float s2 = (u2 >= 1.0f) ? 1.0f : 0.0f; u2 -= s2;
        u3 += r1.y; float s3 = (u3 >= 1.0f) ? 1.0f : 0.0f; u3 -= s3;
        up += 0.25f*(s0 + s1 + s2 + s3);
        float sp = (up >= 1.0f) ? 1.0f : 0.0f; up -= sp;
        op[(size_t)t*TS_OUT] = sp;
    }
}

// ---------------- fc1 GEMM ----------------
__global__ void k_fc1(const float* __restrict__ bf1) {
    __shared__ float sin_[4][512];
    int t0 = blockIdx.x*4, n = blockIdx.y, o = threadIdx.x;
    for (int i = o; i < 4*512; i += 128) {
        int tv = i >> 9, k = i & 511;
        sin_[tv][k] = g_p2[((size_t)(t0+tv)*N_ + n)*512 + k];
    }
    __syncthreads();
    float b = bf1[o];
    float acc[4] = {b, b, b, b};
    #pragma unroll 4
    for (int k = 0; k < 512; k++) {
        float w = g_wt1[k*128 + o];
        #pragma unroll
        for (int tv = 0; tv < 4; tv++) acc[tv] += sin_[tv][k] * w;
    }
    #pragma unroll
    for (int tv = 0; tv < 4; tv++)
        g_z1[((size_t)(t0+tv)*N_ + n)*128 + o] = acc[tv];
}

// ---------------- head: warp-parallel fc2 ----------------
__global__ void k_head(const float* __restrict__ Wf2, const float* __restrict__ bf2,
                       float* __restrict__ out) {
    int n = blockIdx.x, o = threadIdx.x;
    int wid = o >> 5, lane = o & 31;
    __shared__ float s1[128];
    float wr[4] = {0.f, 0.f, 0.f, 0.f};
    float b2 = 0.f;
    if (wid < 2) {
        #pragma unroll
        for (int k = 0; k < 4; k++) wr[k] = Wf2[wid*128 + lane + 32*k];
        b2 = bf2[wid];
    }
    float u1 = 0.f, u2 = 0.f, ssum = 0.f;
    for (int t = 0; t < T_; t++) {
        float z = g_z1[((size_t)t*N_ + n)*128 + o];
        u1 += z;
        float s = (u1 >= 1.0f) ? 1.0f : 0.0f;
        u1 -= s;
        s1[o] = s;
        __syncthreads();
        if (wid < 2) {
            float d = s1[lane]*wr[0] + s1[lane+32]*wr[1]
                    + s1[lane+64]*wr[2] + s1[lane+96]*wr[3];
            #pragma unroll
            for (int off = 16; off > 0; off >>= 1)
                d += __shfl_xor_sync(0xFFFFFFFFu, d, off);
            u2 += d + b2;
            float s2 = (u2 >= 1.0f) ? 1.0f : 0.0f;
            u2 -= s2;
            ssum += s2;
        }
        __syncthreads();
    }
    if (wid < 2 && lane == 0) out[n*2 + wid] = ssum * (1.0f / T_);
}

// ---------------- launch ----------------
extern "C" void kernel_launch(void* const* d_in, const int* in_sizes, int n_in,
                              void* d_out, int out_size) {
    (void)in_sizes; (void)n_in; (void)out_size;
    const float* x   = (const float*)d_in[0];
    const float* Wc1 = (const float*)d_in[1];
    const float* bc1 = (const float*)d_in[2];
    const float* Wc2 = (const float*)d_in[3];
    const float* bc2 = (const float*)d_in[4];
    const float* Wc3 = (const float*)d_in[5];
    const float* bc3 = (const float*)d_in[6];
    const float* Wf1 = (const float*)d_in[7];
    const float* bf1 = (const float*)d_in[8];
    const float* Wf2 = (const float*)d_in[9];
    const float* bf2 = (const float*)d_in[10];
    float* out = (float*)d_out;

    float *p_xt, *p_z1c, *p_h1, *p_z2c, *p_p1, *p_z3c, *p_p2;
    cudaGetSymbolAddress((void**)&p_xt,  g_xt);
    cudaGetSymbolAddress((void**)&p_z1c, g_z1c);
    cudaGetSymbolAddress((void**)&p_h1,  g_h1);
    cudaGetSymbolAddress((void**)&p_z2c, g_z2c);
    cudaGetSymbolAddress((void**)&p_p1,  g_p1);
    cudaGetSymbolAddress((void**)&p_z3c, g_z3c);
    cudaGetSymbolAddress((void**)&p_p2,  g_p2);

    auto c1 = k_conv<1,16,32,32,4,4,7,2,2>;

    constexpr int SMEM_C2 = C2_TB*784*C2_PAD*2 + 2*25*32*C2_PAD*2;
    constexpr int SMEM_C3 = 2*25*32*C3_PAD*2 + C3_TB*144*C3_PAD*2;
    cudaFuncSetAttribute(k_conv2_mma, cudaFuncAttributeMaxDynamicSharedMemorySize, SMEM_C2);
    cudaFuncSetAttribute(k_conv3_mma, cudaFuncAttributeMaxDynamicSharedMemorySize, SMEM_C3);

    constexpr int SZ1 = N_*16*28*28;

    // launch order chosen so k_conv2_mma is launch #4 (ncu capture slot)
    k_prep<<<(PWT + 255)/256, 256>>>(x, Wf1, Wc2, Wc3);                       // 1
    c1<<<dim3(4*(T_/2), N_), dim3(28, 7), 16*1*25*4>>>(p_xt, Wc1, bc1, p_z1c); // 2
    k_scan<SZ1><<<(SZ1 + 255)/256, 256>>>(p_z1c, p_h1);                        // 3
    k_conv2_mma<<<NSM, 384, SMEM_C2>>>(p_h1, bc2, p_z2c);                      // 4 <- profiled
    k_scanpool<32,24><<<(N_*32*12*12 + 255)/256, 256>>>(p_z2c, p_p1);          // 5
    k_conv3_mma<<<NSM, 256, SMEM_C3>>>(p_p1, bc3, p_z3c);                      // 6
    k_scanpool<32,8><<<(N_*32*4*4 + 255)/256, 256>>>(p_z3c, p_p2);             // 7
    k_fc1<<<dim3(T_/4, N_), 128>>>(bf1);                                       // 8
    k_head<<<N_, 128>>>(Wf2, bf2, out);                                        // 9
}

// round 14
// speedup vs baseline: 2.5980x; 1.0317x over previous
#include <cuda_runtime.h>
#include <cuda_bf16.h>
#include <cuda_fp16.h>

#define N_ 32
#define T_ 48
#define NSM 148

// ---------------- scratch ----------------
__device__ float g_xt[(size_t)T_*N_*32*32];
__device__ float g_z1c[(size_t)T_*N_*16*28*28];            // conv1 pre-acts [t][n][c][hw]
__device__ __align__(256) __half g_h1h[(size_t)T_*N_*784*16]; // conv1 spikes fp16 [t][n][hw][c16]
__device__ float g_z2c[(size_t)T_*N_*32*24*24];
__device__ float g_p1[(size_t)T_*N_*32*12*12];
__device__ float g_z3c[(size_t)T_*N_*32*8*8];
__device__ float g_p2[(size_t)T_*N_*32*4*4];
__device__ float g_wt1[512*128];
__device__ float g_z1[(size_t)T_*N_*128];
__device__ __half g_w2s[2*25*32*16];   // conv2 w split [s][j][o][c16], fp16 2-way
__device__ __half g_w3s[2*25*32*32];   // conv3 w split [s][j][o][c32], fp16 2-way

// ---------------- fused prep ----------------
#define PW0 (N_*32*32)
#define PW1 (128*512)
#define PW2 (25*32*16)
#define PW3 (25*32*32)
#define PWT (PW0+PW1+PW2+PW3)
__global__ void k_prep(const float* __restrict__ x,  const float* __restrict__ Wf1,
                       const float* __restrict__ Wc2, const float* __restrict__ Wc3) {
    int gid = blockIdx.x*256 + threadIdx.x;
    if (gid < PW0) {
        int n = gid >> 10, hw = gid & 1023;
        const float* xp = x + (size_t)gid * T_;
        #pragma unroll
        for (int t = 0; t < T_; t++)
            g_xt[((size_t)t*N_ + n)*1024 + hw] = xp[t];
    } else if (gid < PW0+PW1) {
        int i = gid - PW0;
        int o = i >> 9, k = i & 511;
        g_wt1[k*128 + o] = Wf1[i];
    } else if (gid < PW0+PW1+PW2) {
        int i = gid - (PW0+PW1);
        int c = i % 16, o = (i/16) % 32, j = i/512;
        int kh = j/5, kw = j%5;
        float w = Wc2[((o*16 + c)*5 + kh)*5 + kw];
        __half h = __float2half_rn(w);
        float r = w - __half2float(h);
        g_w2s[0*12800 + i] = h;
        g_w2s[1*12800 + i] = __float2half_rn(r);
    } else if (gid < PWT) {
        int i = gid - (PW0+PW1+PW2);
        int c = i % 32, o = (i/32) % 32, j = i/1024;
        int kh = j/5, kw = j%5;
        float w = Wc3[((o*32 + c)*5 + kh)*5 + kw];
        __half h = __float2half_rn(w);
        float r = w - __half2float(h);
        g_w3s[0*25600 + i] = h;
        g_w3s[1*25600 + i] = __float2half_rn(r);
    }
}

// ---------------- mma / ldmatrix / cp.async helpers ----------------
__device__ __forceinline__ void mma16816(float* c, const unsigned* a,
                                         unsigned b0, unsigned b1) {
    asm volatile(
        "mma.sync.aligned.m16n8k16.row.col.f32.f16.f16.f32 "
        "{%0,%1,%2,%3}, {%4,%5,%6,%7}, {%8,%9}, {%0,%1,%2,%3};"
        : "+f"(c[0]), "+f"(c[1]), "+f"(c[2]), "+f"(c[3])
        : "r"(a[0]), "r"(a[1]), "r"(a[2]), "r"(a[3]), "r"(b0), "r"(b1));
}
__device__ __forceinline__ void ldsm_x4(unsigned* d, unsigned a) {
    asm volatile("ldmatrix.sync.aligned.m8n8.x4.shared.b16 {%0,%1,%2,%3}, [%4];"
                 : "=r"(d[0]), "=r"(d[1]), "=r"(d[2]), "=r"(d[3]) : "r"(a));
}
__device__ __forceinline__ void ldsm_x2(unsigned& d0, unsigned& d1, unsigned a) {
    asm volatile("ldmatrix.sync.aligned.m8n8.x2.shared.b16 {%0,%1}, [%2];"
                 : "=r"(d0), "=r"(d1) : "r"(a));
}
__device__ __forceinline__ void cp16(unsigned dst, const void* src) {
    asm volatile("cp.async.ca.shared.global [%0], [%1], 16;" :: "r"(dst), "l"(src));
}
#define CP_COMMIT() asm volatile("cp.async.commit_group;" ::: "memory")
#define CP_WAIT1()  asm volatile("cp.async.wait_group 1;" ::: "memory")

// ---------------- conv2: persistent blocks + cp.async double-buffered staging ----------------
#define C2_PAD 24
#define C2_TB  2
#define C2_TILES ((T_/C2_TB)*N_)   // 768
#define C2_BUFB (C2_TB*784*C2_PAD*2)   // bytes per input buffer = 75264
__global__ void __launch_bounds__(384, 1)
k_conv2_mma(const __half* __restrict__ h1h,
            const float* __restrict__ bc2,
            float* __restrict__ z2c) {
    extern __shared__ char sm[];
    __half* sIn = reinterpret_cast<__half*>(sm);                  // 2 buffers
    __half* sW  = reinterpret_cast<__half*>(sm + 2*C2_BUFB);      // [2][25][32][C2_PAD]

    int tid = threadIdx.x;

    {   // stage weights ONCE
        const unsigned* src = reinterpret_cast<const unsigned*>(g_w2s);
        unsigned* dst = reinterpret_cast<unsigned*>(sW);
        for (int i = tid; i < 2*25*32*16/2; i += 384) {
            int e = i*2; int row = e >> 4; int c = e & 15;
            dst[(row*C2_PAD + c) >> 1] = src[i];
        }
    }

    int w    = tid >> 5;
    int lane = tid & 31;
    int qid  = lane >> 2;
    int rid  = lane & 3;
    int mi   = lane >> 3;
    int rr   = lane & 7;
    int matB = mi & 1;

    unsigned sInA = (unsigned)__cvta_generic_to_shared(sIn);
    unsigned sWA  = (unsigned)__cvta_generic_to_shared(sW);

    unsigned aaddr[2][2];
    #pragma unroll
    for (int s = 0; s < 2; s++)
        #pragma unroll
        for (int mt = 0; mt < 2; mt++) {
            int row = mt*16 + (mi & 1)*8 + rr;
            aaddr[s][mt] = sWA + (((s*25)*32 + row)*C2_PAD + (mi >> 1)*8)*2;
        }
    unsigned baddr[6];
    #pragma unroll
    for (int nt = 0; nt < 6; nt++) {
        int sp = w*48 + nt*8 + rr;
        int ho = sp / 24, wo = sp % 24;
        baddr[nt] = sInA + ((ho*28 + wo)*C2_PAD + matB*8)*2;
    }
    constexpr unsigned TTOFF = 784*C2_PAD*2;

    // cp.async staging of one tile (pure byte copy, 16B chunks)
    auto stage = [&](int tile, int buf) {
        int n  = tile & (N_-1);
        int t0 = (tile >> 5) * C2_TB;
        for (int i = tid; i < C2_TB*784*2; i += 384) {
            int half16 = i & 1;
            int r = i >> 1;
            int hw = r % 784, tt = r / 784;
            const __half* src = h1h + (((size_t)(t0+tt)*N_ + n)*784 + hw)*16 + half16*8;
            unsigned dst = sInA + (unsigned)(buf*C2_BUFB)
                         + (unsigned)(((tt*784 + hw)*C2_PAD + half16*8)*2);
            cp16(dst, src);
        }
    };

    if (blockIdx.x < C2_TILES) stage(blockIdx.x, 0);
    CP_COMMIT();

    int it = 0;
    #pragma unroll 1
    for (int tile = blockIdx.x; tile < C2_TILES; tile += gridDim.x, it++) {
        int cur = it & 1;
        __syncthreads();                 // prior compute done before overwriting other buf
        int nxt = tile + gridDim.x;
        if (nxt < C2_TILES) stage(nxt, cur ^ 1);
        CP_COMMIT();
        CP_WAIT1();                      // current tile's copies complete
        __syncthreads();

        unsigned bufoff = (unsigned)(cur*C2_BUFB);
        int n  = tile & (N_-1);
        int t0 = (tile >> 5) * C2_TB;

        float acc[C2_TB][2][6][4];
        #pragma unroll
        for (int tt = 0; tt < C2_TB; tt++)
            #pragma unroll
            for (int mt = 0; mt < 2; mt++)
                #pragma unroll
                for (int nt = 0; nt < 6; nt++)
                    #pragma unroll
                    for (int r = 0; r < 4; r++) acc[tt][mt][nt][r] = 0.f;

        #pragma unroll 1
        for (int j = 0; j < 25; j++) {
            int kh = j / 5, kw = j % 5;
            unsigned aoff = (unsigned)(j*32*C2_PAD*2);
            unsigned boff = bufoff + (unsigned)((kh*28 + kw)*C2_PAD*2);

            unsigned aF[2][2][4];
            #pragma unroll
            for (int s = 0; s < 2; s++)
                #pragma unroll
                for (int mt = 0; mt < 2; mt++)
                    ldsm_x4(aF[s][mt], aaddr[s][mt] + aoff);

            #pragma unroll
            for (int tt = 0; tt < C2_TB; tt++) {
                unsigned bF[6][2];
                #pragma unroll
                for (int nt = 0; nt < 6; nt++)
                    ldsm_x2(bF[nt][0], bF[nt][1], baddr[nt] + boff + tt*TTOFF);
                #pragma unroll
                for (int s = 0; s < 2; s++)
                    #pragma unroll
                    for (int nt = 0; nt < 6; nt++)
                        #pragma unroll
                        for (int mt = 0; mt < 2; mt++)
                            mma16816(acc[tt][mt][nt], aF[s][mt], bF[nt][0], bF[nt][1]);
            }
        }

        #pragma unroll
        for (int tt = 0; tt < C2_TB; tt++) {
            float* zb = z2c + ((size_t)(t0+tt)*N_ + n)*32*576;
            #pragma unroll
            for (int mt = 0; mt < 2; mt++) {
                int o0 = mt*16 + qid;
                float b0 = bc2[o0], b1 = bc2[o0 + 8];
                #pragma unroll
                for (int nt = 0; nt < 6; nt++) {
                    int sp = w*48 + nt*8 + rid*2;
                    float2 d0; d0.x = acc[tt][mt][nt][0] + b0; d0.y = acc[tt][mt][nt][1] + b0;
                    float2 d1; d1.x = acc[tt][mt][nt][2] + b1; d1.y = acc[tt][mt][nt][3] + b1;
                    *reinterpret_cast<float2*>(zb + (size_t)o0*576 + sp)     = d0;
                    *reinterpret_cast<float2*>(zb + (size_t)(o0+8)*576 + sp) = d1;
                }
            }
        }
    }
}

// ---------------- conv3, tensor cores, persistent (unchanged from R13) ----------------
#define C3_PAD 40
#define C3_TB  4
#define C3_TILES ((T_/C3_TB)*N_)
__global__ void __launch_bounds__(256, 1)
k_conv3_mma(const float* __restrict__ p1s,
            const float* __restrict__ bc3,
            float* __restrict__ z3c) {
    extern __shared__ char sm[];
    __half* sW  = reinterpret_cast<__half*>(sm);
    __half* sIn = reinterpret_cast<__half*>(sm + 2*25*32*C3_PAD*2);

    int tid = threadIdx.x;

    {
        const unsigned* src = reinterpret_cast<const unsigned*>(g_w3s);
        unsigned* dst = reinterpret_cast<unsigned*>(sW);
        for (int i = tid; i < 2*25*32*32/2; i += 256) {
            int e = i*2; int row = e >> 5; int c = e & 31;
            dst[(row*C3_PAD + c) >> 1] = src[i];
        }
    }

    int w    = tid >> 5;
    int lane = tid & 31;
    int qid  = lane >> 2;
    int rid  = lane & 3;
    int mi   = lane >> 3;
    int rr   = lane & 7;
    int matB = mi & 1;
    int mt   = w >> 2;
    int ntp  = w & 3;

    unsigned sInA = (unsigned)__cvta_generic_to_shared(sIn);
    unsigned sWA  = (unsigned)__cvta_generic_to_shared(sW);

    unsigned aaddr[2];
    #pragma unroll
    for (int s = 0; s < 2; s++) {
        int row = mt*16 + (mi & 1)*8 + rr;
        aaddr[s] = sWA + (((s*25)*32 + row)*C3_PAD + (mi >> 1)*8)*2;
    }
    unsigned baddr[2];
    #pragma unroll
    for (int q = 0; q < 2; q++) {
        int ntr = ntp*2 + q;
        baddr[q] = sInA + ((ntr*12 + rr)*C3_PAD + matB*8)*2;
    }
    constexpr unsigned TTOFF3 = 144*C3_PAD*2;

    int o0 = mt*16 + qid;
    float bb0 = bc3[o0], bb1 = bc3[o0 + 8];

    #pragma unroll 1
    for (int tile = blockIdx.x; tile < C3_TILES; tile += gridDim.x) {
        int n  = tile & (N_-1);
        int t0 = (tile >> 5) * C3_TB;

        __syncthreads();
        for (int tt = 0; tt < C3_TB; tt++) {
            const float* ib = p1s + ((size_t)(t0+tt)*N_ + n)*32*144;
            __half* sI = sIn + tt*144*C3_PAD;
            for (int i = tid; i < 32*144; i += 256) {
                int c = i / 144, hw = i % 144;
                sI[hw*C3_PAD + c] = __float2half_rn(ib[i]);
            }
        }
        __syncthreads();

        #pragma unroll 1
        for (int tp = 0; tp < C3_TB/2; tp++) {
            float acc[2][2][4];
            #pragma unroll
            for (int u = 0; u < 2; u++)
                #pragma unroll
                for (int q = 0; q < 2; q++)
                    #pragma unroll
                    for (int r = 0; r < 4; r++) acc[u][q][r] = 0.f;

            unsigned toffA = (tp*2)*TTOFF3, toffB = (tp*2+1)*TTOFF3;

            #pragma unroll 1
            for (int j = 0; j < 25; j++) {
                int kh = j / 5, kw = j % 5;
                unsigned aF[2][2][4];
                #pragma unroll
                for (int s = 0; s < 2; s++)
                    #pragma unroll
                    for (int kc = 0; kc < 2; kc++)
                        ldsm_x4(aF[s][kc], aaddr[s] + (unsigned)((j*32*C3_PAD + kc*16)*2));

                unsigned bF[2][2][2][2];
                #pragma unroll
                for (int kc = 0; kc < 2; kc++) {
                    unsigned bo = (unsigned)(((kh*12 + kw)*C3_PAD + kc*16)*2);
                    #pragma unroll
                    for (int q = 0; q < 2; q++) {
                        ldsm_x2(bF[0][kc][q][0], bF[0][kc][q][1], baddr[q] + bo + toffA);
                        ldsm_x2(bF[1][kc][q][0], bF[1][kc][q][1], baddr[q] + bo + toffB);
                    }
                }
                #pragma unroll
                for (int s = 0; s < 2; s++)
                    #pragma unroll
                    for (int kc = 0; kc < 2; kc++)
                        #pragma unroll
                        for (int u = 0; u < 2; u++)
                            #pragma unroll
                            for (int q = 0; q < 2; q++)
                                mma16816(acc[u][q], aF[s][kc], bF[u][kc][q][0], bF[u][kc][q][1]);
            }

            #pragma unroll
            for (int u = 0; u < 2; u++) {
                float* zb = z3c + ((size_t)(t0 + tp*2 + u)*N_ + n)*32*64;
                #pragma unroll
                for (int q = 0; q < 2; q++) {
                    int sp = (ntp*2 + q)*8 + rid*2;
                    float2 d0; d0.x = acc[u][q][0] + bb0; d0.y = acc[u][q][1] + bb0;
                    float2 d1; d1.x = acc[u][q][2] + bb1; d1.y = acc[u][q][3] + bb1;
                    *reinterpret_cast<float2*>(zb + (size_t)o0*64 + sp)     = d0;
                    *reinterpret_cast<float2*>(zb + (size_t)(o0+8)*64 + sp) = d1;
                }
            }
        }
    }
}

// ---------------- conv1 scalar (unchanged) ----------------
template<int CIN,int COUT,int HIN,int WIN,int GO,int WOT,int HOT,int TV,int MINB>
__global__ void
__launch_bounds__(((WIN-4)/WOT)*(COUT/GO)*HOT, MINB)
k_conv(const float* __restrict__ in,
       const float* __restrict__ Wc,
       const float* __restrict__ bc,
       float* __restrict__ z) {
    constexpr int HOUT = HIN-4, WOUT = WIN-4;
    constexpr int NWG  = WOUT/WOT;
    constexpr int NOG  = COUT/GO;
    constexpr int LANES = NWG*NOG;
    constexpr int HBLK = HOUT/HOT;
    constexpr int M    = CIN*5;
    constexpr size_t TS_IN  = (size_t)N_*CIN*HIN*WIN;
    constexpr size_t TS_OUT = (size_t)N_*COUT*HOUT*WOUT;
    extern __shared__ float ws[];
    {
        int tid = threadIdx.y*LANES + threadIdx.x;
        for (int i = tid; i < COUT*CIN*25; i += LANES*HOT) {
            int oc = i % COUT;
            int ck = i / COUT;
            ws[i] = Wc[oc*CIN*25 + ck];
        }
    }
    __syncthreads();

    int hb = blockIdx.x % HBLK;
    int t0 = (blockIdx.x / HBLK) * TV;
    int n  = blockIdx.y;
    int wg = threadIdx.x % NWG;
    int og = threadIdx.x / NWG;
    int wo = wg * WOT;
    int ho = hb*HOT + threadIdx.y;

    float acc[GO][WOT][TV];
    #pragma unroll
    for (int g = 0; g < GO; g++) {
        float b = bc[og*GO + g];
        #pragma unroll
        for (int ww = 0; ww < WOT; ww++)
            #pragma unroll
            for (int tv = 0; tv < TV; tv++) acc[g][ww][tv] = b;
    }

    const float* inb = in + (size_t)t0*TS_IN + (size_t)n*CIN*HIN*WIN
                          + (size_t)ho*WIN + wo;

    float va[WOT+4][TV], vb[WOT+4][TV];

    auto load_v = [&](int m, float (&v)[WOT+4][TV]) {
        int c = m / 5, kh = m % 5;
        const float* ip = inb + ((size_t)c*HIN + kh)*WIN;
        #pragma unroll
        for (int tv = 0; tv < TV; tv++) {
            const float2* p2 = reinterpret_cast<const float2*>(ip + (size_t)tv*TS_IN);
            #pragma unroll
            for (int j2 = 0; j2 < (WOT+4)/2; j2++) {
                float2 d = p2[j2];
                v[2*j2][tv]   = d.x;
                v[2*j2+1][tv] = d.y;
            }
        }
    };

    auto fma_step = [&](int m, float (&v)[WOT+4][TV]) {
        #pragma unroll
        for (int kw = 0; kw < 5; kw++) {
            float wreg[GO];
            if constexpr (GO == 4) {
                float4 w4 = *reinterpret_cast<const float4*>(&ws[(m*5 + kw)*COUT + og*4]);
                wreg[0] = w4.x; wreg[1] = w4.y; wreg[2] = w4.z; wreg[3] = w4.w;
            } else if constexpr (GO == 2) {
                float2 w2 = *reinterpret_cast<const float2*>(&ws[(m*5 + kw)*COUT + og*2]);
                wreg[0] = w2.x; wreg[1] = w2.y;
            } else {
                #pragma unroll
                for (int g = 0; g < GO; g++) wreg[g] = ws[(m*5 + kw)*COUT + og*GO + g];
            }
            #pragma unroll
            for (int g = 0; g < GO; g++)
                #pragma unroll
                for (int ww = 0; ww < WOT; ww++)
                    #pragma unroll
                    for (int tv = 0; tv < TV; tv++)
                        acc[g][ww][tv] += v[ww+kw][tv] * wreg[g];
        }
    };

    load_v(0, va);
    int m = 0;
    #pragma unroll 1
    for (; m + 2 <= M; m += 2) {
        load_v(m + 1, vb);
        fma_step(m, va);
        if (m + 2 < M) load_v(m + 2, va);
        fma_step(m + 1, vb);
    }
    if (m < M) fma_step(m, va);

    float* zb = z + (size_t)t0*TS_OUT + (size_t)n*COUT*HOUT*WOUT
                  + (size_t)og*GO*HOUT*WOUT + (size_t)ho*WOUT + wo;
    #pragma unroll
    for (int tv = 0; tv < TV; tv++)
        #pragma unroll
        for (int g = 0; g < GO; g++) {
            float* op = zb + (size_t)tv*TS_OUT + (size_t)g*HOUT*WOUT;
            #pragma unroll
            for (int j2 = 0; j2 < WOT/2; j2++) {
                float2 d; d.x = acc[g][2*j2][tv]; d.y = acc[g][2*j2+1][tv];
                reinterpret_cast<float2*>(op)[j2] = d;
            }
        }
}

// ---------------- layer-1 LIF scan: fp32 [t][n][c][hw] -> fp16 [t][n][hw][c16] ----------------
__global__ void k_scan1t(const float* __restrict__ z, __half* __restrict__ hout) {
    int idx = blockIdx.x * blockDim.x + threadIdx.x;   // over N_*784
    if (idx >= N_*784) return;
    int n = idx / 784, hw = idx % 784;
    float u[16];
    #pragma unroll
    for (int c = 0; c < 16; c++) u[c] = 0.f;
    #pragma unroll 2
    for (int t = 0; t < T_; t++) {
        const float* zp = z + ((size_t)t*N_ + n)*16*784 + hw;
        __half hh[16];
        #pragma unroll
        for (int c = 0; c < 16; c++) {
            u[c] += zp[(size_t)c*784];
            float s = (u[c] >= 1.0f) ? 1.0f : 0.0f;
            u[c] -= s;
            hh[c] = __float2half_rn(s);
        }
        uint4* op = reinterpret_cast<uint4*>(hout + (((size_t)t*N_ + n)*784 + hw)*16);
        op[0] = reinterpret_cast<uint4*>(hh)[0];
        op[1] = reinterpret_cast<uint4*>(hh)[1];
    }
}

// ---------------- fused LIF scan + 2x2 avg-pool + LIF scan ----------------
template<int C,int HIN>
__global__ void k_scanpool(const float* __restrict__ z, float* __restrict__ out) {
    constexpr int HO = HIN/2;
    constexpr size_t TS_IN  = (size_t)N_*C*HIN*HIN;
    constexpr size_t TS_OUT = (size_t)N_*C*HO*HO;
    int idx = blockIdx.x * blockDim.x + threadIdx.x;
    if (idx >= N_*C*HO*HO) return;
    int wo = idx % HO; int t1 = idx / HO;
    int ho = t1 % HO;  int t2 = t1 / HO;
    int c  = t2 % C;   int n  = t2 / C;
    const float* ip = z + ((size_t)n*C + c)*HIN*HIN + (size_t)(2*ho)*HIN + 2*wo;
    float* op = out + ((size_t)n*C + c)*HO*HO + (size_t)ho*HO + wo;
    float u0 = 0.f, u1 = 0.f, u2 = 0.f, u3 = 0.f, up = 0.f;
    #pragma unroll 4
    for (int t = 0; t < T_; t++) {
        const float* p = ip + (size_t)t*TS_IN;
        float2 r0 = *reinterpret_cast<const float2*>(p);
        float2 r1 = *reinterpret_cast<const float2*>(p + HIN);
        u0 += r0.x; float s0 = (u0 >= 1.0f) ? 1.0f : 0.0f; u0 -= s0;
        u1 += r0.y; float s1 = (u1 >= 1.0f) ? 1.0f : 0.0f; u1 -= s1;
        u2 += r1.x; float s2 = (u2 >= 1.0f) ? 1.0f : 0.0f; u2 -= s2;
        u3 += r1.y; float s3 = (u3 >= 1.0f) ? 1.0f : 0.0f; u3 -= s3;
        up += 0.25f*(s0 + s1 + s2 + s3);
        float sp = (up >= 1.0f) ? 1.0f : 0.0f; up -= sp;
        op[(size_t)t*TS_OUT] = sp;
    }
}

// ---------------- fc1 GEMM ----------------
__global__ void k_fc1(const float* __restrict__ bf1) {
    __shared__ float sin_[4][512];
    int t0 = blockIdx.x*4, n = blockIdx.y, o = threadIdx.x;
    for (int i = o; i < 4*512; i += 128) {
        int tv = i >> 9, k = i & 511;
        sin_[tv][k] = g_p2[((size_t)(t0+tv)*N_ + n)*512 + k];
    }
    __syncthreads();
    float b = bf1[o];
    float acc[4] = {b, b, b, b};
    #pragma unroll 4
    for (int k = 0; k < 512; k++) {
        float w = g_wt1[k*128 + o];
        #pragma unroll
        for (int tv = 0; tv < 4; tv++) acc[tv] += sin_[tv][k] * w;
    }
    #pragma unroll
    for (int tv = 0; tv < 4; tv++)
        g_z1[((size_t)(t0+tv)*N_ + n)*128 + o] = acc[tv];
}

// ---------------- head: warp-parallel fc2 ----------------
__global__ void k_head(const float* __restrict__ Wf2, const float* __restrict__ bf2,
                       float* __restrict__ out) {
    int n = blockIdx.x, o = threadIdx.x;
    int wid = o >> 5, lane = o & 31;
    __shared__ float s1[128];
    float wr[4] = {0.f, 0.f, 0.f, 0.f};
    float b2 = 0.f;
    if (wid < 2) {
        #pragma unroll
        for (int k = 0; k < 4; k++) wr[k] = Wf2[wid*128 + lane + 32*k];
        b2 = bf2[wid];
    }
    float u1 = 0.f, u2 = 0.f, ssum = 0.f;
    for (int t = 0; t < T_; t++) {
        float z = g_z1[((size_t)t*N_ + n)*128 + o];
        u1 += z;
        float s = (u1 >= 1.0f) ? 1.0f : 0.0f;
        u1 -= s;
        s1[o] = s;
        __syncthreads();
        if (wid < 2) {
            float d = s1[lane]*wr[0] + s1[lane+32]*wr[1]
                    + s1[lane+64]*wr[2] + s1[lane+96]*wr[3];
            #pragma unroll
            for (int off = 16; off > 0; off >>= 1)
                d += __shfl_xor_sync(0xFFFFFFFFu, d, off);
            u2 += d + b2;
            float s2 = (u2 >= 1.0f) ? 1.0f : 0.0f;
            u2 -= s2;
            ssum += s2;
        }
        __syncthreads();
    }
    if (wid < 2 && lane == 0) out[n*2 + wid] = ssum * (1.0f / T_);
}

// ---------------- launch ----------------
extern "C" void kernel_launch(void* const* d_in, const int* in_sizes, int n_in,
                              void* d_out, int out_size) {
    (void)in_sizes; (void)n_in; (void)out_size;
    const float* x   = (const float*)d_in[0];
    const float* Wc1 = (const float*)d_in[1];
    const float* bc1 = (const float*)d_in[2];
    const float* Wc2 = (const float*)d_in[3];
    const float* bc2 = (const float*)d_in[4];
    const float* Wc3 = (const float*)d_in[5];
    const float* bc3 = (const float*)d_in[6];
    const float* Wf1 = (const float*)d_in[7];
    const float* bf1 = (const float*)d_in[8];
    const float* Wf2 = (const float*)d_in[9];
    const float* bf2 = (const float*)d_in[10];
    float* out = (float*)d_out;

    float *p_xt, *p_z1c, *p_z2c, *p_p1, *p_z3c, *p_p2;
    __half *p_h1h;
    cudaGetSymbolAddress((void**)&p_xt,  g_xt);
    cudaGetSymbolAddress((void**)&p_z1c, g_z1c);
    cudaGetSymbolAddress((void**)&p_h1h, g_h1h);
    cudaGetSymbolAddress((void**)&p_z2c, g_z2c);
    cudaGetSymbolAddress((void**)&p_p1,  g_p1);
    cudaGetSymbolAddress((void**)&p_z3c, g_z3c);
    cudaGetSymbolAddress((void**)&p_p2,  g_p2);

    auto c1 = k_conv<1,16,32,32,4,4,7,2,2>;

    constexpr int SMEM_C2 = 2*C2_BUFB + 2*25*32*C2_PAD*2;             // 150528 + 76800 = 227328
    constexpr int SMEM_C3 = 2*25*32*C3_PAD*2 + C3_TB*144*C3_PAD*2;
    cudaFuncSetAttribute(k_conv2_mma, cudaFuncAttributeMaxDynamicSharedMemorySize, SMEM_C2);
    cudaFuncSetAttribute(k_conv3_mma, cudaFuncAttributeMaxDynamicSharedMemorySize, SMEM_C3);

    // launch order: k_conv2_mma stays launch #4 (ncu capture slot)
    k_prep<<<(PWT + 255)/256, 256>>>(x, Wf1, Wc2, Wc3);                        // 1
    c1<<<dim3(4*(T_/2), N_), dim3(28, 7), 16*1*25*4>>>(p_xt, Wc1, bc1, p_z1c); // 2
    k_scan1t<<<(N_*784 + 255)/256, 256>>>(p_z1c, p_h1h);                       // 3
    k_conv2_mma<<<NSM, 384, SMEM_C2>>>(p_h1h, bc2, p_z2c);                     // 4 <- profiled
    k_scanpool<32,24><<<(N_*32*12*12 + 255)/256, 256>>>(p_z2c, p_p1);          // 5
    k_conv3_mma<<<NSM, 256, SMEM_C3>>>(p_p1, bc3, p_z3c);                      // 6
    k_scanpool<32,8><<<(N_*32*4*4 + 255)/256, 256>>>(p_z3c, p_p2);             // 7
    k_fc1<<<dim3(T_/4, N_), 128>>>(bf1);                                       // 8
    k_head<<<N_, 128>>>(Wf2, bf2, out);                                        // 9
}

// round 15
// speedup vs baseline: 2.7891x; 1.0736x over previous
#include <cuda_runtime.h>
#include <cuda_bf16.h>
#include <cuda_fp16.h>

#define N_ 32
#define T_ 48
#define NSM 148

// ---------------- scratch ----------------
__device__ float g_xt[(size_t)T_*N_*32*32];
__device__ float g_z1c[(size_t)T_*N_*16*28*28];               // conv1 pre-acts [t][n][c][hw]
__device__ __align__(256) __half g_h1h[(size_t)T_*N_*784*16]; // conv1 spikes fp16 [t][n][hw][c16]
__device__ float g_z2c[(size_t)T_*N_*576*32];                 // conv2 pre-acts [t][n][sp576][c32]
__device__ __align__(256) __half g_p1h[(size_t)T_*N_*144*32]; // pool1 spikes fp16 [t][n][pp144][c32]
__device__ float g_z3c[(size_t)T_*N_*32*8*8];                 // conv3 pre-acts [t][n][c][64]
__device__ float g_p2[(size_t)T_*N_*32*4*4];
__device__ float g_wt1[512*128];
__device__ float g_z1[(size_t)T_*N_*128];
__device__ __half g_w2s[2*25*32*16];   // conv2 w split [s][j][o][c16]
__device__ __half g_w3s[2*25*32*32];   // conv3 w split [s][j][o][c32]

// ---------------- fused prep ----------------
#define PW0 (N_*32*32)
#define PW1 (128*512)
#define PW2 (25*32*16)
#define PW3 (25*32*32)
#define PWT (PW0+PW1+PW2+PW3)
__global__ void k_prep(const float* __restrict__ x,  const float* __restrict__ Wf1,
                       const float* __restrict__ Wc2, const float* __restrict__ Wc3) {
    int gid = blockIdx.x*256 + threadIdx.x;
    if (gid < PW0) {
        int n = gid >> 10, hw = gid & 1023;
        const float* xp = x + (size_t)gid * T_;
        #pragma unroll
        for (int t = 0; t < T_; t++)
            g_xt[((size_t)t*N_ + n)*1024 + hw] = xp[t];
    } else if (gid < PW0+PW1) {
        int i = gid - PW0;
        int o = i >> 9, k = i & 511;
        g_wt1[k*128 + o] = Wf1[i];
    } else if (gid < PW0+PW1+PW2) {
        int i = gid - (PW0+PW1);
        int c = i % 16, o = (i/16) % 32, j = i/512;
        int kh = j/5, kw = j%5;
        float w = Wc2[((o*16 + c)*5 + kh)*5 + kw];
        __half h = __float2half_rn(w);
        float r = w - __half2float(h);
        g_w2s[0*12800 + i] = h;
        g_w2s[1*12800 + i] = __float2half_rn(r);
    } else if (gid < PWT) {
        int i = gid - (PW0+PW1+PW2);
        int c = i % 32, o = (i/32) % 32, j = i/1024;
        int kh = j/5, kw = j%5;
        float w = Wc3[((o*32 + c)*5 + kh)*5 + kw];
        __half h = __float2half_rn(w);
        float r = w - __half2float(h);
        g_w3s[0*25600 + i] = h;
        g_w3s[1*25600 + i] = __float2half_rn(r);
    }
}

// ---------------- mma / ldmatrix / cp.async helpers ----------------
__device__ __forceinline__ void mma16816(float* c, const unsigned* a,
                                         unsigned b0, unsigned b1) {
    asm volatile(
        "mma.sync.aligned.m16n8k16.row.col.f32.f16.f16.f32 "
        "{%0,%1,%2,%3}, {%4,%5,%6,%7}, {%8,%9}, {%0,%1,%2,%3};"
        : "+f"(c[0]), "+f"(c[1]), "+f"(c[2]), "+f"(c[3])
        : "r"(a[0]), "r"(a[1]), "r"(a[2]), "r"(a[3]), "r"(b0), "r"(b1));
}
__device__ __forceinline__ void ldsm_x4(unsigned* d, unsigned a) {
    asm volatile("ldmatrix.sync.aligned.m8n8.x4.shared.b16 {%0,%1,%2,%3}, [%4];"
                 : "=r"(d[0]), "=r"(d[1]), "=r"(d[2]), "=r"(d[3]) : "r"(a));
}
__device__ __forceinline__ void ldsm_x2(unsigned& d0, unsigned& d1, unsigned a) {
    asm volatile("ldmatrix.sync.aligned.m8n8.x2.shared.b16 {%0,%1}, [%2];"
                 : "=r"(d0), "=r"(d1) : "r"(a));
}
__device__ __forceinline__ void cp16(unsigned dst, const void* src) {
    asm volatile("cp.async.ca.shared.global [%0], [%1], 16;" :: "r"(dst), "l"(src));
}
#define CP_COMMIT() asm volatile("cp.async.commit_group;" ::: "memory")
#define CP_WAIT1()  asm volatile("cp.async.wait_group 1;" ::: "memory")

// ---------------- conv2: persistent + cp.async double buffer ----------------
#define C2_PAD 24
#define C2_TB  2
#define C2_TILES ((T_/C2_TB)*N_)
#define C2_BUFB (C2_TB*784*C2_PAD*2)
__global__ void __launch_bounds__(384, 1)
k_conv2_mma(const __half* __restrict__ h1h,
            const float* __restrict__ bc2,
            float* __restrict__ z2c) {
    extern __shared__ char sm[];
    __half* sIn = reinterpret_cast<__half*>(sm);
    __half* sW  = reinterpret_cast<__half*>(sm + 2*C2_BUFB);

    int tid = threadIdx.x;
    {
        const unsigned* src = reinterpret_cast<const unsigned*>(g_w2s);
        unsigned* dst = reinterpret_cast<unsigned*>(sW);
        for (int i = tid; i < 2*25*32*16/2; i += 384) {
            int e = i*2; int row = e >> 4; int c = e & 15;
            dst[(row*C2_PAD + c) >> 1] = src[i];
        }
    }

    int w    = tid >> 5;
    int lane = tid & 31;
    int qid  = lane >> 2;
    int rid  = lane & 3;
    int mi   = lane >> 3;
    int rr   = lane & 7;
    int matB = mi & 1;

    unsigned sInA = (unsigned)__cvta_generic_to_shared(sIn);
    unsigned sWA  = (unsigned)__cvta_generic_to_shared(sW);

    unsigned aaddr[2][2];
    #pragma unroll
    for (int s = 0; s < 2; s++)
        #pragma unroll
        for (int mt = 0; mt < 2; mt++) {
            int row = mt*16 + (mi & 1)*8 + rr;
            aaddr[s][mt] = sWA + (((s*25)*32 + row)*C2_PAD + (mi >> 1)*8)*2;
        }
    unsigned baddr[6];
    #pragma unroll
    for (int nt = 0; nt < 6; nt++) {
        int sp = w*48 + nt*8 + rr;
        int ho = sp / 24, wo = sp % 24;
        baddr[nt] = sInA + ((ho*28 + wo)*C2_PAD + matB*8)*2;
    }
    constexpr unsigned TTOFF = 784*C2_PAD*2;

    auto stage = [&](int tile, int buf) {
        int n  = tile & (N_-1);
        int t0 = (tile >> 5) * C2_TB;
        for (int i = tid; i < C2_TB*784*2; i += 384) {
            int half16 = i & 1;
            int r = i >> 1;
            int hw = r % 784, tt = r / 784;
            const __half* src = h1h + (((size_t)(t0+tt)*N_ + n)*784 + hw)*16 + half16*8;
            unsigned dst = sInA + (unsigned)(buf*C2_BUFB)
                         + (unsigned)(((tt*784 + hw)*C2_PAD + half16*8)*2);
            cp16(dst, src);
        }
    };

    if (blockIdx.x < C2_TILES) stage(blockIdx.x, 0);
    CP_COMMIT();

    int it = 0;
    #pragma unroll 1
    for (int tile = blockIdx.x; tile < C2_TILES; tile += gridDim.x, it++) {
        int cur = it & 1;
        __syncthreads();
        int nxt = tile + gridDim.x;
        if (nxt < C2_TILES) stage(nxt, cur ^ 1);
        CP_COMMIT();
        CP_WAIT1();
        __syncthreads();

        unsigned bufoff = (unsigned)(cur*C2_BUFB);
        int n  = tile & (N_-1);
        int t0 = (tile >> 5) * C2_TB;

        float acc[C2_TB][2][6][4];
        #pragma unroll
        for (int tt = 0; tt < C2_TB; tt++)
            #pragma unroll
            for (int mt = 0; mt < 2; mt++)
                #pragma unroll
                for (int nt = 0; nt < 6; nt++)
                    #pragma unroll
                    for (int r = 0; r < 4; r++) acc[tt][mt][nt][r] = 0.f;

        #pragma unroll 1
        for (int j = 0; j < 25; j++) {
            int kh = j / 5, kw = j % 5;
            unsigned aoff = (unsigned)(j*32*C2_PAD*2);
            unsigned boff = bufoff + (unsigned)((kh*28 + kw)*C2_PAD*2);

            unsigned aF[2][2][4];
            #pragma unroll
            for (int s = 0; s < 2; s++)
                #pragma unroll
                for (int mt = 0; mt < 2; mt++)
                    ldsm_x4(aF[s][mt], aaddr[s][mt] + aoff);

            #pragma unroll
            for (int tt = 0; tt < C2_TB; tt++) {
                unsigned bF[6][2];
                #pragma unroll
                for (int nt = 0; nt < 6; nt++)
                    ldsm_x2(bF[nt][0], bF[nt][1], baddr[nt] + boff + tt*TTOFF);
                #pragma unroll
                for (int s = 0; s < 2; s++)
                    #pragma unroll
                    for (int nt = 0; nt < 6; nt++)
                        #pragma unroll
                        for (int mt = 0; mt < 2; mt++)
                            mma16816(acc[tt][mt][nt], aF[s][mt], bF[nt][0], bF[nt][1]);
            }
        }

        // epilogue: channel-last store z2c[t][n][sp][c]
        #pragma unroll
        for (int tt = 0; tt < C2_TB; tt++) {
            float* zb = z2c + ((size_t)(t0+tt)*N_ + n)*576*32;
            #pragma unroll
            for (int mt = 0; mt < 2; mt++) {
                int o0 = mt*16 + qid;
                float b0 = bc2[o0], b1 = bc2[o0 + 8];
                #pragma unroll
                for (int nt = 0; nt < 6; nt++) {
                    int sp = w*48 + nt*8 + rid*2;
                    zb[(size_t)sp*32 + o0]          = acc[tt][mt][nt][0] + b0;
                    zb[(size_t)(sp+1)*32 + o0]      = acc[tt][mt][nt][1] + b0;
                    zb[(size_t)sp*32 + o0 + 8]      = acc[tt][mt][nt][2] + b1;
                    zb[(size_t)(sp+1)*32 + o0 + 8]  = acc[tt][mt][nt][3] + b1;
                }
            }
        }
    }
}

// ---------------- conv3: persistent + cp.async double buffer (fp16 input) ----------------
#define C3_PAD 40
#define C3_TB  4
#define C3_TILES ((T_/C3_TB)*N_)
#define C3_BUFB (C3_TB*144*C3_PAD*2)   // 46080
__global__ void __launch_bounds__(256, 1)
k_conv3_mma(const __half* __restrict__ p1h,
            const float* __restrict__ bc3,
            float* __restrict__ z3c) {
    extern __shared__ char sm[];
    __half* sW  = reinterpret_cast<__half*>(sm);                     // [2][25][32][C3_PAD] = 128000 B
    __half* sIn = reinterpret_cast<__half*>(sm + 2*25*32*C3_PAD*2);  // 2 buffers

    int tid = threadIdx.x;
    {
        const unsigned* src = reinterpret_cast<const unsigned*>(g_w3s);
        unsigned* dst = reinterpret_cast<unsigned*>(sW);
        for (int i = tid; i < 2*25*32*32/2; i += 256) {
            int e = i*2; int row = e >> 5; int c = e & 31;
            dst[(row*C3_PAD + c) >> 1] = src[i];
        }
    }

    int w    = tid >> 5;
    int lane = tid & 31;
    int qid  = lane >> 2;
    int rid  = lane & 3;
    int mi   = lane >> 3;
    int rr   = lane & 7;
    int matB = mi & 1;
    int mt   = w >> 2;
    int ntp  = w & 3;

    unsigned sInA = (unsigned)__cvta_generic_to_shared(sIn);
    unsigned sWA  = (unsigned)__cvta_generic_to_shared(sW);

    unsigned aaddr[2];
    #pragma unroll
    for (int s = 0; s < 2; s++) {
        int row = mt*16 + (mi & 1)*8 + rr;
        aaddr[s] = sWA + (((s*25)*32 + row)*C3_PAD + (mi >> 1)*8)*2;
    }
    unsigned baddr[2];
    #pragma unroll
    for (int q = 0; q < 2; q++) {
        int ntr = ntp*2 + q;
        baddr[q] = sInA + ((ntr*12 + rr)*C3_PAD + matB*8)*2;
    }
    constexpr unsigned TTOFF3 = 144*C3_PAD*2;

    auto stage = [&](int tile, int buf) {
        int n  = tile & (N_-1);
        int t0 = (tile >> 5) * C3_TB;
        for (int i = tid; i < C3_TB*144*4; i += 256) {
            int q  = i & 3;            // 16B quarter of a 64B row
            int r  = i >> 2;
            int hw = r % 144, tt = r / 144;
            const __half* src = p1h + (((size_t)(t0+tt)*N_ + n)*144 + hw)*32 + q*8;
            unsigned dst = sInA + (unsigned)(buf*C3_BUFB)
                         + (unsigned)(((tt*144 + hw)*C3_PAD + q*8)*2);
            cp16(dst, src);
        }
    };

    if (blockIdx.x < C3_TILES) stage(blockIdx.x, 0);
    CP_COMMIT();

    int o0 = mt*16 + qid;
    float bb0 = bc3[o0], bb1 = bc3[o0 + 8];

    int it = 0;
    #pragma unroll 1
    for (int tile = blockIdx.x; tile < C3_TILES; tile += gridDim.x, it++) {
        int cur = it & 1;
        __syncthreads();
        int nxt = tile + gridDim.x;
        if (nxt < C3_TILES) stage(nxt, cur ^ 1);
        CP_COMMIT();
        CP_WAIT1();
        __syncthreads();

        unsigned bufoff = (unsigned)(cur*C3_BUFB);
        int n  = tile & (N_-1);
        int t0 = (tile >> 5) * C3_TB;

        #pragma unroll 1
        for (int tp = 0; tp < C3_TB/2; tp++) {
            float acc[2][2][4];
            #pragma unroll
            for (int u = 0; u < 2; u++)
                #pragma unroll
                for (int q = 0; q < 2; q++)
                    #pragma unroll
                    for (int r = 0; r < 4; r++) acc[u][q][r] = 0.f;

            unsigned toffA = bufoff + (tp*2)*TTOFF3;
            unsigned toffB = bufoff + (tp*2+1)*TTOFF3;

            #pragma unroll 1
            for (int j = 0; j < 25; j++) {
                int kh = j / 5, kw = j % 5;
                unsigned aF[2][2][4];
                #pragma unroll
                for (int s = 0; s < 2; s++)
                    #pragma unroll
                    for (int kc = 0; kc < 2; kc++)
                        ldsm_x4(aF[s][kc], aaddr[s] + (unsigned)((j*32*C3_PAD + kc*16)*2));

                unsigned bF[2][2][2][2];
                #pragma unroll
                for (int kc = 0; kc < 2; kc++) {
                    unsigned bo = (unsigned)(((kh*12 + kw)*C3_PAD + kc*16)*2);
                    #pragma unroll
                    for (int q = 0; q < 2; q++) {
                        ldsm_x2(bF[0][kc][q][0], bF[0][kc][q][1], baddr[q] + bo + toffA);
                        ldsm_x2(bF[1][kc][q][0], bF[1][kc][q][1], baddr[q] + bo + toffB);
                    }
                }
                #pragma unroll
                for (int s = 0; s < 2; s++)
                    #pragma unroll
                    for (int kc = 0; kc < 2; kc++)
                        #pragma unroll
                        for (int u = 0; u < 2; u++)
                            #pragma unroll
                            for (int q = 0; q < 2; q++)
                                mma16816(acc[u][q], aF[s][kc], bF[u][kc][q][0], bF[u][kc][q][1]);
            }

            #pragma unroll
            for (int u = 0; u < 2; u++) {
                float* zb = z3c + ((size_t)(t0 + tp*2 + u)*N_ + n)*32*64;
                #pragma unroll
                for (int q = 0; q < 2; q++) {
                    int sp = (ntp*2 + q)*8 + rid*2;
                    float2 d0; d0.x = acc[u][q][0] + bb0; d0.y = acc[u][q][1] + bb0;
                    float2 d1; d1.x = acc[u][q][2] + bb1; d1.y = acc[u][q][3] + bb1;
                    *reinterpret_cast<float2*>(zb + (size_t)o0*64 + sp)     = d0;
                    *reinterpret_cast<float2*>(zb + (size_t)(o0+8)*64 + sp) = d1;
                }
            }
        }
    }
}

// ---------------- conv1 scalar (unchanged) ----------------
template<int CIN,int COUT,int HIN,int WIN,int GO,int WOT,int HOT,int TV,int MINB>
__global__ void
__launch_bounds__(((WIN-4)/WOT)*(COUT/GO)*HOT, MINB)
k_conv(const float* __restrict__ in,
       const float* __restrict__ Wc,
       const float* __restrict__ bc,
       float* __restrict__ z) {
    constexpr int HOUT = HIN-4, WOUT = WIN-4;
    constexpr int NWG  = WOUT/WOT;
    constexpr int NOG  = COUT/GO;
    constexpr int LANES = NWG*NOG;
    constexpr int HBLK = HOUT/HOT;
    constexpr int M    = CIN*5;
    constexpr size_t TS_IN  = (size_t)N_*CIN*HIN*WIN;
    constexpr size_t TS_OUT = (size_t)N_*COUT*HOUT*WOUT;
    extern __shared__ float ws[];
    {
        int tid = threadIdx.y*LANES + threadIdx.x;
        for (int i = tid; i < COUT*CIN*25; i += LANES*HOT) {
            int oc = i % COUT;
            int ck = i / COUT;
            ws[i] = Wc[oc*CIN*25 + ck];
        }
    }
    __syncthreads();

    int hb = blockIdx.x % HBLK;
    int t0 = (blockIdx.x / HBLK) * TV;
    int n  = blockIdx.y;
    int wg = threadIdx.x % NWG;
    int og = threadIdx.x / NWG;
    int wo = wg * WOT;
    int ho = hb*HOT + threadIdx.y;

    float acc[GO][WOT][TV];
    #pragma unroll
    for (int g = 0; g < GO; g++) {
        float b = bc[og*GO + g];
        #pragma unroll
        for (int ww = 0; ww < WOT; ww++)
            #pragma unroll
            for (int tv = 0; tv < TV; tv++) acc[g][ww][tv] = b;
    }

    const float* inb = in + (size_t)t0*TS_IN + (size_t)n*CIN*HIN*WIN
                          + (size_t)ho*WIN + wo;

    float va[WOT+4][TV], vb[WOT+4][TV];

    auto load_v = [&](int m, float (&v)[WOT+4][TV]) {
        int c = m / 5, kh = m % 5;
        const float* ip = inb + ((size_t)c*HIN + kh)*WIN;
        #pragma unroll
        for (int tv = 0; tv < TV; tv++) {
            const float2* p2 = reinterpret_cast<const float2*>(ip + (size_t)tv*TS_IN);
            #pragma unroll
            for (int j2 = 0; j2 < (WOT+4)/2; j2++) {
                float2 d = p2[j2];
                v[2*j2][tv]   = d.x;
                v[2*j2+1][tv] = d.y;
            }
        }
    };

    auto fma_step = [&](int m, float (&v)[WOT+4][TV]) {
        #pragma unroll
        for (int kw = 0; kw < 5; kw++) {
            float wreg[GO];
            if constexpr (GO == 4) {
                float4 w4 = *reinterpret_cast<const float4*>(&ws[(m*5 + kw)*COUT + og*4]);
                wreg[0] = w4.x; wreg[1] = w4.y; wreg[2] = w4.z; wreg[3] = w4.w;
            } else if constexpr (GO == 2) {
                float2 w2 = *reinterpret_cast<const float2*>(&ws[(m*5 + kw)*COUT + og*2]);
                wreg[0] = w2.x; wreg[1] = w2.y;
            } else {
                #pragma unroll
                for (int g = 0; g < GO; g++) wreg[g] = ws[(m*5 + kw)*COUT + og*GO + g];
            }
            #pragma unroll
            for (int g = 0; g < GO; g++)
                #pragma unroll
                for (int ww = 0; ww < WOT; ww++)
                    #pragma unroll
                    for (int tv = 0; tv < TV; tv++)
                        acc[g][ww][tv] += v[ww+kw][tv] * wreg[g];
        }
    };

    load_v(0, va);
    int m = 0;
    #pragma unroll 1
    for (; m + 2 <= M; m += 2) {
        load_v(m + 1, vb);
        fma_step(m, va);
        if (m + 2 < M) load_v(m + 2, va);
        fma_step(m + 1, vb);
    }
    if (m < M) fma_step(m, va);

    float* zb = z + (size_t)t0*TS_OUT + (size_t)n*COUT*HOUT*WOUT
                  + (size_t)og*GO*HOUT*WOUT + (size_t)ho*WOUT + wo;
    #pragma unroll
    for (int tv = 0; tv < TV; tv++)
        #pragma unroll
        for (int g = 0; g < GO; g++) {
            float* op = zb + (size_t)tv*TS_OUT + (size_t)g*HOUT*WOUT;
            #pragma unroll
            for (int j2 = 0; j2 < WOT/2; j2++) {
                float2 d; d.x = acc[g][2*j2][tv]; d.y = acc[g][2*j2+1][tv];
                reinterpret_cast<float2*>(op)[j2] = d;
            }
        }
}

// ---------------- layer-1 LIF scan: fp32 [t][n][c][hw] -> fp16 [t][n][hw][c16] ----------------
__global__ void k_scan1t(const float* __restrict__ z, __half* __restrict__ hout) {
    int idx = blockIdx.x * blockDim.x + threadIdx.x;
    if (idx >= N_*784) return;
    int n = idx / 784, hw = idx % 784;
    float u[16];
    #pragma unroll
    for (int c = 0; c < 16; c++) u[c] = 0.f;
    #pragma unroll 2
    for (int t = 0; t < T_; t++) {
        const float* zp = z + ((size_t)t*N_ + n)*16*784 + hw;
        __half hh[16];
        #pragma unroll
        for (int c = 0; c < 16; c++) {
            u[c] += zp[(size_t)c*784];
            float s = (u[c] >= 1.0f) ? 1.0f : 0.0f;
            u[c] -= s;
            hh[c] = __float2half_rn(s);
        }
        uint4* op = reinterpret_cast<uint4*>(hout + (((size_t)t*N_ + n)*784 + hw)*16);
        op[0] = reinterpret_cast<uint4*>(hh)[0];
        op[1] = reinterpret_cast<uint4*>(hh)[1];
    }
}

// ---------------- scanpool24 channel-last: z2c [t][n][sp][c32] -> p1h fp16 [t][n][pp][c32] ----------------
__global__ void k_scanpool2c(const float* __restrict__ z, __half* __restrict__ hout) {
    int idx = blockIdx.x * blockDim.x + threadIdx.x;   // N_*144*32
    if (idx >= N_*144*32) return;
    int c  = idx & 31;
    int pp = (idx >> 5) % 144;
    int n  = idx / (144*32);
    int ho = pp / 12, wo = pp % 12;
    int s00 = (2*ho)*24 + 2*wo;
    const float* zb = z + c + (size_t)s00*32;
    float u0 = 0.f, u1 = 0.f, u2 = 0.f, u3 = 0.f, up = 0.f;
    #pragma unroll 4
    for (int t = 0; t < T_; t++) {
        const float* p = zb + ((size_t)t*N_ + n)*576*32;
        u0 += p[0];      float sp0 = (u0 >= 1.0f) ? 1.0f : 0.0f; u0 -= sp0;
        u1 += p[32];     float sp1 = (u1 >= 1.0f) ? 1.0f : 0.0f; u1 -= sp1;
        u2 += p[24*32];  float sp2 = (u2 >= 1.0f) ? 1.0f : 0.0f; u2 -= sp2;
        u3 += p[25*32];  float sp3 = (u3 >= 1.0f) ? 1.0f : 0.0f; u3 -= sp3;
        up += 0.25f*(sp0 + sp1 + sp2 + sp3);
        float so = (up >= 1.0f) ? 1.0f : 0.0f; up -= so;
        hout[(((size_t)t*N_ + n)*144 + pp)*32 + c] = __float2half_rn(so);
    }
}

// ---------------- scanpool8 (z3c [t][n][c][64] -> p2 fp32, unchanged) ----------------
template<int C,int HIN>
__global__ void k_scanpool(const float* __restrict__ z, float* __restrict__ out) {
    constexpr int HO = HIN/2;
    constexpr size_t TS_IN  = (size_t)N_*C*HIN*HIN;
    constexpr size_t TS_OUT = (size_t)N_*C*HO*HO;
    int idx = blockIdx.x * blockDim.x + threadIdx.x;
    if (idx >= N_*C*HO*HO) return;
    int wo = idx % HO; int t1 = idx / HO;
    int ho = t1 % HO;  int t2 = t1 / HO;
    int c  = t2 % C;   int n  = t2 / C;
    const float* ip = z + ((size_t)n*C + c)*HIN*HIN + (size_t)(2*ho)*HIN + 2*wo;
    float* op = out + ((size_t)n*C + c)*HO*HO + (size_t)ho*HO + wo;
    float u0 = 0.f, u1 = 0.f, u2 = 0.f, u3 = 0.f, up = 0.f;
    #pragma unroll 4
    for (int t = 0; t < T_; t++) {
        const float* p = ip + (size_t)t*TS_IN;
        float2 r0 = *reinterpret_cast<const float2*>(p);
        float2 r1 = *reinterpret_cast<const float2*>(p + HIN);
        u0 += r0.x; float s0 = (u0 >= 1.0f) ? 1.0f : 0.0f; u0 -= s0;
        u1 += r0.y; float s1 = (u1 >= 1.0f) ? 1.0f : 0.0f; u1 -= s1;
        u2 += r1.x; float s2 = (u2 >= 1.0f) ? 1.0f : 0.0f; u2 -= s2;
        u3 += r1.y; float s3 = (u3 >= 1.0f) ? 1.0f : 0.0f; u3 -= s3;
        up += 0.25f*(s0 + s1 + s2 + s3);
        float sp = (up >= 1.0f) ? 1.0f : 0.0f; up -= sp;
        op[(size_t)t*TS_OUT] = sp;
    }
}

// ---------------- fc1 GEMM ----------------
__global__ void k_fc1(const float* __restrict__ bf1) {
    __shared__ float sin_[4][512];
    int t0 = blockIdx.x*4, n = blockIdx.y, o = threadIdx.x;
    for (int i = o; i < 4*512; i += 128) {
        int tv = i >> 9, k = i & 511;
        sin_[tv][k] = g_p2[((size_t)(t0+tv)*N_ + n)*512 + k];
    }
    __syncthreads();
    float b = bf1[o];
    float acc[4] = {b, b, b, b};
    #pragma unroll 4
    for (int k = 0; k < 512; k++) {
        float w = g_wt1[k*128 + o];
        #pragma unroll
        for (int tv = 0; tv < 4; tv++) acc[tv] += sin_[tv][k] * w;
    }
    #pragma unroll
    for (int tv = 0; tv < 4; tv++)
        g_z1[((size_t)(t0+tv)*N_ + n)*128 + o] = acc[tv];
}

// ---------------- head ----------------
__global__ void k_head(const float* __restrict__ Wf2, const float* __restrict__ bf2,
                       float* __restrict__ out) {
    int n = blockIdx.x, o = threadIdx.x;
    int wid = o >> 5, lane = o & 31;
    __shared__ float s1[128];
    float wr[4] = {0.f, 0.f, 0.f, 0.f};
    float b2 = 0.f;
    if (wid < 2) {
        #pragma unroll
        for (int k = 0; k < 4; k++) wr[k] = Wf2[wid*128 + lane + 32*k];
        b2 = bf2[wid];
    }
    float u1 = 0.f, u2 = 0.f, ssum = 0.f;
    for (int t = 0; t < T_; t++) {
        float z = g_z1[((size_t)t*N_ + n)*128 + o];
        u1 += z;
        float s = (u1 >= 1.0f) ? 1.0f : 0.0f;
        u1 -= s;
        s1[o] = s;
        __syncthreads();
        if (wid < 2) {
            float d = s1[lane]*wr[0] + s1[lane+32]*wr[1]
                    + s1[lane+64]*wr[2] + s1[lane+96]*wr[3];
            #pragma unroll
            for (int off = 16; off > 0; off >>= 1)
                d += __shfl_xor_sync(0xFFFFFFFFu, d, off);
            u2 += d + b2;
            float s2 = (u2 >= 1.0f) ? 1.0f : 0.0f;
            u2 -= s2;
            ssum += s2;
        }
        __syncthreads();
    }
    if (wid < 2 && lane == 0) out[n*2 + wid] = ssum * (1.0f / T_);
}

// ---------------- launch ----------------
extern "C" void kernel_launch(void* const* d_in, const int* in_sizes, int n_in,
                              void* d_out, int out_size) {
    (void)in_sizes; (void)n_in; (void)out_size;
    const float* x   = (const float*)d_in[0];
    const float* Wc1 = (const float*)d_in[1];
    const float* bc1 = (const float*)d_in[2];
    const float* Wc2 = (const float*)d_in[3];
    const float* bc2 = (const float*)d_in[4];
    const float* Wc3 = (const float*)d_in[5];
    const float* bc3 = (const float*)d_in[6];
    const float* Wf1 = (const float*)d_in[7];
    const float* bf1 = (const float*)d_in[8];
    const float* Wf2 = (const float*)d_in[9];
    const float* bf2 = (const float*)d_in[10];
    float* out = (float*)d_out;

    float *p_xt, *p_z1c, *p_z2c, *p_z3c, *p_p2;
    __half *p_h1h, *p_p1h;
    cudaGetSymbolAddress((void**)&p_xt,  g_xt);
    cudaGetSymbolAddress((void**)&p_z1c, g_z1c);
    cudaGetSymbolAddress((void**)&p_h1h, g_h1h);
    cudaGetSymbolAddress((void**)&p_z2c, g_z2c);
    cudaGetSymbolAddress((void**)&p_p1h, g_p1h);
    cudaGetSymbolAddress((void**)&p_z3c, g_z3c);
    cudaGetSymbolAddress((void**)&p_p2,  g_p2);

    auto c1 = k_conv<1,16,32,32,4,4,7,2,2>;

    constexpr int SMEM_C2 = 2*C2_BUFB + 2*25*32*C2_PAD*2;             // 227328
    constexpr int SMEM_C3 = 2*25*32*C3_PAD*2 + 2*C3_BUFB;             // 128000 + 92160 = 220160
    cudaFuncSetAttribute(k_conv2_mma, cudaFuncAttributeMaxDynamicSharedMemorySize, SMEM_C2);
    cudaFuncSetAttribute(k_conv3_mma, cudaFuncAttributeMaxDynamicSharedMemorySize, SMEM_C3);

    // launch order: k_conv2_mma stays launch #4 (ncu capture slot)
    k_prep<<<(PWT + 255)/256, 256>>>(x, Wf1, Wc2, Wc3);                        // 1
    c1<<<dim3(4*(T_/2), N_), dim3(28, 7), 16*1*25*4>>>(p_xt, Wc1, bc1, p_z1c); // 2
    k_scan1t<<<(N_*784 + 255)/256, 256>>>(p_z1c, p_h1h);                       // 3
    k_conv2_mma<<<NSM, 384, SMEM_C2>>>(p_h1h, bc2, p_z2c);                     // 4 <- profiled
    k_scanpool2c<<<(N_*144*32 + 255)/256, 256>>>(p_z2c, p_p1h);                // 5
    k_conv3_mma<<<NSM, 256, SMEM_C3>>>(p_p1h, bc3, p_z3c);                     // 6
    k_scanpool<32,8><<<(N_*32*4*4 + 255)/256, 256>>>(p_z3c, p_p2);             // 7
    k_fc1<<<dim3(T_/4, N_), 128>>>(bf1);                                       // 8
    k_head<<<N_, 128>>>(Wf2, bf2, out);                                        // 9
}

// round 16
// speedup vs baseline: 2.8477x; 1.0210x over previous
#include <cuda_runtime.h>
#include <cuda_bf16.h>
#include <cuda_fp16.h>

#define N_ 32
#define T_ 48
#define NSM 148

// ---------------- scratch ----------------
__device__ float g_xt[(size_t)T_*N_*32*32];
__device__ float g_z1c[(size_t)T_*N_*16*28*28];               // conv1 pre-acts [t][n][c][hw]
__device__ __align__(256) __half g_h1h[(size_t)T_*N_*784*16]; // conv1 spikes fp16 [t][n][hw][c16]
__device__ float g_z2c[(size_t)T_*N_*576*32];                 // conv2 pre-acts [t][n][sp576][c32]
__device__ __align__(256) __half g_p1h[(size_t)T_*N_*144*32]; // pool1 spikes fp16 [t][n][pp144][c32]
__device__ float g_z3c[(size_t)T_*N_*32*8*8];                 // conv3 pre-acts [t][n][c][64]
__device__ float g_p2[(size_t)T_*N_*32*4*4];
__device__ float g_wt1[512*128];
__device__ float g_z1[(size_t)T_*N_*128];
__device__ __half g_w2s[2*25*32*16];
__device__ __half g_w3s[2*25*32*32];

// ---------------- fused prep ----------------
#define PW0 (N_*32*32)
#define PW1 (128*512)
#define PW2 (25*32*16)
#define PW3 (25*32*32)
#define PWT (PW0+PW1+PW2+PW3)
__global__ void k_prep(const float* __restrict__ x,  const float* __restrict__ Wf1,
                       const float* __restrict__ Wc2, const float* __restrict__ Wc3) {
    int gid = blockIdx.x*256 + threadIdx.x;
    if (gid < PW0) {
        int n = gid >> 10, hw = gid & 1023;
        const float* xp = x + (size_t)gid * T_;
        #pragma unroll
        for (int t = 0; t < T_; t++)
            g_xt[((size_t)t*N_ + n)*1024 + hw] = xp[t];
    } else if (gid < PW0+PW1) {
        int i = gid - PW0;
        int o = i >> 9, k = i & 511;
        g_wt1[k*128 + o] = Wf1[i];
    } else if (gid < PW0+PW1+PW2) {
        int i = gid - (PW0+PW1);
        int c = i % 16, o = (i/16) % 32, j = i/512;
        int kh = j/5, kw = j%5;
        float w = Wc2[((o*16 + c)*5 + kh)*5 + kw];
        __half h = __float2half_rn(w);
        float r = w - __half2float(h);
        g_w2s[0*12800 + i] = h;
        g_w2s[1*12800 + i] = __float2half_rn(r);
    } else if (gid < PWT) {
        int i = gid - (PW0+PW1+PW2);
        int c = i % 32, o = (i/32) % 32, j = i/1024;
        int kh = j/5, kw = j%5;
        float w = Wc3[((o*32 + c)*5 + kh)*5 + kw];
        __half h = __float2half_rn(w);
        float r = w - __half2float(h);
        g_w3s[0*25600 + i] = h;
        g_w3s[1*25600 + i] = __float2half_rn(r);
    }
}

// ---------------- mma / ldmatrix / cp.async helpers ----------------
__device__ __forceinline__ void mma16816(float* c, const unsigned* a,
                                         unsigned b0, unsigned b1) {
    asm volatile(
        "mma.sync.aligned.m16n8k16.row.col.f32.f16.f16.f32 "
        "{%0,%1,%2,%3}, {%4,%5,%6,%7}, {%8,%9}, {%0,%1,%2,%3};"
        : "+f"(c[0]), "+f"(c[1]), "+f"(c[2]), "+f"(c[3])
        : "r"(a[0]), "r"(a[1]), "r"(a[2]), "r"(a[3]), "r"(b0), "r"(b1));
}
__device__ __forceinline__ void ldsm_x4(unsigned* d, unsigned a) {
    asm volatile("ldmatrix.sync.aligned.m8n8.x4.shared.b16 {%0,%1,%2,%3}, [%4];"
                 : "=r"(d[0]), "=r"(d[1]), "=r"(d[2]), "=r"(d[3]) : "r"(a));
}
__device__ __forceinline__ void ldsm_x2(unsigned& d0, unsigned& d1, unsigned a) {
    asm volatile("ldmatrix.sync.aligned.m8n8.x2.shared.b16 {%0,%1}, [%2];"
                 : "=r"(d0), "=r"(d1) : "r"(a));
}
__device__ __forceinline__ void cp16(unsigned dst, const void* src) {
    asm volatile("cp.async.ca.shared.global [%0], [%1], 16;" :: "r"(dst), "l"(src));
}
#define CP_COMMIT() asm volatile("cp.async.commit_group;" ::: "memory")
#define CP_WAIT1()  asm volatile("cp.async.wait_group 1;" ::: "memory")

// ---------------- conv2: persistent, 512 thr (16 warps = 2 tt x 8 spatial) ----------------
#define C2_PAD 24
#define C2_TB  2
#define C2_TILES ((T_/C2_TB)*N_)
#define C2_BUFB (C2_TB*784*C2_PAD*2)
__global__ void __launch_bounds__(512, 1)
k_conv2_mma(const __half* __restrict__ h1h,
            const float* __restrict__ bc2,
            float* __restrict__ z2c) {
    extern __shared__ char sm[];
    __half* sIn = reinterpret_cast<__half*>(sm);
    __half* sW  = reinterpret_cast<__half*>(sm + 2*C2_BUFB);

    int tid = threadIdx.x;
    {
        const unsigned* src = reinterpret_cast<const unsigned*>(g_w2s);
        unsigned* dst = reinterpret_cast<unsigned*>(sW);
        for (int i = tid; i < 2*25*32*16/2; i += 512) {
            int e = i*2; int row = e >> 4; int c = e & 15;
            dst[(row*C2_PAD + c) >> 1] = src[i];
        }
    }

    int w    = tid >> 5;
    int lane = tid & 31;
    int qid  = lane >> 2;
    int rid  = lane & 3;
    int mi   = lane >> 3;
    int rr   = lane & 7;
    int matB = mi & 1;
    int ttw  = w >> 3;     // timestep this warp owns (0/1)
    int sg   = w & 7;      // spatial group: 9 n8-tiles of 576

    unsigned sInA = (unsigned)__cvta_generic_to_shared(sIn);
    unsigned sWA  = (unsigned)__cvta_generic_to_shared(sW);

    unsigned aaddr[2][2];
    #pragma unroll
    for (int s = 0; s < 2; s++)
        #pragma unroll
        for (int mt = 0; mt < 2; mt++) {
            int row = mt*16 + (mi & 1)*8 + rr;
            aaddr[s][mt] = sWA + (((s*25)*32 + row)*C2_PAD + (mi >> 1)*8)*2;
        }
    unsigned baddr[9];
    #pragma unroll
    for (int nt = 0; nt < 9; nt++) {
        int sp = sg*72 + nt*8 + rr;
        int ho = sp / 24, wo = sp % 24;
        baddr[nt] = sInA + ((ho*28 + wo)*C2_PAD + matB*8)*2;
    }
    constexpr unsigned TTOFF = 784*C2_PAD*2;

    auto stage = [&](int tile, int buf) {
        int n  = tile & (N_-1);
        int t0 = (tile >> 5) * C2_TB;
        for (int i = tid; i < C2_TB*784*2; i += 512) {
            int half16 = i & 1;
            int r = i >> 1;
            int hw = r % 784, tt = r / 784;
            const __half* src = h1h + (((size_t)(t0+tt)*N_ + n)*784 + hw)*16 + half16*8;
            unsigned dst = sInA + (unsigned)(buf*C2_BUFB)
                         + (unsigned)(((tt*784 + hw)*C2_PAD + half16*8)*2);
            cp16(dst, src);
        }
    };

    if (blockIdx.x < C2_TILES) stage(blockIdx.x, 0);
    CP_COMMIT();

    int it = 0;
    #pragma unroll 1
    for (int tile = blockIdx.x; tile < C2_TILES; tile += gridDim.x, it++) {
        int cur = it & 1;
        __syncthreads();
        int nxt = tile + gridDim.x;
        if (nxt < C2_TILES) stage(nxt, cur ^ 1);
        CP_COMMIT();
        CP_WAIT1();
        __syncthreads();

        unsigned bufoff = (unsigned)(cur*C2_BUFB) + (unsigned)(ttw*TTOFF);
        int n  = tile & (N_-1);
        int t0 = (tile >> 5) * C2_TB;

        float acc[2][9][4];    // [mt][nt][4]
        #pragma unroll
        for (int mt = 0; mt < 2; mt++)
            #pragma unroll
            for (int nt = 0; nt < 9; nt++)
                #pragma unroll
                for (int r = 0; r < 4; r++) acc[mt][nt][r] = 0.f;

        #pragma unroll 1
        for (int j = 0; j < 25; j++) {
            int kh = j / 5, kw = j % 5;
            unsigned aoff = (unsigned)(j*32*C2_PAD*2);
            unsigned boff = bufoff + (unsigned)((kh*28 + kw)*C2_PAD*2);

            unsigned aF[2][2][4];
            #pragma unroll
            for (int s = 0; s < 2; s++)
                #pragma unroll
                for (int mt = 0; mt < 2; mt++)
                    ldsm_x4(aF[s][mt], aaddr[s][mt] + aoff);

            // 3 groups of 3 n8-tiles: same-acc reuse distance 6 MMAs
            #pragma unroll
            for (int ng = 0; ng < 3; ng++) {
                unsigned bF[3][2];
                #pragma unroll
                for (int q = 0; q < 3; q++)
                    ldsm_x2(bF[q][0], bF[q][1], baddr[ng*3 + q] + boff);
                #pragma unroll
                for (int s = 0; s < 2; s++)
                    #pragma unroll
                    for (int q = 0; q < 3; q++)
                        #pragma unroll
                        for (int mt = 0; mt < 2; mt++)
                            mma16816(acc[mt][ng*3 + q], aF[s][mt], bF[q][0], bF[q][1]);
            }
        }

        // epilogue: channel-last store z2c[t0+ttw][n][sp][c]
        {
            float* zb = z2c + ((size_t)(t0+ttw)*N_ + n)*576*32;
            #pragma unroll
            for (int mt = 0; mt < 2; mt++) {
                int o0 = mt*16 + qid;
                float b0 = bc2[o0], b1 = bc2[o0 + 8];
                #pragma unroll
                for (int nt = 0; nt < 9; nt++) {
                    int sp = sg*72 + nt*8 + rid*2;
                    zb[(size_t)sp*32 + o0]          = acc[mt][nt][0] + b0;
                    zb[(size_t)(sp+1)*32 + o0]      = acc[mt][nt][1] + b0;
                    zb[(size_t)sp*32 + o0 + 8]      = acc[mt][nt][2] + b1;
                    zb[(size_t)(sp+1)*32 + o0 + 8]  = acc[mt][nt][3] + b1;
                }
            }
        }
    }
}

// ---------------- conv3: persistent, 512 thr (16 warps = 2 tp x 2 mt x 4 ntp) ----------------
#define C3_PAD 40
#define C3_TB  4
#define C3_TILES ((T_/C3_TB)*N_)
#define C3_BUFB (C3_TB*144*C3_PAD*2)
__global__ void __launch_bounds__(512, 1)
k_conv3_mma(const __half* __restrict__ p1h,
            const float* __restrict__ bc3,
            float* __restrict__ z3c) {
    extern __shared__ char sm[];
    __half* sW  = reinterpret_cast<__half*>(sm);
    __half* sIn = reinterpret_cast<__half*>(sm + 2*25*32*C3_PAD*2);

    int tid = threadIdx.x;
    {
        const unsigned* src = reinterpret_cast<const unsigned*>(g_w3s);
        unsigned* dst = reinterpret_cast<unsigned*>(sW);
        for (int i = tid; i < 2*25*32*32/2; i += 512) {
            int e = i*2; int row = e >> 5; int c = e & 31;
            dst[(row*C3_PAD + c) >> 1] = src[i];
        }
    }

    int w    = tid >> 5;
    int lane = tid & 31;
    int qid  = lane >> 2;
    int rid  = lane & 3;
    int mi   = lane >> 3;
    int rr   = lane & 7;
    int matB = mi & 1;
    int tp   = w >> 3;          // timestep pair (0/1)
    int mt   = (w >> 2) & 1;
    int ntp  = w & 3;

    unsigned sInA = (unsigned)__cvta_generic_to_shared(sIn);
    unsigned sWA  = (unsigned)__cvta_generic_to_shared(sW);

    unsigned aaddr[2];
    #pragma unroll
    for (int s = 0; s < 2; s++) {
        int row = mt*16 + (mi & 1)*8 + rr;
        aaddr[s] = sWA + (((s*25)*32 + row)*C3_PAD + (mi >> 1)*8)*2;
    }
    unsigned baddr[2];
    #pragma unroll
    for (int q = 0; q < 2; q++) {
        int ntr = ntp*2 + q;
        baddr[q] = sInA + ((ntr*12 + rr)*C3_PAD + matB*8)*2;
    }
    constexpr unsigned TTOFF3 = 144*C3_PAD*2;

    auto stage = [&](int tile, int buf) {
        int n  = tile & (N_-1);
        int t0 = (tile >> 5) * C3_TB;
        for (int i = tid; i < C3_TB*144*4; i += 512) {
            int q  = i & 3;
            int r  = i >> 2;
            int hw = r % 144, tt = r / 144;
            const __half* src = p1h + (((size_t)(t0+tt)*N_ + n)*144 + hw)*32 + q*8;
            unsigned dst = sInA + (unsigned)(buf*C3_BUFB)
                         + (unsigned)(((tt*144 + hw)*C3_PAD + q*8)*2);
            cp16(dst, src);
        }
    };

    if (blockIdx.x < C3_TILES) stage(blockIdx.x, 0);
    CP_COMMIT();

    int o0 = mt*16 + qid;
    float bb0 = bc3[o0], bb1 = bc3[o0 + 8];

    int it = 0;
    #pragma unroll 1
    for (int tile = blockIdx.x; tile < C3_TILES; tile += gridDim.x, it++) {
        int cur = it & 1;
        __syncthreads();
        int nxt = tile + gridDim.x;
        if (nxt < C3_TILES) stage(nxt, cur ^ 1);
        CP_COMMIT();
        CP_WAIT1();
        __syncthreads();

        unsigned bufoff = (unsigned)(cur*C3_BUFB);
        int n  = tile & (N_-1);
        int t0 = (tile >> 5) * C3_TB;

        float acc[2][2][4];
        #pragma unroll
        for (int u = 0; u < 2; u++)
            #pragma unroll
            for (int q = 0; q < 2; q++)
                #pragma unroll
                for (int r = 0; r < 4; r++) acc[u][q][r] = 0.f;

        unsigned toffA = bufoff + (tp*2)*TTOFF3;
        unsigned toffB = bufoff + (tp*2+1)*TTOFF3;

        #pragma unroll 1
        for (int j = 0; j < 25; j++) {
            int kh = j / 5, kw = j % 5;
            unsigned aF[2][2][4];
            #pragma unroll
            for (int s = 0; s < 2; s++)
                #pragma unroll
                for (int kc = 0; kc < 2; kc++)
                    ldsm_x4(aF[s][kc], aaddr[s] + (unsigned)((j*32*C3_PAD + kc*16)*2));

            unsigned bF[2][2][2][2];
            #pragma unroll
            for (int kc = 0; kc < 2; kc++) {
                unsigned bo = (unsigned)(((kh*12 + kw)*C3_PAD + kc*16)*2);
                #pragma unroll
                for (int q = 0; q < 2; q++) {
                    ldsm_x2(bF[0][kc][q][0], bF[0][kc][q][1], baddr[q] + bo + toffA);
                    ldsm_x2(bF[1][kc][q][0], bF[1][kc][q][1], baddr[q] + bo + toffB);
                }
            }
            #pragma unroll
            for (int s = 0; s < 2; s++)
                #pragma unroll
                for (int kc = 0; kc < 2; kc++)
                    #pragma unroll
                    for (int u = 0; u < 2; u++)
                        #pragma unroll
                        for (int q = 0; q < 2; q++)
                            mma16816(acc[u][q], aF[s][kc], bF[u][kc][q][0], bF[u][kc][q][1]);
        }

        #pragma unroll
        for (int u = 0; u < 2; u++) {
            float* zb = z3c + ((size_t)(t0 + tp*2 + u)*N_ + n)*32*64;
            #pragma unroll
            for (int q = 0; q < 2; q++) {
                int sp = (ntp*2 + q)*8 + rid*2;
                float2 d0; d0.x = acc[u][q][0] + bb0; d0.y = acc[u][q][1] + bb0;
                float2 d1; d1.x = acc[u][q][2] + bb1; d1.y = acc[u][q][3] + bb1;
                *reinterpret_cast<float2*>(zb + (size_t)o0*64 + sp)     = d0;
                *reinterpret_cast<float2*>(zb + (size_t)(o0+8)*64 + sp) = d1;
            }
        }
    }
}

// ---------------- conv1 scalar (unchanged) ----------------
template<int CIN,int COUT,int HIN,int WIN,int GO,int WOT,int HOT,int TV,int MINB>
__global__ void
__launch_bounds__(((WIN-4)/WOT)*(COUT/GO)*HOT, MINB)
k_conv(const float* __restrict__ in,
       const float* __restrict__ Wc,
       const float* __restrict__ bc,
       float* __restrict__ z) {
    constexpr int HOUT = HIN-4, WOUT = WIN-4;
    constexpr int NWG  = WOUT/WOT;
    constexpr int NOG  = COUT/GO;
    constexpr int LANES = NWG*NOG;
    constexpr int HBLK = HOUT/HOT;
    constexpr int M    = CIN*5;
    constexpr size_t TS_IN  = (size_t)N_*CIN*HIN*WIN;
    constexpr size_t TS_OUT = (size_t)N_*COUT*HOUT*WOUT;
    extern __shared__ float ws[];
    {
        int tid = threadIdx.y*LANES + threadIdx.x;
        for (int i = tid; i < COUT*CIN*25; i += LANES*HOT) {
            int oc = i % COUT;
            int ck = i / COUT;
            ws[i] = Wc[oc*CIN*25 + ck];
        }
    }
    __syncthreads();

    int hb = blockIdx.x % HBLK;
    int t0 = (blockIdx.x / HBLK) * TV;
    int n  = blockIdx.y;
    int wg = threadIdx.x % NWG;
    int og = threadIdx.x / NWG;
    int wo = wg * WOT;
    int ho = hb*HOT + threadIdx.y;

    float acc[GO][WOT][TV];
    #pragma unroll
    for (int g = 0; g < GO; g++) {
        float b = bc[og*GO + g];
        #pragma unroll
        for (int ww = 0; ww < WOT; ww++)
            #pragma unroll
            for (int tv = 0; tv < TV; tv++) acc[g][ww][tv] = b;
    }

    const float* inb = in + (size_t)t0*TS_IN + (size_t)n*CIN*HIN*WIN
                          + (size_t)ho*WIN + wo;

    float va[WOT+4][TV], vb[WOT+4][TV];

    auto load_v = [&](int m, float (&v)[WOT+4][TV]) {
        int c = m / 5, kh = m % 5;
        const float* ip = inb + ((size_t)c*HIN + kh)*WIN;
        #pragma unroll
        for (int tv = 0; tv < TV; tv++) {
            const float2* p2 = reinterpret_cast<const float2*>(ip + (size_t)tv*TS_IN);
            #pragma unroll
            for (int j2 = 0; j2 < (WOT+4)/2; j2++) {
                float2 d = p2[j2];
                v[2*j2][tv]   = d.x;
                v[2*j2+1][tv] = d.y;
            }
        }
    };

    auto fma_step = [&](int m, float (&v)[WOT+4][TV]) {
        #pragma unroll
        for (int kw = 0; kw < 5; kw++) {
            float wreg[GO];
            if constexpr (GO == 4) {
                float4 w4 = *reinterpret_cast<const float4*>(&ws[(m*5 + kw)*COUT + og*4]);
                wreg[0] = w4.x; wreg[1] = w4.y; wreg[2] = w4.z; wreg[3] = w4.w;
            } else if constexpr (GO == 2) {
                float2 w2 = *reinterpret_cast<const float2*>(&ws[(m*5 + kw)*COUT + og*2]);
                wreg[0] = w2.x; wreg[1] = w2.y;
            } else {
                #pragma unroll
                for (int g = 0; g < GO; g++) wreg[g] = ws[(m*5 + kw)*COUT + og*GO + g];
            }
            #pragma unroll
            for (int g = 0; g < GO; g++)
                #pragma unroll
                for (int ww = 0; ww < WOT; ww++)
                    #pragma unroll
                    for (int tv = 0; tv < TV; tv++)
                        acc[g][ww][tv] += v[ww+kw][tv] * wreg[g];
        }
    };

    load_v(0, va);
    int m = 0;
    #pragma unroll 1
    for (; m + 2 <= M; m += 2) {
        load_v(m + 1, vb);
        fma_step(m, va);
        if (m + 2 < M) load_v(m + 2, va);
        fma_step(m + 1, vb);
    }
    if (m < M) fma_step(m, va);

    float* zb = z + (size_t)t0*TS_OUT + (size_t)n*COUT*HOUT*WOUT
                  + (size_t)og*GO*HOUT*WOUT + (size_t)ho*WOUT + wo;
    #pragma unroll
    for (int tv = 0; tv < TV; tv++)
        #pragma unroll
        for (int g = 0; g < GO; g++) {
            float* op = zb + (size_t)tv*TS_OUT + (size_t)g*HOUT*WOUT;
            #pragma unroll
            for (int j2 = 0; j2 < WOT/2; j2++) {
                float2 d; d.x = acc[g][2*j2][tv]; d.y = acc[g][2*j2+1][tv];
                reinterpret_cast<float2*>(op)[j2] = d;
            }
        }
}

// ---------------- layer-1 LIF scan: fp32 [t][n][c][hw] -> fp16 [t][n][hw][c16] ----------------
__global__ void k_scan1t(const float* __restrict__ z, __half* __restrict__ hout) {
    int idx = blockIdx.x * blockDim.x + threadIdx.x;
    if (idx >= N_*784) return;
    int n = idx / 784, hw = idx % 784;
    float u[16];
    #pragma unroll
    for (int c = 0; c < 16; c++) u[c] = 0.f;
    #pragma unroll 2
    for (int t = 0; t < T_; t++) {
        const float* zp = z + ((size_t)t*N_ + n)*16*784 + hw;
        __half hh[16];
        #pragma unroll
        for (int c = 0; c < 16; c++) {
            u[c] += zp[(size_t)c*784];
            float s = (u[c] >= 1.0f) ? 1.0f : 0.0f;
            u[c] -= s;
            hh[c] = __float2half_rn(s);
        }
        uint4* op = reinterpret_cast<uint4*>(hout + (((size_t)t*N_ + n)*784 + hw)*16);
        op[0] = reinterpret_cast<uint4*>(hh)[0];
        op[1] = reinterpret_cast<uint4*>(hh)[1];
    }
}

// ---------------- scanpool24 channel-last ----------------
__global__ void k_scanpool2c(const float* __restrict__ z, __half* __restrict__ hout) {
    int idx = blockIdx.x * blockDim.x + threadIdx.x;
    if (idx >= N_*144*32) return;
    int c  = idx & 31;
    int pp = (idx >> 5) % 144;
    int n  = idx / (144*32);
    int ho = pp / 12, wo = pp % 12;
    int s00 = (2*ho)*24 + 2*wo;
    const float* zb = z + c + (size_t)s00*32;
    float u0 = 0.f, u1 = 0.f, u2 = 0.f, u3 = 0.f, up = 0.f;
    #pragma unroll 4
    for (int t = 0; t < T_; t++) {
        const float* p = zb + ((size_t)t*N_ + n)*576*32;
        u0 += p[0];      float sp0 = (u0 >= 1.0f) ? 1.0f : 0.0f; u0 -= sp0;
        u1 += p[32];     float sp1 = (u1 >= 1.0f) ? 1.0f : 0.0f; u1 -= sp1;
        u2 += p[24*32];  float sp2 = (u2 >= 1.0f) ? 1.0f : 0.0f; u2 -= sp2;
        u3 += p[25*32];  float sp3 = (u3 >= 1.0f) ? 1.0f : 0.0f; u3 -= sp3;
        up += 0.25f*(sp0 + sp1 + sp2 + sp3);
        float so = (up >= 1.0f) ? 1.0f : 0.0f; up -= so;
        hout[(((size_t)t*N_ + n)*144 + pp)*32 + c] = __float2half_rn(so);
    }
}

// ---------------- scanpool8 ----------------
template<int C,int HIN>
__global__ void k_scanpool(const float* __restrict__ z, float* __restrict__ out) {
    constexpr int HO = HIN/2;
    constexpr size_t TS_IN  = (size_t)N_*C*HIN*HIN;
    constexpr size_t TS_OUT = (size_t)N_*C*HO*HO;
    int idx = blockIdx.x * blockDim.x + threadIdx.x;
    if (idx >= N_*C*HO*HO) return;
    int wo = idx % HO; int t1 = idx / HO;
    int ho = t1 % HO;  int t2 = t1 / HO;
    int c  = t2 % C;   int n  = t2 / C;
    const float* ip = z + ((size_t)n*C + c)*HIN*HIN + (size_t)(2*ho)*HIN + 2*wo;
    float* op = out + ((size_t)n*C + c)*HO*HO + (size_t)ho*HO + wo;
    float u0 = 0.f, u1 = 0.f, u2 = 0.f, u3 = 0.f, up = 0.f;
    #pragma unroll 4
    for (int t = 0; t < T_; t++) {
        const float* p = ip + (size_t)t*TS_IN;
        float2 r0 = *reinterpret_cast<const float2*>(p);
        float2 r1 = *reinterpret_cast<const float2*>(p + HIN);
        u0 += r0.x; float s0 = (u0 >= 1.0f) ? 1.0f : 0.0f; u0 -= s0;
        u1 += r0.y; float s1 = (u1 >= 1.0f) ? 1.0f : 0.0f; u1 -= s1;
        u2 += r1.x; float s2 = (u2 >= 1.0f) ? 1.0f : 0.0f; u2 -= s2;
        u3 += r1.y; float s3 = (u3 >= 1.0f) ? 1.0f : 0.0f; u3 -= s3;
        up += 0.25f*(s0 + s1 + s2 + s3);
        float sp = (up >= 1.0f) ? 1.0f : 0.0f; up -= sp;
        op[(size_t)t*TS_OUT] = sp;
    }
}

// ---------------- fc1 GEMM ----------------
__global__ void k_fc1(const float* __restrict__ bf1) {
    __shared__ float sin_[4][512];
    int t0 = blockIdx.x*4, n = blockIdx.y, o = threadIdx.x;
    for (int i = o; i < 4*512; i += 128) {
        int tv = i >> 9, k = i & 511;
        sin_[tv][k] = g_p2[((size_t)(t0+tv)*N_ + n)*512 + k];
    }
    __syncthreads();
    float b = bf1[o];
    float acc[4] = {b, b, b, b};
    #pragma unroll 4
    for (int k = 0; k < 512; k++) {
        float w = g_wt1[k*128 + o];
        #pragma unroll
        for (int tv = 0; tv < 4; tv++) acc[tv] += sin_[tv][k] * w;
    }
    #pragma unroll
    for (int tv = 0; tv < 4; tv++)
        g_z1[((size_t)(t0+tv)*N_ + n)*128 + o] = acc[tv];
}

// ---------------- head ----------------
__global__ void k_head(const float* __restrict__ Wf2, const float* __restrict__ bf2,
                       float* __restrict__ out) {
    int n = blockIdx.x, o = threadIdx.x;
    int wid = o >> 5, lane = o & 31;
    __shared__ float s1[128];
    float wr[4] = {0.f, 0.f, 0.f, 0.f};
    float b2 = 0.f;
    if (wid < 2) {
        #pragma unroll
        for (int k = 0; k < 4; k++) wr[k] = Wf2[wid*128 + lane + 32*k];
        b2 = bf2[wid];
    }
    float u1 = 0.f, u2 = 0.f, ssum = 0.f;
    for (int t = 0; t < T_; t++) {
        float z = g_z1[((size_t)t*N_ + n)*128 + o];
        u1 += z;
        float s = (u1 >= 1.0f) ? 1.0f : 0.0f;
        u1 -= s;
        s1[o] = s;
        __syncthreads();
        if (wid < 2) {
            float d = s1[lane]*wr[0] + s1[lane+32]*wr[1]
                    + s1[lane+64]*wr[2] + s1[lane+96]*wr[3];
            #pragma unroll
            for (int off = 16; off > 0; off >>= 1)
                d += __shfl_xor_sync(0xFFFFFFFFu, d, off);
            u2 += d + b2;
            float s2 = (u2 >= 1.0f) ? 1.0f : 0.0f;
            u2 -= s2;
            ssum += s2;
        }
        __syncthreads();
    }
    if (wid < 2 && lane == 0) out[n*2 + wid] = ssum * (1.0f / T_);
}

// ---------------- launch ----------------
extern "C" void kernel_launch(void* const* d_in, const int* in_sizes, int n_in,
                              void* d_out, int out_size) {
    (void)in_sizes; (void)n_in; (void)out_size;
    const float* x   = (const float*)d_in[0];
    const float* Wc1 = (const float*)d_in[1];
    const float* bc1 = (const float*)d_in[2];
    const float* Wc2 = (const float*)d_in[3];
    const float* bc2 = (const float*)d_in[4];
    const float* Wc3 = (const float*)d_in[5];
    const float* bc3 = (const float*)d_in[6];
    const float* Wf1 = (const float*)d_in[7];
    const float* bf1 = (const float*)d_in[8];
    const float* Wf2 = (const float*)d_in[9];
    const float* bf2 = (const float*)d_in[10];
    float* out = (float*)d_out;

    float *p_xt, *p_z1c, *p_z2c, *p_z3c, *p_p2;
    __half *p_h1h, *p_p1h;
    cudaGetSymbolAddress((void**)&p_xt,  g_xt);
    cudaGetSymbolAddress((void**)&p_z1c, g_z1c);
    cudaGetSymbolAddress((void**)&p_h1h, g_h1h);
    cudaGetSymbolAddress((void**)&p_z2c, g_z2c);
    cudaGetSymbolAddress((void**)&p_p1h, g_p1h);
    cudaGetSymbolAddress((void**)&p_z3c, g_z3c);
    cudaGetSymbolAddress((void**)&p_p2,  g_p2);

    auto c1 = k_conv<1,16,32,32,4,4,7,2,2>;

    constexpr int SMEM_C2 = 2*C2_BUFB + 2*25*32*C2_PAD*2;
    constexpr int SMEM_C3 = 2*25*32*C3_PAD*2 + 2*C3_BUFB;
    cudaFuncSetAttribute(k_conv2_mma, cudaFuncAttributeMaxDynamicSharedMemorySize, SMEM_C2);
    cudaFuncSetAttribute(k_conv3_mma, cudaFuncAttributeMaxDynamicSharedMemorySize, SMEM_C3);

    // launch order: k_conv2_mma stays launch #4 (ncu capture slot)
    k_prep<<<(PWT + 255)/256, 256>>>(x, Wf1, Wc2, Wc3);                        // 1
    c1<<<dim3(4*(T_/2), N_), dim3(28, 7), 16*1*25*4>>>(p_xt, Wc1, bc1, p_z1c); // 2
    k_scan1t<<<(N_*784 + 255)/256, 256>>>(p_z1c, p_h1h);                       // 3
    k_conv2_mma<<<NSM, 512, SMEM_C2>>>(p_h1h, bc2, p_z2c);                     // 4 <- profiled
    k_scanpool2c<<<(N_*144*32 + 255)/256, 256>>>(p_z2c, p_p1h);                // 5
    k_conv3_mma<<<NSM, 512, SMEM_C3>>>(p_p1h, bc3, p_z3c);                     // 6
    k_scanpool<32,8><<<(N_*32*4*4 + 255)/256, 256>>>(p_z3c, p_p2);             // 7
    k_fc1<<<dim3(T_/4, N_), 128>>>(bf1);                                       // 8
    k_head<<<N_, 128>>>(Wf2, bf2, out);                                        // 9
}